// round 11
// baseline (speedup 1.0000x reference)
#include <cuda_runtime.h>
#include <cuda_fp16.h>
#include <cstdint>

// ---------------- Problem constants ----------------
#define NMAX    50000
#define EMAX    800000
#define ETOTMAX (EMAX + NMAX)
#define GG      64
#define INC     128
#define HIDC    64
#define NHEADS  4
#define F1      (NHEADS * HIDC)   // 256
#define OUTC    10
#define NEG     0.2f
#define EPSV    1e-16f
#define FLTMAX  3.402823466e38f

// ---------------- Device scratch ----------------
__device__ __align__(16) __half d_h[(size_t)NMAX * F1];   // fp16 features (gathered buffer)
__device__ float d_feat[(size_t)NMAX * F1];
__device__ __align__(16) float d_asrcA[NMAX * NHEADS];
__device__ __align__(16) float d_adstA[NMAX * NHEADS];
__device__ __align__(16) float d_asrcB[NMAX * NHEADS];
__device__ __align__(16) float d_adstB[NMAX * NHEADS];
__device__ int   d_deg[NMAX];
__device__ int   d_off[NMAX];
__device__ int   d_cur[NMAX];
__device__ int   d_bsum[64];
__device__ int   d_csr_src[ETOTMAX];
__device__ float d_pool[GG * HIDC];
__device__ float d_cnt[GG];
// tf32-pre-rounded weights (referenced ONLY from device code via WSEL)
__device__ uint32_t d_W1t[INC * F1];
__device__ uint32_t d_W2t[F1 * F1];
__device__ uint32_t d_W3t[F1 * HIDC];
// precomputed W @ a vectors, PERMUTED: p(ch) = (ch>>7)*128 + (ch&3)*32 + ((ch>>2)&31)
__device__ float4 d_wa1s[INC], d_wa1d[INC];
__device__ float4 d_wa2s[F1],  d_wa2d[F1];
__device__ float  d_wa3s[F1],  d_wa3d[F1];

__device__ __forceinline__ int waperm(int ch) {
    return (ch >> 7) * 128 + (ch & 3) * 32 + ((ch >> 2) & 31);
}

__device__ __forceinline__ uint32_t cvt_tf32(float x) {
    uint32_t u;
    asm("cvt.rna.tf32.f32 %0, %1;" : "=r"(u) : "f"(x));
    return u;
}

// ================= weight rounding =================
__global__ void round_w(const float* __restrict__ W1, const float* __restrict__ W2,
                        const float* __restrict__ W3) {
    int i = blockIdx.x * 256 + threadIdx.x;
    if (i < INC * F1) d_W1t[i] = cvt_tf32(W1[i]);
    if (i < F1 * F1)  d_W2t[i] = cvt_tf32(W2[i]);
    if (i < F1 * HIDC) d_W3t[i] = cvt_tf32(W3[i]);
}

// ================= wa precompute: warp per k, coalesced =================
__global__ void wa_prep(const float* __restrict__ W1, const float* __restrict__ as1, const float* __restrict__ ad1,
                        const float* __restrict__ W2, const float* __restrict__ as2, const float* __restrict__ ad2,
                        const float* __restrict__ W3, const float* __restrict__ as3, const float* __restrict__ ad3) {
    int gw = (blockIdx.x * blockDim.x + threadIdx.x) >> 5;
    int lane = threadIdx.x & 31;
    if (gw >= F1) return;
    int k = gw;

    if (k < INC) {
        float4 s, d;
        float* sp = (float*)&s; float* dp = (float*)&d;
#pragma unroll
        for (int h = 0; h < NHEADS; h++) {
            float w0 = W1[(size_t)k * F1 + h * HIDC + lane];
            float w1 = W1[(size_t)k * F1 + h * HIDC + lane + 32];
            float ss = w0 * as1[h * HIDC + lane] + w1 * as1[h * HIDC + lane + 32];
            float dd = w0 * ad1[h * HIDC + lane] + w1 * ad1[h * HIDC + lane + 32];
#pragma unroll
            for (int o = 16; o; o >>= 1) {
                ss += __shfl_xor_sync(0xffffffffu, ss, o);
                dd += __shfl_xor_sync(0xffffffffu, dd, o);
            }
            sp[h] = ss; dp[h] = dd;
        }
        if (!lane) { int p = waperm(k); d_wa1s[p] = s; d_wa1d[p] = d; }
    }
    {
        float4 s, d;
        float* sp = (float*)&s; float* dp = (float*)&d;
#pragma unroll
        for (int h = 0; h < NHEADS; h++) {
            float w0 = W2[(size_t)k * F1 + h * HIDC + lane];
            float w1 = W2[(size_t)k * F1 + h * HIDC + lane + 32];
            float ss = w0 * as2[h * HIDC + lane] + w1 * as2[h * HIDC + lane + 32];
            float dd = w0 * ad2[h * HIDC + lane] + w1 * ad2[h * HIDC + lane + 32];
#pragma unroll
            for (int o = 16; o; o >>= 1) {
                ss += __shfl_xor_sync(0xffffffffu, ss, o);
                dd += __shfl_xor_sync(0xffffffffu, dd, o);
            }
            sp[h] = ss; dp[h] = dd;
        }
        float w0 = W3[(size_t)k * HIDC + lane];
        float w1 = W3[(size_t)k * HIDC + lane + 32];
        float s3 = w0 * as3[lane] + w1 * as3[lane + 32];
        float d3 = w0 * ad3[lane] + w1 * ad3[lane + 32];
#pragma unroll
        for (int o = 16; o; o >>= 1) {
            s3 += __shfl_xor_sync(0xffffffffu, s3, o);
            d3 += __shfl_xor_sync(0xffffffffu, d3, o);
        }
        if (!lane) {
            int p = waperm(k);
            d_wa2s[p] = s; d_wa2d[p] = d;
            d_wa3s[p] = s3; d_wa3d[p] = d3;
        }
    }
}

// ================= zero =================
__global__ void zero_all(int n) {
    int i = blockIdx.x * blockDim.x + threadIdx.x;
    if (i < n) { d_deg[i] = 0; d_cur[i] = 0; }
    if (i < GG * HIDC) d_pool[i] = 0.f;
    if (i < GG) d_cnt[i] = 0.f;
}

// ================= CSR construction =================
__global__ void hist_k(const int* __restrict__ ei, int E, int n) {
    int e = blockIdx.x * blockDim.x + threadIdx.x;
    int Etot = E + n;
    if (e >= Etot) return;
    int d = (e < E) ? __ldg(&ei[E + e]) : (e - E);
    atomicAdd(&d_deg[d], 1);
}

__global__ void scan_blk(int n) {
    int i = blockIdx.x * 1024 + threadIdx.x;
    int lane = threadIdx.x & 31, wid = threadIdx.x >> 5;
    int v = (i < n) ? d_deg[i] : 0;
    int x = v;
#pragma unroll
    for (int o = 1; o < 32; o <<= 1) {
        int t = __shfl_up_sync(0xffffffffu, x, o);
        if (lane >= o) x += t;
    }
    __shared__ int ws[32];
    if (lane == 31) ws[wid] = x;
    __syncthreads();
    if (wid == 0) {
        int y = ws[lane];
#pragma unroll
        for (int o = 1; o < 32; o <<= 1) {
            int t = __shfl_up_sync(0xffffffffu, y, o);
            if (lane >= o) y += t;
        }
        ws[lane] = y;
    }
    __syncthreads();
    int incl = x + (wid ? ws[wid - 1] : 0);
    if (i < n) d_off[i] = incl - v;
    if (threadIdx.x == 1023) d_bsum[blockIdx.x] = incl;
}

__global__ void scan_top(int nb) {
    int tid = threadIdx.x;
    int lane = tid & 31, wid = tid >> 5;
    int v = (tid < nb) ? d_bsum[tid] : 0;
    int x = v;
#pragma unroll
    for (int o = 1; o < 32; o <<= 1) {
        int t = __shfl_up_sync(0xffffffffu, x, o);
        if (lane >= o) x += t;
    }
    __shared__ int w0;
    if (wid == 0 && lane == 31) w0 = x;
    __syncthreads();
    int incl = x + (wid ? w0 : 0);
    if (tid < nb) d_bsum[tid] = incl - v;
}

__global__ void scan_add(int n) {
    int i = blockIdx.x * 1024 + threadIdx.x;
    if (i < n) d_off[i] += d_bsum[blockIdx.x];
}

__global__ void scatter_k(const int* __restrict__ ei, int E, int n) {
    int e = blockIdx.x * blockDim.x + threadIdx.x;
    int Etot = E + n;
    if (e >= Etot) return;
    int s, d;
    if (e < E) { s = __ldg(&ei[e]); d = __ldg(&ei[E + e]); } else { s = d = e - E; }
    int pos = d_off[d] + atomicAdd(&d_cur[d], 1);
    d_csr_src[pos] = s;
}

// ================= layer-1 attention coefficients =================
__global__ void gemv_attn(const float* __restrict__ x, int n) {
    __shared__ float4 ws[INC], wd[INC];
    for (int i = threadIdx.x; i < INC; i += 256) { ws[i] = d_wa1s[i]; wd[i] = d_wa1d[i]; }
    __syncthreads();
    int warp = (blockIdx.x * blockDim.x + threadIdx.x) >> 5;
    int lane = threadIdx.x & 31;
    if (warp >= n) return;
    float4 xv = *reinterpret_cast<const float4*>(&x[(size_t)warp * INC + lane * 4]);
    float xr[4] = {xv.x, xv.y, xv.z, xv.w};
    float ps[NHEADS] = {}, pd[NHEADS] = {};
#pragma unroll
    for (int j = 0; j < 4; j++) {
        float4 a = ws[j * 32 + lane];
        float4 b = wd[j * 32 + lane];
        ps[0] = fmaf(xr[j], a.x, ps[0]); ps[1] = fmaf(xr[j], a.y, ps[1]);
        ps[2] = fmaf(xr[j], a.z, ps[2]); ps[3] = fmaf(xr[j], a.w, ps[3]);
        pd[0] = fmaf(xr[j], b.x, pd[0]); pd[1] = fmaf(xr[j], b.y, pd[1]);
        pd[2] = fmaf(xr[j], b.z, pd[2]); pd[3] = fmaf(xr[j], b.w, pd[3]);
    }
#pragma unroll
    for (int h = 0; h < NHEADS; h++) {
#pragma unroll
        for (int o = 16; o; o >>= 1) {
            ps[h] += __shfl_xor_sync(0xffffffffu, ps[h], o);
            pd[h] += __shfl_xor_sync(0xffffffffu, pd[h], o);
        }
    }
    if (!lane) {
#pragma unroll
        for (int h = 0; h < NHEADS; h++) {
            d_asrcA[warp * NHEADS + h] = ps[h];
            d_adstA[warp * NHEADS + h] = pd[h];
        }
    }
}

// ================= TF32 GEMM: cp.async double buffer; fp16 output =================
__device__ __forceinline__ void mma_tf32(float c[4], uint32_t a0, uint32_t a1,
                                         uint32_t a2, uint32_t a3,
                                         uint32_t b0, uint32_t b1) {
    asm volatile(
        "mma.sync.aligned.m16n8k8.row.col.f32.tf32.tf32.f32 "
        "{%0,%1,%2,%3}, {%4,%5,%6,%7}, {%8,%9}, {%0,%1,%2,%3};"
        : "+f"(c[0]), "+f"(c[1]), "+f"(c[2]), "+f"(c[3])
        : "r"(a0), "r"(a1), "r"(a2), "r"(a3), "r"(b0), "r"(b1));
}

__device__ __forceinline__ void cp16p(void* smem_dst, const void* gsrc, bool pred) {
    unsigned sa = (unsigned)__cvta_generic_to_shared(smem_dst);
    int sz = pred ? 16 : 0;
    asm volatile("cp.async.ca.shared.global [%0], [%1], 16, %2;\n" :: "r"(sa), "l"(gsrc), "r"(sz));
}
__device__ __forceinline__ void cp_commit() { asm volatile("cp.async.commit_group;"); }
template <int N>
__device__ __forceinline__ void cp_wait() { asm volatile("cp.async.wait_group %0;" :: "n"(N)); }

template <int K, int NOUT, bool AG, int BN, int WM, int WN, int WSEL>
__launch_bounds__(256, 2)
__global__ void tgemm_k(const float* __restrict__ Ain, int M) {
    constexpr int BM = 128, BK = 16;
    constexpr int MT = BM / (WM * 16);
    constexpr int NT = BN / (WN * 8);
    __shared__ float    As[2][BM][BK + 4];
    __shared__ uint32_t Bs[2][BK][BN + 8];
    const float* A = AG ? (const float*)d_feat : Ain;
    const uint32_t* Bt = (WSEL == 1) ? (const uint32_t*)d_W1t
                       : (WSEL == 2) ? (const uint32_t*)d_W2t
                                     : (const uint32_t*)d_W3t;

    int tid = threadIdx.x;
    int wid = tid >> 5, lane = tid & 31;
    int wm = wid % WM, wn = wid / WM;
    int row0 = blockIdx.y * BM;
    int col0 = blockIdx.x * BN;
    int lr = lane >> 2, lc = lane & 3;

    float c[MT][NT][4];
#pragma unroll
    for (int i = 0; i < MT; i++)
#pragma unroll
        for (int j = 0; j < NT; j++)
#pragma unroll
            for (int q = 0; q < 4; q++) c[i][j][q] = 0.f;

    constexpr int B4 = BN / 4;
    constexpr int BLD = (BK * B4) / 256;
    const int nk = K / BK;

    {
#pragma unroll
        for (int j = 0; j < 2; j++) {
            int idx = tid + j * 256;
            int r = idx >> 2, q = idx & 3;
            cp16p(&As[0][r][q * 4], &A[(size_t)(row0 + r) * K + q * 4], (row0 + r) < M);
        }
#pragma unroll
        for (int j = 0; j < BLD; j++) {
            int idx = tid + j * 256;
            int r = idx / B4, q = idx % B4;
            cp16p(&Bs[0][r][q * 4], &Bt[(size_t)r * NOUT + col0 + q * 4], true);
        }
        cp_commit();
    }

    for (int t = 0; t < nk; t++) {
        int cur = t & 1;
        if (t + 1 < nk) {
            int k0 = (t + 1) * BK;
#pragma unroll
            for (int j = 0; j < 2; j++) {
                int idx = tid + j * 256;
                int r = idx >> 2, q = idx & 3;
                cp16p(&As[1 - cur][r][q * 4], &A[(size_t)(row0 + r) * K + k0 + q * 4], (row0 + r) < M);
            }
#pragma unroll
            for (int j = 0; j < BLD; j++) {
                int idx = tid + j * 256;
                int r = idx / B4, q = idx % B4;
                cp16p(&Bs[1 - cur][r][q * 4], &Bt[(size_t)(k0 + r) * NOUT + col0 + q * 4], true);
            }
            cp_commit();
            cp_wait<1>();
        } else {
            cp_wait<0>();
        }
        __syncthreads();

#pragma unroll
        for (int kk = 0; kk < BK; kk += 8) {
            uint32_t af[MT][4], bf[NT][2];
#pragma unroll
            for (int mt = 0; mt < MT; mt++) {
                int bm = wm * MT * 16 + mt * 16;
                af[mt][0] = cvt_tf32(As[cur][bm + lr][kk + lc]);
                af[mt][1] = cvt_tf32(As[cur][bm + lr + 8][kk + lc]);
                af[mt][2] = cvt_tf32(As[cur][bm + lr][kk + lc + 4]);
                af[mt][3] = cvt_tf32(As[cur][bm + lr + 8][kk + lc + 4]);
            }
#pragma unroll
            for (int nt = 0; nt < NT; nt++) {
                int bn = wn * NT * 8 + nt * 8;
                bf[nt][0] = Bs[cur][kk + lc][bn + lr];
                bf[nt][1] = Bs[cur][kk + lc + 4][bn + lr];
            }
#pragma unroll
            for (int mt = 0; mt < MT; mt++)
#pragma unroll
                for (int nt = 0; nt < NT; nt++)
                    mma_tf32(c[mt][nt], af[mt][0], af[mt][1], af[mt][2], af[mt][3],
                             bf[nt][0], bf[nt][1]);
        }
        __syncthreads();
    }

    // epilogue: fp16 output (half2 per c-pair)
#pragma unroll
    for (int mt = 0; mt < MT; mt++) {
        int r0 = row0 + wm * MT * 16 + mt * 16 + lr;
#pragma unroll
        for (int nt = 0; nt < NT; nt++) {
            int cc = col0 + wn * NT * 8 + nt * 8 + 2 * lc;
            if (r0 < M)
                *reinterpret_cast<__half2*>(&d_h[(size_t)r0 * NOUT + cc]) =
                    __floats2half2_rn(c[mt][nt][0], c[mt][nt][1]);
            if (r0 + 8 < M)
                *reinterpret_cast<__half2*>(&d_h[(size_t)(r0 + 8) * NOUT + cc]) =
                    __floats2half2_rn(c[mt][nt][2], c[mt][nt][3]);
        }
    }
}

// ================= fused aggregation: WPN warps per dst node (fp16 gather) ============
template <int H, int WPN, int HN, bool DOELU, bool SRCA, bool POOL>
__launch_bounds__(256)
__global__ void agg_k(const float* __restrict__ bias, const int* __restrict__ batch, int n) {
    constexpr int C = 64, F = H * C, CH = F / WPN, RF = CH / 32;
    constexpr int HL = (H == 4) ? 2 : 1;
    __shared__ float4 wsn4[HN == 4 ? F : 1], wdn4[HN == 4 ? F : 1];
    __shared__ float  wsn1[HN == 1 ? F : 1], wdn1[HN == 1 ? F : 1];
    __shared__ float  parts[8][8];
    if (HN == 4) {
        for (int i = threadIdx.x; i < F; i += 256) { wsn4[i] = d_wa2s[i]; wdn4[i] = d_wa2d[i]; }
        __syncthreads();
    } else if (HN == 1) {
        for (int i = threadIdx.x; i < F; i += 256) { wsn1[i] = d_wa3s[i]; wdn1[i] = d_wa3d[i]; }
        __syncthreads();
    }
    const float* asrc  = SRCA ? d_asrcA : d_asrcB;
    const float* adstp = SRCA ? d_adstA : d_adstB;
    float* nsrc = SRCA ? d_asrcB : d_asrcA;
    float* ndst = SRCA ? d_adstB : d_adstA;

    int gw   = (blockIdx.x * blockDim.x + threadIdx.x) >> 5;
    int wblk = threadIdx.x >> 5;
    int lane = threadIdx.x & 31;
    int node = gw / WPN;
    int sub  = gw % WPN;
    bool valid = node < n;

    float acc[RF];
#pragma unroll
    for (int k = 0; k < RF; k++) acc[k] = 0.f;

    if (valid) {
        int off = d_off[node], deg = d_deg[node];

        float ad[HL];
#pragma unroll
        for (int h = 0; h < HL; h++) ad[h] = adstp[node * H + sub * HL + h];

        // phase 1: online softmax
        float mx[HL], sv[HL];
#pragma unroll
        for (int h = 0; h < HL; h++) { mx[h] = -FLTMAX; sv[h] = 0.f; }
        for (int j = lane; j < deg; j += 32) {
            int s = d_csr_src[off + j];
            float av[HL];
            if (H == 4) {
                float2 a2 = *reinterpret_cast<const float2*>(&asrc[s * 4 + sub * 2]);
                av[0] = a2.x; av[1] = a2.y;
            } else {
                av[0] = asrc[s];
            }
#pragma unroll
            for (int h = 0; h < HL; h++) {
                float v = av[h] + ad[h];
                v = v > 0.f ? v : NEG * v;
                float nm = fmaxf(mx[h], v);
                sv[h] = sv[h] * __expf(mx[h] - nm) + __expf(v - nm);
                mx[h] = nm;
            }
        }
#pragma unroll
        for (int h = 0; h < HL; h++) {
#pragma unroll
            for (int o = 16; o; o >>= 1) {
                float om = __shfl_xor_sync(0xffffffffu, mx[h], o);
                float os = __shfl_xor_sync(0xffffffffu, sv[h], o);
                float nm = fmaxf(mx[h], om);
                sv[h] = sv[h] * __expf(mx[h] - nm) + os * __expf(om - nm);
                mx[h] = nm;
            }
            sv[h] = 1.f / (sv[h] + EPSV);
        }

        // phase 2: weighted fp16 gather, chunked x4 for MLP
        const int hl = (H == 4) ? (lane >> 4) : 0;
        const float adh = ad[hl], mxh = mx[hl], svh = sv[hl];
        const int asoff = (H == 4) ? (sub * 2 + hl) : 0;
        const size_t cbase = sub * CH + lane * RF;

        int j = 0;
        for (; j + 4 <= deg; j += 4) {
            int s0 = d_csr_src[off + j];
            int s1 = d_csr_src[off + j + 1];
            int s2 = d_csr_src[off + j + 2];
            int s3 = d_csr_src[off + j + 3];
            float e0 = asrc[s0 * H + asoff], e1 = asrc[s1 * H + asoff];
            float e2 = asrc[s2 * H + asoff], e3 = asrc[s3 * H + asoff];
            e0 += adh; e1 += adh; e2 += adh; e3 += adh;
            e0 = e0 > 0.f ? e0 : NEG * e0;  e1 = e1 > 0.f ? e1 : NEG * e1;
            e2 = e2 > 0.f ? e2 : NEG * e2;  e3 = e3 > 0.f ? e3 : NEG * e3;
            float w0 = __expf(e0 - mxh) * svh, w1 = __expf(e1 - mxh) * svh;
            float w2 = __expf(e2 - mxh) * svh, w3 = __expf(e3 - mxh) * svh;
            if (RF == 4) {
                uint2 u0 = *reinterpret_cast<const uint2*>(&d_h[(size_t)s0 * F + cbase]);
                uint2 u1 = *reinterpret_cast<const uint2*>(&d_h[(size_t)s1 * F + cbase]);
                uint2 u2 = *reinterpret_cast<const uint2*>(&d_h[(size_t)s2 * F + cbase]);
                uint2 u3 = *reinterpret_cast<const uint2*>(&d_h[(size_t)s3 * F + cbase]);
                float2 a0 = __half22float2(*reinterpret_cast<__half2*>(&u0.x));
                float2 b0 = __half22float2(*reinterpret_cast<__half2*>(&u0.y));
                float2 a1 = __half22float2(*reinterpret_cast<__half2*>(&u1.x));
                float2 b1 = __half22float2(*reinterpret_cast<__half2*>(&u1.y));
                float2 a2 = __half22float2(*reinterpret_cast<__half2*>(&u2.x));
                float2 b2 = __half22float2(*reinterpret_cast<__half2*>(&u2.y));
                float2 a3 = __half22float2(*reinterpret_cast<__half2*>(&u3.x));
                float2 b3 = __half22float2(*reinterpret_cast<__half2*>(&u3.y));
                acc[0] = fmaf(w0, a0.x, acc[0]); acc[1] = fmaf(w0, a0.y, acc[1]);
                acc[2] = fmaf(w0, b0.x, acc[2]); acc[3] = fmaf(w0, b0.y, acc[3]);
                acc[0] = fmaf(w1, a1.x, acc[0]); acc[1] = fmaf(w1, a1.y, acc[1]);
                acc[2] = fmaf(w1, b1.x, acc[2]); acc[3] = fmaf(w1, b1.y, acc[3]);
                acc[0] = fmaf(w2, a2.x, acc[0]); acc[1] = fmaf(w2, a2.y, acc[1]);
                acc[2] = fmaf(w2, b2.x, acc[2]); acc[3] = fmaf(w2, b2.y, acc[3]);
                acc[0] = fmaf(w3, a3.x, acc[0]); acc[1] = fmaf(w3, a3.y, acc[1]);
                acc[2] = fmaf(w3, b3.x, acc[2]); acc[3] = fmaf(w3, b3.y, acc[3]);
            } else {
                uint u0 = *reinterpret_cast<const uint*>(&d_h[(size_t)s0 * F + cbase]);
                uint u1 = *reinterpret_cast<const uint*>(&d_h[(size_t)s1 * F + cbase]);
                uint u2 = *reinterpret_cast<const uint*>(&d_h[(size_t)s2 * F + cbase]);
                uint u3 = *reinterpret_cast<const uint*>(&d_h[(size_t)s3 * F + cbase]);
                float2 a0 = __half22float2(*reinterpret_cast<__half2*>(&u0));
                float2 a1 = __half22float2(*reinterpret_cast<__half2*>(&u1));
                float2 a2 = __half22float2(*reinterpret_cast<__half2*>(&u2));
                float2 a3 = __half22float2(*reinterpret_cast<__half2*>(&u3));
                acc[0] = fmaf(w0, a0.x, acc[0]); acc[1] = fmaf(w0, a0.y, acc[1]);
                acc[0] = fmaf(w1, a1.x, acc[0]); acc[1] = fmaf(w1, a1.y, acc[1]);
                acc[0] = fmaf(w2, a2.x, acc[0]); acc[1] = fmaf(w2, a2.y, acc[1]);
                acc[0] = fmaf(w3, a3.x, acc[0]); acc[1] = fmaf(w3, a3.y, acc[1]);
            }
        }
        for (; j < deg; j++) {
            int s = d_csr_src[off + j];
            float v = asrc[s * H + asoff] + adh;
            v = v > 0.f ? v : NEG * v;
            float w = __expf(v - mxh) * svh;
            if (RF == 4) {
                uint2 u0 = *reinterpret_cast<const uint2*>(&d_h[(size_t)s * F + cbase]);
                float2 a0 = __half22float2(*reinterpret_cast<__half2*>(&u0.x));
                float2 b0 = __half22float2(*reinterpret_cast<__half2*>(&u0.y));
                acc[0] = fmaf(w, a0.x, acc[0]); acc[1] = fmaf(w, a0.y, acc[1]);
                acc[2] = fmaf(w, b0.x, acc[2]); acc[3] = fmaf(w, b0.y, acc[3]);
            } else {
                uint u0 = *reinterpret_cast<const uint*>(&d_h[(size_t)s * F + cbase]);
                float2 a0 = __half22float2(*reinterpret_cast<__half2*>(&u0));
                acc[0] = fmaf(w, a0.x, acc[0]); acc[1] = fmaf(w, a0.y, acc[1]);
            }
        }

        // bias + optional ELU
#pragma unroll
        for (int k = 0; k < RF; k++) {
            float v = acc[k] + bias[sub * CH + lane * RF + k];
            if (DOELU) v = v > 0.f ? v : (__expf(v) - 1.f);
            acc[k] = v;
        }

        if (POOL) {
            int g = __ldg(&batch[node]);
            atomicAdd(&d_pool[g * HIDC + lane * RF + 0], acc[0]);
            atomicAdd(&d_pool[g * HIDC + lane * RF + 1], acc[1]);
            if (!lane) atomicAdd(&d_cnt[g], 1.0f);
        } else {
            float* outp = &d_feat[(size_t)node * F + sub * CH + lane * RF];
            if (RF == 4)
                *reinterpret_cast<float4*>(outp) = make_float4(acc[0], acc[1], acc[2], acc[3]);
            else
                *reinterpret_cast<float2*>(outp) = make_float2(acc[0], acc[1]);
        }

        // partial next-layer coefficients
        if (HN == 4) {
            float ps[4] = {}, pd[4] = {};
#pragma unroll
            for (int k = 0; k < RF; k++) {
                float4 a = wsn4[sub * CH + k * 32 + lane];
                float4 b = wdn4[sub * CH + k * 32 + lane];
                ps[0] = fmaf(acc[k], a.x, ps[0]); ps[1] = fmaf(acc[k], a.y, ps[1]);
                ps[2] = fmaf(acc[k], a.z, ps[2]); ps[3] = fmaf(acc[k], a.w, ps[3]);
                pd[0] = fmaf(acc[k], b.x, pd[0]); pd[1] = fmaf(acc[k], b.y, pd[1]);
                pd[2] = fmaf(acc[k], b.z, pd[2]); pd[3] = fmaf(acc[k], b.w, pd[3]);
            }
#pragma unroll
            for (int h = 0; h < 4; h++) {
#pragma unroll
                for (int o = 16; o; o >>= 1) {
                    ps[h] += __shfl_xor_sync(0xffffffffu, ps[h], o);
                    pd[h] += __shfl_xor_sync(0xffffffffu, pd[h], o);
                }
            }
            if (!lane) {
#pragma unroll
                for (int h = 0; h < 4; h++) {
                    parts[wblk][h] = ps[h];
                    parts[wblk][4 + h] = pd[h];
                }
            }
        } else if (HN == 1) {
            float ps = 0.f, pd = 0.f;
#pragma unroll
            for (int k = 0; k < RF; k++) {
                ps = fmaf(acc[k], wsn1[sub * CH + k * 32 + lane], ps);
                pd = fmaf(acc[k], wdn1[sub * CH + k * 32 + lane], pd);
            }
#pragma unroll
            for (int o = 16; o; o >>= 1) {
                ps += __shfl_xor_sync(0xffffffffu, ps, o);
                pd += __shfl_xor_sync(0xffffffffu, pd, o);
            }
            if (!lane) { parts[wblk][0] = ps; parts[wblk][1] = pd; }
        }
    }

    if (HN > 0) {
        __syncthreads();
        if (valid && sub == 0 && !lane) {
            if (HN == 4) {
#pragma unroll
                for (int h = 0; h < 4; h++) {
                    nsrc[node * 4 + h] = parts[wblk][h]     + parts[wblk + 1][h];
                    ndst[node * 4 + h] = parts[wblk][4 + h] + parts[wblk + 1][4 + h];
                }
            } else {
                nsrc[node] = parts[wblk][0] + parts[wblk + 1][0];
                ndst[node] = parts[wblk][1] + parts[wblk + 1][1];
            }
        }
    }
}

// ---------------- head ----------------
__global__ void head_k(const float* __restrict__ Wc, const float* __restrict__ bc,
                       float* __restrict__ out) {
    int t = blockIdx.x * blockDim.x + threadIdx.x;
    if (t >= GG * OUTC) return;
    int g = t / OUTC, o = t % OUTC;
    float inv = 1.f / fmaxf(d_cnt[g], 1.f);
    float s = 0.f;
#pragma unroll
    for (int c = 0; c < HIDC; c++) s += d_pool[g * HIDC + c] * Wc[c * OUTC + o];
    out[t] = s * inv + bc[o];
}

// ---------------- host orchestration ----------------
extern "C" void kernel_launch(void* const* d_in, const int* in_sizes, int n_in,
                              void* d_out, int out_size) {
    const float* x   = (const float*)d_in[0];
    const int*   ei  = (const int*)d_in[1];
    const int*   bat = (const int*)d_in[2];
    const float* W1 = (const float*)d_in[3],  *as1 = (const float*)d_in[4],
               * ad1 = (const float*)d_in[5], *b1  = (const float*)d_in[6];
    const float* W2 = (const float*)d_in[7],  *as2 = (const float*)d_in[8],
               * ad2 = (const float*)d_in[9], *b2  = (const float*)d_in[10];
    const float* W3 = (const float*)d_in[11], *as3 = (const float*)d_in[12],
               * ad3 = (const float*)d_in[13],*b3  = (const float*)d_in[14];
    const float* Wc = (const float*)d_in[15], *bc  = (const float*)d_in[16];
    float* out = (float*)d_out;

    int n    = in_sizes[0] / INC;
    int E    = in_sizes[1] / 2;
    int Etot = E + n;

    int gemm_rows = (n + 127) / 128;
    int eb    = (Etot + 255) / 256;
    int nb    = (n + 255) / 256;
    int sb    = (n + 1023) / 1024;
    int aggb2 = ((long long)n * 2 * 32 + 255) / 256;
    int aggb1 = ((long long)n * 32 + 255) / 256;

    wa_prep<<<32, 256>>>(W1, as1, ad1, W2, as2, ad2, W3, as3, ad3);         // 0
    round_w<<<(F1 * F1 + 255) / 256, 256>>>(W1, W2, W3);                    // 1
    zero_all<<<nb, 256>>>(n);                                               // 2
    tgemm_k<INC, F1, false, 128, 2, 4, 1><<<dim3(F1 / 128, gemm_rows), 256>>>(x, n); // 3
    hist_k<<<eb, 256>>>(ei, E, n);                                          // 4
    scan_blk<<<sb, 1024>>>(n);                                              // 5
    scan_top<<<1, 64>>>(sb);                                                // 6
    scan_add<<<sb, 1024>>>(n);                                              // 7
    scatter_k<<<eb, 256>>>(ei, E, n);                                       // 8
    gemv_attn<<<(n + 7) / 8, 256>>>(x, n);                                  // 9

    // ---- Layer 1 agg (H=4, 2 warps/node); writes layer-2 coeffs ----
    agg_k<NHEADS, 2, NHEADS, true, true, false><<<aggb2, 256>>>(b1, nullptr, n);

    // ---- Layer 2 (H=4, in=256, out=256) ----
    tgemm_k<F1, F1, true, 128, 2, 4, 2><<<dim3(F1 / 128, gemm_rows), 256>>>(nullptr, n);
    agg_k<NHEADS, 2, 1, true, false, false><<<aggb2, 256>>>(b2, nullptr, n);

    // ---- Layer 3 (H=1, in=256, out=64) ----
    tgemm_k<F1, HIDC, true, 64, 4, 2, 3><<<dim3(1, gemm_rows), 256>>>(nullptr, n);
    agg_k<1, 1, 0, false, true, true><<<aggb1, 256>>>(b3, bat, n);

    // ---- head ----
    head_k<<<(GG * OUTC + 255) / 256, 256>>>(Wc, bc, out);
}

// round 12
// speedup vs baseline: 1.2416x; 1.2416x over previous
#include <cuda_runtime.h>
#include <cstdint>

// ---------------- Problem constants ----------------
#define NMAX    50000
#define EMAX    800000
#define ETOTMAX (EMAX + NMAX)
#define GG      64
#define INC     128
#define HIDC    64
#define NHEADS  4
#define F1      (NHEADS * HIDC)   // 256
#define OUTC    10
#define NEG     0.2f
#define EPSV    1e-16f
#define FLTMAX  3.402823466e38f

// ---------------- Device scratch ----------------
__device__ float d_h[(size_t)NMAX * F1];
__device__ float d_feat[(size_t)NMAX * F1];
__device__ __align__(16) float d_asrcA[NMAX * NHEADS];
__device__ __align__(16) float d_adstA[NMAX * NHEADS];
__device__ __align__(16) float d_asrcB[NMAX * NHEADS];
__device__ __align__(16) float d_adstB[NMAX * NHEADS];
__device__ int   d_deg[NMAX];
__device__ int   d_off[NMAX];
__device__ int   d_cur[NMAX];
__device__ int   d_bsum[64];
__device__ int   d_csr_src[ETOTMAX];
__device__ float d_pool[GG * HIDC];
__device__ float d_cnt[GG];
// tf32-pre-rounded weights (referenced ONLY from device code via WSEL)
__device__ uint32_t d_W1t[INC * F1];
__device__ uint32_t d_W2t[F1 * F1];
__device__ uint32_t d_W3t[F1 * HIDC];
// precomputed W @ a vectors.
// wa1 (gemv): entry (j*32+l) holds heads of k=l*4+j (float4)
// wa2/wa3 (agg epilogue, 4-way node split): p(ch) = (ch>>6)*64 + (ch&1)*32 + ((ch>>1)&31)
__device__ float4 d_wa1s[INC], d_wa1d[INC];
__device__ float4 d_wa2s[F1],  d_wa2d[F1];
__device__ float  d_wa3s[F1],  d_wa3d[F1];

__device__ __forceinline__ int waperm4(int ch) {
    return (ch >> 6) * 64 + (ch & 1) * 32 + ((ch >> 1) & 31);
}

__device__ __forceinline__ uint32_t cvt_tf32(float x) {
    uint32_t u;
    asm("cvt.rna.tf32.f32 %0, %1;" : "=r"(u) : "f"(x));
    return u;
}

// ================= weight rounding =================
__global__ void round_w(const float* __restrict__ W1, const float* __restrict__ W2,
                        const float* __restrict__ W3) {
    int i = blockIdx.x * 256 + threadIdx.x;
    if (i < INC * F1) d_W1t[i] = cvt_tf32(W1[i]);
    if (i < F1 * F1)  d_W2t[i] = cvt_tf32(W2[i]);
    if (i < F1 * HIDC) d_W3t[i] = cvt_tf32(W3[i]);
}

// ================= wa precompute: warp per k, coalesced =================
__global__ void wa_prep(const float* __restrict__ W1, const float* __restrict__ as1, const float* __restrict__ ad1,
                        const float* __restrict__ W2, const float* __restrict__ as2, const float* __restrict__ ad2,
                        const float* __restrict__ W3, const float* __restrict__ as3, const float* __restrict__ ad3) {
    int gw = (blockIdx.x * blockDim.x + threadIdx.x) >> 5;
    int lane = threadIdx.x & 31;
    if (gw >= F1) return;
    int k = gw;

    if (k < INC) {
        float4 s, d;
        float* sp = (float*)&s; float* dp = (float*)&d;
#pragma unroll
        for (int h = 0; h < NHEADS; h++) {
            float w0 = W1[(size_t)k * F1 + h * HIDC + lane];
            float w1 = W1[(size_t)k * F1 + h * HIDC + lane + 32];
            float ss = w0 * as1[h * HIDC + lane] + w1 * as1[h * HIDC + lane + 32];
            float dd = w0 * ad1[h * HIDC + lane] + w1 * ad1[h * HIDC + lane + 32];
#pragma unroll
            for (int o = 16; o; o >>= 1) {
                ss += __shfl_xor_sync(0xffffffffu, ss, o);
                dd += __shfl_xor_sync(0xffffffffu, dd, o);
            }
            sp[h] = ss; dp[h] = dd;
        }
        if (!lane) {
            int p = (k & 3) * 32 + (k >> 2);
            d_wa1s[p] = s; d_wa1d[p] = d;
        }
    }
    {
        float4 s, d;
        float* sp = (float*)&s; float* dp = (float*)&d;
#pragma unroll
        for (int h = 0; h < NHEADS; h++) {
            float w0 = W2[(size_t)k * F1 + h * HIDC + lane];
            float w1 = W2[(size_t)k * F1 + h * HIDC + lane + 32];
            float ss = w0 * as2[h * HIDC + lane] + w1 * as2[h * HIDC + lane + 32];
            float dd = w0 * ad2[h * HIDC + lane] + w1 * ad2[h * HIDC + lane + 32];
#pragma unroll
            for (int o = 16; o; o >>= 1) {
                ss += __shfl_xor_sync(0xffffffffu, ss, o);
                dd += __shfl_xor_sync(0xffffffffu, dd, o);
            }
            sp[h] = ss; dp[h] = dd;
        }
        float w0 = W3[(size_t)k * HIDC + lane];
        float w1 = W3[(size_t)k * HIDC + lane + 32];
        float s3 = w0 * as3[lane] + w1 * as3[lane + 32];
        float d3 = w0 * ad3[lane] + w1 * ad3[lane + 32];
#pragma unroll
        for (int o = 16; o; o >>= 1) {
            s3 += __shfl_xor_sync(0xffffffffu, s3, o);
            d3 += __shfl_xor_sync(0xffffffffu, d3, o);
        }
        if (!lane) {
            int p = waperm4(k);
            d_wa2s[p] = s; d_wa2d[p] = d;
            d_wa3s[p] = s3; d_wa3d[p] = d3;
        }
    }
}

// ================= zero =================
__global__ void zero_all(int n) {
    int i = blockIdx.x * blockDim.x + threadIdx.x;
    if (i < n) { d_deg[i] = 0; d_cur[i] = 0; }
    if (i < GG * HIDC) d_pool[i] = 0.f;
    if (i < GG) d_cnt[i] = 0.f;
}

// ================= CSR construction =================
__global__ void hist_k(const int* __restrict__ ei, int E, int n) {
    int e = blockIdx.x * blockDim.x + threadIdx.x;
    int Etot = E + n;
    if (e >= Etot) return;
    int d = (e < E) ? __ldg(&ei[E + e]) : (e - E);
    atomicAdd(&d_deg[d], 1);
}

__global__ void scan_blk(int n) {
    int i = blockIdx.x * 1024 + threadIdx.x;
    int lane = threadIdx.x & 31, wid = threadIdx.x >> 5;
    int v = (i < n) ? d_deg[i] : 0;
    int x = v;
#pragma unroll
    for (int o = 1; o < 32; o <<= 1) {
        int t = __shfl_up_sync(0xffffffffu, x, o);
        if (lane >= o) x += t;
    }
    __shared__ int ws[32];
    if (lane == 31) ws[wid] = x;
    __syncthreads();
    if (wid == 0) {
        int y = ws[lane];
#pragma unroll
        for (int o = 1; o < 32; o <<= 1) {
            int t = __shfl_up_sync(0xffffffffu, y, o);
            if (lane >= o) y += t;
        }
        ws[lane] = y;
    }
    __syncthreads();
    int incl = x + (wid ? ws[wid - 1] : 0);
    if (i < n) d_off[i] = incl - v;
    if (threadIdx.x == 1023) d_bsum[blockIdx.x] = incl;
}

__global__ void scan_top(int nb) {
    int tid = threadIdx.x;
    int lane = tid & 31, wid = tid >> 5;
    int v = (tid < nb) ? d_bsum[tid] : 0;
    int x = v;
#pragma unroll
    for (int o = 1; o < 32; o <<= 1) {
        int t = __shfl_up_sync(0xffffffffu, x, o);
        if (lane >= o) x += t;
    }
    __shared__ int w0;
    if (wid == 0 && lane == 31) w0 = x;
    __syncthreads();
    int incl = x + (wid ? w0 : 0);
    if (tid < nb) d_bsum[tid] = incl - v;
}

__global__ void scan_add(int n) {
    int i = blockIdx.x * 1024 + threadIdx.x;
    if (i < n) d_off[i] += d_bsum[blockIdx.x];
}

__global__ void scatter_k(const int* __restrict__ ei, int E, int n) {
    int e = blockIdx.x * blockDim.x + threadIdx.x;
    int Etot = E + n;
    if (e >= Etot) return;
    int s, d;
    if (e < E) { s = __ldg(&ei[e]); d = __ldg(&ei[E + e]); } else { s = d = e - E; }
    int pos = d_off[d] + atomicAdd(&d_cur[d], 1);
    d_csr_src[pos] = s;
}

// ================= layer-1 attention coefficients =================
__global__ void gemv_attn(const float* __restrict__ x, int n) {
    __shared__ float4 ws[INC], wd[INC];
    for (int i = threadIdx.x; i < INC; i += 256) { ws[i] = d_wa1s[i]; wd[i] = d_wa1d[i]; }
    __syncthreads();
    int warp = (blockIdx.x * blockDim.x + threadIdx.x) >> 5;
    int lane = threadIdx.x & 31;
    if (warp >= n) return;
    float4 xv = *reinterpret_cast<const float4*>(&x[(size_t)warp * INC + lane * 4]);
    float xr[4] = {xv.x, xv.y, xv.z, xv.w};
    float ps[NHEADS] = {}, pd[NHEADS] = {};
#pragma unroll
    for (int j = 0; j < 4; j++) {
        float4 a = ws[j * 32 + lane];
        float4 b = wd[j * 32 + lane];
        ps[0] = fmaf(xr[j], a.x, ps[0]); ps[1] = fmaf(xr[j], a.y, ps[1]);
        ps[2] = fmaf(xr[j], a.z, ps[2]); ps[3] = fmaf(xr[j], a.w, ps[3]);
        pd[0] = fmaf(xr[j], b.x, pd[0]); pd[1] = fmaf(xr[j], b.y, pd[1]);
        pd[2] = fmaf(xr[j], b.z, pd[2]); pd[3] = fmaf(xr[j], b.w, pd[3]);
    }
#pragma unroll
    for (int h = 0; h < NHEADS; h++) {
#pragma unroll
        for (int o = 16; o; o >>= 1) {
            ps[h] += __shfl_xor_sync(0xffffffffu, ps[h], o);
            pd[h] += __shfl_xor_sync(0xffffffffu, pd[h], o);
        }
    }
    if (!lane) {
#pragma unroll
        for (int h = 0; h < NHEADS; h++) {
            d_asrcA[warp * NHEADS + h] = ps[h];
            d_adstA[warp * NHEADS + h] = pd[h];
        }
    }
}

// ================= TF32 GEMM: cp.async double buffer; B pre-rounded =================
__device__ __forceinline__ void mma_tf32(float c[4], uint32_t a0, uint32_t a1,
                                         uint32_t a2, uint32_t a3,
                                         uint32_t b0, uint32_t b1) {
    asm volatile(
        "mma.sync.aligned.m16n8k8.row.col.f32.tf32.tf32.f32 "
        "{%0,%1,%2,%3}, {%4,%5,%6,%7}, {%8,%9}, {%0,%1,%2,%3};"
        : "+f"(c[0]), "+f"(c[1]), "+f"(c[2]), "+f"(c[3])
        : "r"(a0), "r"(a1), "r"(a2), "r"(a3), "r"(b0), "r"(b1));
}

__device__ __forceinline__ void cp16p(void* smem_dst, const void* gsrc, bool pred) {
    unsigned sa = (unsigned)__cvta_generic_to_shared(smem_dst);
    int sz = pred ? 16 : 0;
    asm volatile("cp.async.ca.shared.global [%0], [%1], 16, %2;\n" :: "r"(sa), "l"(gsrc), "r"(sz));
}
__device__ __forceinline__ void cp_commit() { asm volatile("cp.async.commit_group;"); }
template <int N>
__device__ __forceinline__ void cp_wait() { asm volatile("cp.async.wait_group %0;" :: "n"(N)); }

template <int K, int NOUT, bool AG, int BN, int WM, int WN, int WSEL>
__launch_bounds__(256, 2)
__global__ void tgemm_k(const float* __restrict__ Ain, int M) {
    constexpr int BM = 128, BK = 16;
    constexpr int MT = BM / (WM * 16);
    constexpr int NT = BN / (WN * 8);
    __shared__ float    As[2][BM][BK + 4];
    __shared__ uint32_t Bs[2][BK][BN + 8];
    const float* A = AG ? (const float*)d_feat : Ain;
    const uint32_t* Bt = (WSEL == 1) ? (const uint32_t*)d_W1t
                       : (WSEL == 2) ? (const uint32_t*)d_W2t
                                     : (const uint32_t*)d_W3t;

    int tid = threadIdx.x;
    int wid = tid >> 5, lane = tid & 31;
    int wm = wid % WM, wn = wid / WM;
    int row0 = blockIdx.y * BM;
    int col0 = blockIdx.x * BN;
    int lr = lane >> 2, lc = lane & 3;

    float c[MT][NT][4];
#pragma unroll
    for (int i = 0; i < MT; i++)
#pragma unroll
        for (int j = 0; j < NT; j++)
#pragma unroll
            for (int q = 0; q < 4; q++) c[i][j][q] = 0.f;

    constexpr int B4 = BN / 4;
    constexpr int BLD = (BK * B4) / 256;
    const int nk = K / BK;

    {
#pragma unroll
        for (int j = 0; j < 2; j++) {
            int idx = tid + j * 256;
            int r = idx >> 2, q = idx & 3;
            cp16p(&As[0][r][q * 4], &A[(size_t)(row0 + r) * K + q * 4], (row0 + r) < M);
        }
#pragma unroll
        for (int j = 0; j < BLD; j++) {
            int idx = tid + j * 256;
            int r = idx / B4, q = idx % B4;
            cp16p(&Bs[0][r][q * 4], &Bt[(size_t)r * NOUT + col0 + q * 4], true);
        }
        cp_commit();
    }

    for (int t = 0; t < nk; t++) {
        int cur = t & 1;
        if (t + 1 < nk) {
            int k0 = (t + 1) * BK;
#pragma unroll
            for (int j = 0; j < 2; j++) {
                int idx = tid + j * 256;
                int r = idx >> 2, q = idx & 3;
                cp16p(&As[1 - cur][r][q * 4], &A[(size_t)(row0 + r) * K + k0 + q * 4], (row0 + r) < M);
            }
#pragma unroll
            for (int j = 0; j < BLD; j++) {
                int idx = tid + j * 256;
                int r = idx / B4, q = idx % B4;
                cp16p(&Bs[1 - cur][r][q * 4], &Bt[(size_t)(k0 + r) * NOUT + col0 + q * 4], true);
            }
            cp_commit();
            cp_wait<1>();
        } else {
            cp_wait<0>();
        }
        __syncthreads();

#pragma unroll
        for (int kk = 0; kk < BK; kk += 8) {
            uint32_t af[MT][4], bf[NT][2];
#pragma unroll
            for (int mt = 0; mt < MT; mt++) {
                int bm = wm * MT * 16 + mt * 16;
                af[mt][0] = cvt_tf32(As[cur][bm + lr][kk + lc]);
                af[mt][1] = cvt_tf32(As[cur][bm + lr + 8][kk + lc]);
                af[mt][2] = cvt_tf32(As[cur][bm + lr][kk + lc + 4]);
                af[mt][3] = cvt_tf32(As[cur][bm + lr + 8][kk + lc + 4]);
            }
#pragma unroll
            for (int nt = 0; nt < NT; nt++) {
                int bn = wn * NT * 8 + nt * 8;
                bf[nt][0] = Bs[cur][kk + lc][bn + lr];
                bf[nt][1] = Bs[cur][kk + lc + 4][bn + lr];
            }
#pragma unroll
            for (int mt = 0; mt < MT; mt++)
#pragma unroll
                for (int nt = 0; nt < NT; nt++)
                    mma_tf32(c[mt][nt], af[mt][0], af[mt][1], af[mt][2], af[mt][3],
                             bf[nt][0], bf[nt][1]);
        }
        __syncthreads();
    }

#pragma unroll
    for (int mt = 0; mt < MT; mt++) {
        int r0 = row0 + wm * MT * 16 + mt * 16 + lr;
#pragma unroll
        for (int nt = 0; nt < NT; nt++) {
            int cc = col0 + wn * NT * 8 + nt * 8 + 2 * lc;
            if (r0 < M)
                *reinterpret_cast<float2*>(&d_h[(size_t)r0 * NOUT + cc]) =
                    make_float2(c[mt][nt][0], c[mt][nt][1]);
            if (r0 + 8 < M)
                *reinterpret_cast<float2*>(&d_h[(size_t)(r0 + 8) * NOUT + cc]) =
                    make_float2(c[mt][nt][2], c[mt][nt][3]);
        }
    }
}

// ================= fused aggregation: one head (64 ch) per warp =================
// H=4: WPN=4 warps/node (sub = head). H=1: WPN=1. RF=2 channels per lane always.
template <int H, int HN, bool DOELU, bool SRCA, bool POOL>
__launch_bounds__(256)
__global__ void agg_k(const float* __restrict__ bias, const int* __restrict__ batch, int n) {
    constexpr int WPN = (H == 4) ? 4 : 1;
    constexpr int F = H * 64, CH = 64, RF = 2;
    __shared__ float4 wsn4[HN == 4 ? F : 1], wdn4[HN == 4 ? F : 1];
    __shared__ float  wsn1[HN == 1 ? F : 1], wdn1[HN == 1 ? F : 1];
    __shared__ float  parts[8][8];
    if (HN == 4) {
        for (int i = threadIdx.x; i < F; i += 256) { wsn4[i] = d_wa2s[i]; wdn4[i] = d_wa2d[i]; }
        __syncthreads();
    } else if (HN == 1) {
        for (int i = threadIdx.x; i < F; i += 256) { wsn1[i] = d_wa3s[i]; wdn1[i] = d_wa3d[i]; }
        __syncthreads();
    }
    const float* asrc  = SRCA ? d_asrcA : d_asrcB;
    const float* adstp = SRCA ? d_adstA : d_adstB;
    float* nsrc = SRCA ? d_asrcB : d_asrcA;
    float* ndst = SRCA ? d_adstB : d_adstA;

    int gw   = (blockIdx.x * blockDim.x + threadIdx.x) >> 5;
    int wblk = threadIdx.x >> 5;
    int lane = threadIdx.x & 31;
    int node = gw / WPN;
    int sub  = gw % WPN;   // == head for H=4
    bool valid = node < n;

    float acc[RF] = {0.f, 0.f};

    if (valid) {
        int off = d_off[node], deg = d_deg[node];
        const float adh = adstp[node * H + sub];

        // phase 1: online softmax for this warp's head
        float mx = -FLTMAX, sv = 0.f;
        for (int j = lane; j < deg; j += 32) {
            int s = d_csr_src[off + j];
            float v = asrc[s * H + sub] + adh;
            v = v > 0.f ? v : NEG * v;
            float nm = fmaxf(mx, v);
            sv = sv * __expf(mx - nm) + __expf(v - nm);
            mx = nm;
        }
#pragma unroll
        for (int o = 16; o; o >>= 1) {
            float om = __shfl_xor_sync(0xffffffffu, mx, o);
            float os = __shfl_xor_sync(0xffffffffu, sv, o);
            float nm = fmaxf(mx, om);
            sv = sv * __expf(mx - nm) + os * __expf(om - nm);
            mx = nm;
        }
        sv = 1.f / (sv + EPSV);

        // phase 2: weighted gather (float2 per lane), chunked x4
        const size_t cbase = sub * CH + lane * RF;

        int j = 0;
        for (; j + 4 <= deg; j += 4) {
            int s0 = d_csr_src[off + j];
            int s1 = d_csr_src[off + j + 1];
            int s2 = d_csr_src[off + j + 2];
            int s3 = d_csr_src[off + j + 3];
            float e0 = asrc[s0 * H + sub], e1 = asrc[s1 * H + sub];
            float e2 = asrc[s2 * H + sub], e3 = asrc[s3 * H + sub];
            e0 += adh; e1 += adh; e2 += adh; e3 += adh;
            e0 = e0 > 0.f ? e0 : NEG * e0;  e1 = e1 > 0.f ? e1 : NEG * e1;
            e2 = e2 > 0.f ? e2 : NEG * e2;  e3 = e3 > 0.f ? e3 : NEG * e3;
            float w0 = __expf(e0 - mx) * sv, w1 = __expf(e1 - mx) * sv;
            float w2 = __expf(e2 - mx) * sv, w3 = __expf(e3 - mx) * sv;
            float2 v0 = *reinterpret_cast<const float2*>(&d_h[(size_t)s0 * F + cbase]);
            float2 v1 = *reinterpret_cast<const float2*>(&d_h[(size_t)s1 * F + cbase]);
            float2 v2 = *reinterpret_cast<const float2*>(&d_h[(size_t)s2 * F + cbase]);
            float2 v3 = *reinterpret_cast<const float2*>(&d_h[(size_t)s3 * F + cbase]);
            acc[0] = fmaf(w0, v0.x, acc[0]); acc[1] = fmaf(w0, v0.y, acc[1]);
            acc[0] = fmaf(w1, v1.x, acc[0]); acc[1] = fmaf(w1, v1.y, acc[1]);
            acc[0] = fmaf(w2, v2.x, acc[0]); acc[1] = fmaf(w2, v2.y, acc[1]);
            acc[0] = fmaf(w3, v3.x, acc[0]); acc[1] = fmaf(w3, v3.y, acc[1]);
        }
        for (; j < deg; j++) {
            int s = d_csr_src[off + j];
            float v = asrc[s * H + sub] + adh;
            v = v > 0.f ? v : NEG * v;
            float w = __expf(v - mx) * sv;
            float2 v0 = *reinterpret_cast<const float2*>(&d_h[(size_t)s * F + cbase]);
            acc[0] = fmaf(w, v0.x, acc[0]); acc[1] = fmaf(w, v0.y, acc[1]);
        }

        // bias + optional ELU
#pragma unroll
        for (int k = 0; k < RF; k++) {
            float v = acc[k] + bias[sub * CH + lane * RF + k];
            if (DOELU) v = v > 0.f ? v : (__expf(v) - 1.f);
            acc[k] = v;
        }

        if (POOL) {
            int g = __ldg(&batch[node]);
            atomicAdd(&d_pool[g * HIDC + lane * RF + 0], acc[0]);
            atomicAdd(&d_pool[g * HIDC + lane * RF + 1], acc[1]);
            if (!lane) atomicAdd(&d_cnt[g], 1.0f);
        } else {
            *reinterpret_cast<float2*>(&d_feat[(size_t)node * F + sub * CH + lane * RF]) =
                make_float2(acc[0], acc[1]);
        }

        // partial next-layer coefficients over this warp's 64 channels
        if (HN == 4) {
            float ps[4] = {}, pd[4] = {};
#pragma unroll
            for (int k = 0; k < RF; k++) {
                float4 a = wsn4[sub * CH + k * 32 + lane];
                float4 b = wdn4[sub * CH + k * 32 + lane];
                ps[0] = fmaf(acc[k], a.x, ps[0]); ps[1] = fmaf(acc[k], a.y, ps[1]);
                ps[2] = fmaf(acc[k], a.z, ps[2]); ps[3] = fmaf(acc[k], a.w, ps[3]);
                pd[0] = fmaf(acc[k], b.x, pd[0]); pd[1] = fmaf(acc[k], b.y, pd[1]);
                pd[2] = fmaf(acc[k], b.z, pd[2]); pd[3] = fmaf(acc[k], b.w, pd[3]);
            }
#pragma unroll
            for (int h = 0; h < 4; h++) {
#pragma unroll
                for (int o = 16; o; o >>= 1) {
                    ps[h] += __shfl_xor_sync(0xffffffffu, ps[h], o);
                    pd[h] += __shfl_xor_sync(0xffffffffu, pd[h], o);
                }
            }
            if (!lane) {
#pragma unroll
                for (int h = 0; h < 4; h++) {
                    parts[wblk][h] = ps[h];
                    parts[wblk][4 + h] = pd[h];
                }
            }
        } else if (HN == 1) {
            float ps = 0.f, pd = 0.f;
#pragma unroll
            for (int k = 0; k < RF; k++) {
                ps = fmaf(acc[k], wsn1[sub * CH + k * 32 + lane], ps);
                pd = fmaf(acc[k], wdn1[sub * CH + k * 32 + lane], pd);
            }
#pragma unroll
            for (int o = 16; o; o >>= 1) {
                ps += __shfl_xor_sync(0xffffffffu, ps, o);
                pd += __shfl_xor_sync(0xffffffffu, pd, o);
            }
            if (!lane) { parts[wblk][0] = ps; parts[wblk][1] = pd; }
        }
    }

    // cross-sub combine (WPN warps of one node are adjacent in the block)
    if (HN > 0) {
        __syncthreads();
        if (valid && sub == 0 && !lane) {
            int wb = wblk;   // first warp of this node's group
            if (HN == 4) {
#pragma unroll
                for (int h = 0; h < 4; h++) {
                    float s = 0.f, d = 0.f;
#pragma unroll
                    for (int q = 0; q < WPN; q++) { s += parts[wb + q][h]; d += parts[wb + q][4 + h]; }
                    nsrc[node * 4 + h] = s;
                    ndst[node * 4 + h] = d;
                }
            } else {
                float s = 0.f, d = 0.f;
#pragma unroll
                for (int q = 0; q < WPN; q++) { s += parts[wb + q][0]; d += parts[wb + q][1]; }
                nsrc[node] = s;
                ndst[node] = d;
            }
        }
    }
}

// ---------------- head ----------------
__global__ void head_k(const float* __restrict__ Wc, const float* __restrict__ bc,
                       float* __restrict__ out) {
    int t = blockIdx.x * blockDim.x + threadIdx.x;
    if (t >= GG * OUTC) return;
    int g = t / OUTC, o = t % OUTC;
    float inv = 1.f / fmaxf(d_cnt[g], 1.f);
    float s = 0.f;
#pragma unroll
    for (int c = 0; c < HIDC; c++) s += d_pool[g * HIDC + c] * Wc[c * OUTC + o];
    out[t] = s * inv + bc[o];
}

// ---------------- host orchestration ----------------
extern "C" void kernel_launch(void* const* d_in, const int* in_sizes, int n_in,
                              void* d_out, int out_size) {
    const float* x   = (const float*)d_in[0];
    const int*   ei  = (const int*)d_in[1];
    const int*   bat = (const int*)d_in[2];
    const float* W1 = (const float*)d_in[3],  *as1 = (const float*)d_in[4],
               * ad1 = (const float*)d_in[5], *b1  = (const float*)d_in[6];
    const float* W2 = (const float*)d_in[7],  *as2 = (const float*)d_in[8],
               * ad2 = (const float*)d_in[9], *b2  = (const float*)d_in[10];
    const float* W3 = (const float*)d_in[11], *as3 = (const float*)d_in[12],
               * ad3 = (const float*)d_in[13],*b3  = (const float*)d_in[14];
    const float* Wc = (const float*)d_in[15], *bc  = (const float*)d_in[16];
    float* out = (float*)d_out;

    int n    = in_sizes[0] / INC;
    int E    = in_sizes[1] / 2;
    int Etot = E + n;

    int gemm_rows = (n + 127) / 128;
    int eb    = (Etot + 255) / 256;
    int nb    = (n + 255) / 256;
    int sb    = (n + 1023) / 1024;
    int aggb4 = (int)(((long long)n * 4 * 32 + 255) / 256);   // 4 warps per node
    int aggb1 = (int)(((long long)n * 32 + 255) / 256);       // 1 warp per node

    wa_prep<<<32, 256>>>(W1, as1, ad1, W2, as2, ad2, W3, as3, ad3);         // 0
    round_w<<<(F1 * F1 + 255) / 256, 256>>>(W1, W2, W3);                    // 1
    zero_all<<<nb, 256>>>(n);                                               // 2
    tgemm_k<INC, F1, false, 128, 2, 4, 1><<<dim3(F1 / 128, gemm_rows), 256>>>(x, n); // 3
    hist_k<<<eb, 256>>>(ei, E, n);                                          // 4
    scan_blk<<<sb, 1024>>>(n);                                              // 5
    scan_top<<<1, 64>>>(sb);                                                // 6
    scan_add<<<sb, 1024>>>(n);                                              // 7
    scatter_k<<<eb, 256>>>(ei, E, n);                                       // 8
    gemv_attn<<<(n + 7) / 8, 256>>>(x, n);                                  // 9

    // ---- Layer 1 agg (H=4, 4 warps/node); writes layer-2 coeffs ----
    agg_k<NHEADS, NHEADS, true, true, false><<<aggb4, 256>>>(b1, nullptr, n);

    // ---- Layer 2 (H=4, in=256, out=256) ----
    tgemm_k<F1, F1, true, 128, 2, 4, 2><<<dim3(F1 / 128, gemm_rows), 256>>>(nullptr, n);
    agg_k<NHEADS, 1, true, false, false><<<aggb4, 256>>>(b2, nullptr, n);

    // ---- Layer 3 (H=1, in=256, out=64) ----
    tgemm_k<F1, HIDC, true, 64, 4, 2, 3><<<dim3(1, gemm_rows), 256>>>(nullptr, n);
    agg_k<1, 0, false, true, true><<<aggb1, 256>>>(b3, bat, n);

    // ---- head ----
    head_k<<<(GG * OUTC + 255) / 256, 256>>>(Wc, bc, out);
}

// round 13
// speedup vs baseline: 1.5333x; 1.2349x over previous
#include <cuda_runtime.h>
#include <cstdint>

// ---------------- Problem constants ----------------
#define NMAX    50000
#define EMAX    800000
#define ETOTMAX (EMAX + NMAX)
#define GG      64
#define INC     128
#define HIDC    64
#define NHEADS  4
#define F1      (NHEADS * HIDC)   // 256
#define OUTC    10
#define NEG     0.2f
#define EPSV    1e-16f
#define FLTMAX  3.402823466e38f
#define DBINS   1024

// ---------------- Device scratch ----------------
__device__ float d_h[(size_t)NMAX * F1];
__device__ float d_feat[(size_t)NMAX * F1];
__device__ __align__(16) float d_asrcA[NMAX * NHEADS];
__device__ __align__(16) float d_adstA[NMAX * NHEADS];
__device__ __align__(16) float d_asrcB[NMAX * NHEADS];
__device__ __align__(16) float d_adstB[NMAX * NHEADS];
__device__ int   d_deg[NMAX];
__device__ int   d_off[NMAX];
__device__ int   d_cur[NMAX];
__device__ int   d_bsum[64];
__device__ int   d_csr_src[ETOTMAX];
__device__ int   d_dhist[DBINS];
__device__ int   d_dcur[DBINS];
__device__ int   d_perm[NMAX];
__device__ float d_pool[GG * HIDC];
__device__ float d_cnt[GG];
// precomputed W @ a vectors, PERMUTED: p(ch) = (ch>>7)*128 + (ch&3)*32 + ((ch>>2)&31)
__device__ float4 d_wa1s[INC], d_wa1d[INC];
__device__ float4 d_wa2s[F1],  d_wa2d[F1];
__device__ float  d_wa3s[F1],  d_wa3d[F1];

__device__ __forceinline__ int waperm(int ch) {
    return (ch >> 7) * 128 + (ch & 3) * 32 + ((ch >> 2) & 31);
}

// ================= wa precompute: warp per k, coalesced =================
__global__ void wa_prep(const float* __restrict__ W1, const float* __restrict__ as1, const float* __restrict__ ad1,
                        const float* __restrict__ W2, const float* __restrict__ as2, const float* __restrict__ ad2,
                        const float* __restrict__ W3, const float* __restrict__ as3, const float* __restrict__ ad3) {
    int gw = (blockIdx.x * blockDim.x + threadIdx.x) >> 5;
    int lane = threadIdx.x & 31;
    if (gw >= F1) return;
    int k = gw;

    if (k < INC) {
        float4 s, d;
        float* sp = (float*)&s; float* dp = (float*)&d;
#pragma unroll
        for (int h = 0; h < NHEADS; h++) {
            float w0 = W1[(size_t)k * F1 + h * HIDC + lane];
            float w1 = W1[(size_t)k * F1 + h * HIDC + lane + 32];
            float ss = w0 * as1[h * HIDC + lane] + w1 * as1[h * HIDC + lane + 32];
            float dd = w0 * ad1[h * HIDC + lane] + w1 * ad1[h * HIDC + lane + 32];
#pragma unroll
            for (int o = 16; o; o >>= 1) {
                ss += __shfl_xor_sync(0xffffffffu, ss, o);
                dd += __shfl_xor_sync(0xffffffffu, dd, o);
            }
            sp[h] = ss; dp[h] = dd;
        }
        if (!lane) {
            int p = (k & 3) * 32 + (k >> 2);
            d_wa1s[p] = s; d_wa1d[p] = d;
        }
    }
    {
        float4 s, d;
        float* sp = (float*)&s; float* dp = (float*)&d;
#pragma unroll
        for (int h = 0; h < NHEADS; h++) {
            float w0 = W2[(size_t)k * F1 + h * HIDC + lane];
            float w1 = W2[(size_t)k * F1 + h * HIDC + lane + 32];
            float ss = w0 * as2[h * HIDC + lane] + w1 * as2[h * HIDC + lane + 32];
            float dd = w0 * ad2[h * HIDC + lane] + w1 * ad2[h * HIDC + lane + 32];
#pragma unroll
            for (int o = 16; o; o >>= 1) {
                ss += __shfl_xor_sync(0xffffffffu, ss, o);
                dd += __shfl_xor_sync(0xffffffffu, dd, o);
            }
            sp[h] = ss; dp[h] = dd;
        }
        float w0 = W3[(size_t)k * HIDC + lane];
        float w1 = W3[(size_t)k * HIDC + lane + 32];
        float s3 = w0 * as3[lane] + w1 * as3[lane + 32];
        float d3 = w0 * ad3[lane] + w1 * ad3[lane + 32];
#pragma unroll
        for (int o = 16; o; o >>= 1) {
            s3 += __shfl_xor_sync(0xffffffffu, s3, o);
            d3 += __shfl_xor_sync(0xffffffffu, d3, o);
        }
        if (!lane) {
            int p = waperm(k);
            d_wa2s[p] = s; d_wa2d[p] = d;
            d_wa3s[p] = s3; d_wa3d[p] = d3;
        }
    }
}

// ================= zero =================
__global__ void zero_all(int n) {
    int i = blockIdx.x * blockDim.x + threadIdx.x;
    if (i < n) { d_deg[i] = 0; d_cur[i] = 0; }
    if (i < GG * HIDC) d_pool[i] = 0.f;
    if (i < GG) d_cnt[i] = 0.f;
    if (i < DBINS) { d_dhist[i] = 0; d_dcur[i] = 0; }
}

// ================= CSR construction =================
__global__ void hist_k(const int* __restrict__ ei, int E, int n) {
    int e = blockIdx.x * blockDim.x + threadIdx.x;
    int Etot = E + n;
    if (e >= Etot) return;
    int d = (e < E) ? __ldg(&ei[E + e]) : (e - E);
    atomicAdd(&d_deg[d], 1);
}

__global__ void scan_blk(int n) {
    int i = blockIdx.x * 1024 + threadIdx.x;
    int lane = threadIdx.x & 31, wid = threadIdx.x >> 5;
    int v = (i < n) ? d_deg[i] : 0;
    int x = v;
#pragma unroll
    for (int o = 1; o < 32; o <<= 1) {
        int t = __shfl_up_sync(0xffffffffu, x, o);
        if (lane >= o) x += t;
    }
    __shared__ int ws[32];
    if (lane == 31) ws[wid] = x;
    __syncthreads();
    if (wid == 0) {
        int y = ws[lane];
#pragma unroll
        for (int o = 1; o < 32; o <<= 1) {
            int t = __shfl_up_sync(0xffffffffu, y, o);
            if (lane >= o) y += t;
        }
        ws[lane] = y;
    }
    __syncthreads();
    int incl = x + (wid ? ws[wid - 1] : 0);
    if (i < n) d_off[i] = incl - v;
    if (threadIdx.x == 1023) d_bsum[blockIdx.x] = incl;
}

__global__ void scan_top(int nb) {
    int tid = threadIdx.x;
    int lane = tid & 31, wid = tid >> 5;
    int v = (tid < nb) ? d_bsum[tid] : 0;
    int x = v;
#pragma unroll
    for (int o = 1; o < 32; o <<= 1) {
        int t = __shfl_up_sync(0xffffffffu, x, o);
        if (lane >= o) x += t;
    }
    __shared__ int w0;
    if (wid == 0 && lane == 31) w0 = x;
    __syncthreads();
    int incl = x + (wid ? w0 : 0);
    if (tid < nb) d_bsum[tid] = incl - v;
}

__global__ void scan_add(int n) {
    int i = blockIdx.x * 1024 + threadIdx.x;
    if (i < n) d_off[i] += d_bsum[blockIdx.x];
}

__global__ void scatter_k(const int* __restrict__ ei, int E, int n) {
    int e = blockIdx.x * blockDim.x + threadIdx.x;
    int Etot = E + n;
    if (e >= Etot) return;
    int s, d;
    if (e < E) { s = __ldg(&ei[e]); d = __ldg(&ei[E + e]); } else { s = d = e - E; }
    int pos = d_off[d] + atomicAdd(&d_cur[d], 1);
    d_csr_src[pos] = s;
}

// ================= degree-sorted node permutation =================
__global__ void dhist_k(int n) {
    int i = blockIdx.x * blockDim.x + threadIdx.x;
    if (i >= n) return;
    int b = min(d_deg[i], DBINS - 1);
    atomicAdd(&d_dhist[b], 1);
}

__global__ void dscan_k() {    // exclusive scan of 1024 bins, one block
    int tid = threadIdx.x;     // 1024 threads
    int lane = tid & 31, wid = tid >> 5;
    int v = d_dhist[tid];
    int x = v;
#pragma unroll
    for (int o = 1; o < 32; o <<= 1) {
        int t = __shfl_up_sync(0xffffffffu, x, o);
        if (lane >= o) x += t;
    }
    __shared__ int ws[32];
    if (lane == 31) ws[wid] = x;
    __syncthreads();
    if (wid == 0) {
        int y = ws[lane];
#pragma unroll
        for (int o = 1; o < 32; o <<= 1) {
            int t = __shfl_up_sync(0xffffffffu, y, o);
            if (lane >= o) y += t;
        }
        ws[lane] = y;
    }
    __syncthreads();
    int incl = x + (wid ? ws[wid - 1] : 0);
    d_dhist[tid] = incl - v;   // exclusive offset
}

__global__ void dscatter_k(int n) {
    int i = blockIdx.x * blockDim.x + threadIdx.x;
    if (i >= n) return;
    int b = min(d_deg[i], DBINS - 1);
    int pos = d_dhist[b] + atomicAdd(&d_dcur[b], 1);
    d_perm[pos] = i;
}

// ================= layer-1 attention coefficients =================
__global__ void gemv_attn(const float* __restrict__ x, int n) {
    __shared__ float4 ws[INC], wd[INC];
    for (int i = threadIdx.x; i < INC; i += 256) { ws[i] = d_wa1s[i]; wd[i] = d_wa1d[i]; }
    __syncthreads();
    int warp = (blockIdx.x * blockDim.x + threadIdx.x) >> 5;
    int lane = threadIdx.x & 31;
    if (warp >= n) return;
    float4 xv = *reinterpret_cast<const float4*>(&x[(size_t)warp * INC + lane * 4]);
    float xr[4] = {xv.x, xv.y, xv.z, xv.w};
    float ps[NHEADS] = {}, pd[NHEADS] = {};
#pragma unroll
    for (int j = 0; j < 4; j++) {
        float4 a = ws[j * 32 + lane];
        float4 b = wd[j * 32 + lane];
        ps[0] = fmaf(xr[j], a.x, ps[0]); ps[1] = fmaf(xr[j], a.y, ps[1]);
        ps[2] = fmaf(xr[j], a.z, ps[2]); ps[3] = fmaf(xr[j], a.w, ps[3]);
        pd[0] = fmaf(xr[j], b.x, pd[0]); pd[1] = fmaf(xr[j], b.y, pd[1]);
        pd[2] = fmaf(xr[j], b.z, pd[2]); pd[3] = fmaf(xr[j], b.w, pd[3]);
    }
#pragma unroll
    for (int h = 0; h < NHEADS; h++) {
#pragma unroll
        for (int o = 16; o; o >>= 1) {
            ps[h] += __shfl_xor_sync(0xffffffffu, ps[h], o);
            pd[h] += __shfl_xor_sync(0xffffffffu, pd[h], o);
        }
    }
    if (!lane) {
#pragma unroll
        for (int h = 0; h < NHEADS; h++) {
            d_asrcA[warp * NHEADS + h] = ps[h];
            d_adstA[warp * NHEADS + h] = pd[h];
        }
    }
}

// ================= TF32 GEMM (R9 version: cp.async double buffer, cvt at frag load) ======
__device__ __forceinline__ uint32_t cvt_tf32(float x) {
    uint32_t u;
    asm("cvt.rna.tf32.f32 %0, %1;" : "=r"(u) : "f"(x));
    return u;
}

__device__ __forceinline__ void mma_tf32(float c[4], uint32_t a0, uint32_t a1,
                                         uint32_t a2, uint32_t a3,
                                         uint32_t b0, uint32_t b1) {
    asm volatile(
        "mma.sync.aligned.m16n8k8.row.col.f32.tf32.tf32.f32 "
        "{%0,%1,%2,%3}, {%4,%5,%6,%7}, {%8,%9}, {%0,%1,%2,%3};"
        : "+f"(c[0]), "+f"(c[1]), "+f"(c[2]), "+f"(c[3])
        : "r"(a0), "r"(a1), "r"(a2), "r"(a3), "r"(b0), "r"(b1));
}

__device__ __forceinline__ void cp16p(float* smem_dst, const float* gsrc, bool pred) {
    unsigned sa = (unsigned)__cvta_generic_to_shared(smem_dst);
    int sz = pred ? 16 : 0;
    asm volatile("cp.async.ca.shared.global [%0], [%1], 16, %2;\n" :: "r"(sa), "l"(gsrc), "r"(sz));
}
__device__ __forceinline__ void cp_commit() { asm volatile("cp.async.commit_group;"); }
template <int N>
__device__ __forceinline__ void cp_wait() { asm volatile("cp.async.wait_group %0;" :: "n"(N)); }

template <int K, int NOUT, bool AG, int BN, int WM, int WN>
__launch_bounds__(256, 2)
__global__ void tgemm_k(const float* __restrict__ Ain, const float* __restrict__ B, int M) {
    constexpr int BM = 128, BK = 16;
    constexpr int MT = BM / (WM * 16);
    constexpr int NT = BN / (WN * 8);
    __shared__ float As[2][BM][BK + 4];
    __shared__ float Bs[2][BK][BN + 8];
    const float* A = AG ? (const float*)d_feat : Ain;

    int tid = threadIdx.x;
    int wid = tid >> 5, lane = tid & 31;
    int wm = wid % WM, wn = wid / WM;
    int row0 = blockIdx.y * BM;
    int col0 = blockIdx.x * BN;
    int lr = lane >> 2, lc = lane & 3;

    float c[MT][NT][4];
#pragma unroll
    for (int i = 0; i < MT; i++)
#pragma unroll
        for (int j = 0; j < NT; j++)
#pragma unroll
            for (int q = 0; q < 4; q++) c[i][j][q] = 0.f;

    constexpr int B4 = BN / 4;
    constexpr int BLD = (BK * B4) / 256;
    const int nk = K / BK;

    {
#pragma unroll
        for (int j = 0; j < 2; j++) {
            int idx = tid + j * 256;
            int r = idx >> 2, q = idx & 3;
            cp16p(&As[0][r][q * 4], &A[(size_t)(row0 + r) * K + q * 4], (row0 + r) < M);
        }
#pragma unroll
        for (int j = 0; j < BLD; j++) {
            int idx = tid + j * 256;
            int r = idx / B4, q = idx % B4;
            cp16p(&Bs[0][r][q * 4], &B[(size_t)r * NOUT + col0 + q * 4], true);
        }
        cp_commit();
    }

    for (int t = 0; t < nk; t++) {
        int cur = t & 1;
        if (t + 1 < nk) {
            int k0 = (t + 1) * BK;
#pragma unroll
            for (int j = 0; j < 2; j++) {
                int idx = tid + j * 256;
                int r = idx >> 2, q = idx & 3;
                cp16p(&As[1 - cur][r][q * 4], &A[(size_t)(row0 + r) * K + k0 + q * 4], (row0 + r) < M);
            }
#pragma unroll
            for (int j = 0; j < BLD; j++) {
                int idx = tid + j * 256;
                int r = idx / B4, q = idx % B4;
                cp16p(&Bs[1 - cur][r][q * 4], &B[(size_t)(k0 + r) * NOUT + col0 + q * 4], true);
            }
            cp_commit();
            cp_wait<1>();
        } else {
            cp_wait<0>();
        }
        __syncthreads();

#pragma unroll
        for (int kk = 0; kk < BK; kk += 8) {
            uint32_t af[MT][4], bf[NT][2];
#pragma unroll
            for (int mt = 0; mt < MT; mt++) {
                int bm = wm * MT * 16 + mt * 16;
                af[mt][0] = cvt_tf32(As[cur][bm + lr][kk + lc]);
                af[mt][1] = cvt_tf32(As[cur][bm + lr + 8][kk + lc]);
                af[mt][2] = cvt_tf32(As[cur][bm + lr][kk + lc + 4]);
                af[mt][3] = cvt_tf32(As[cur][bm + lr + 8][kk + lc + 4]);
            }
#pragma unroll
            for (int nt = 0; nt < NT; nt++) {
                int bn = wn * NT * 8 + nt * 8;
                bf[nt][0] = cvt_tf32(Bs[cur][kk + lc][bn + lr]);
                bf[nt][1] = cvt_tf32(Bs[cur][kk + lc + 4][bn + lr]);
            }
#pragma unroll
            for (int mt = 0; mt < MT; mt++)
#pragma unroll
                for (int nt = 0; nt < NT; nt++)
                    mma_tf32(c[mt][nt], af[mt][0], af[mt][1], af[mt][2], af[mt][3],
                             bf[nt][0], bf[nt][1]);
        }
        __syncthreads();
    }

#pragma unroll
    for (int mt = 0; mt < MT; mt++) {
        int r0 = row0 + wm * MT * 16 + mt * 16 + lr;
#pragma unroll
        for (int nt = 0; nt < NT; nt++) {
            int cc = col0 + wn * NT * 8 + nt * 8 + 2 * lc;
            if (r0 < M)
                *reinterpret_cast<float2*>(&d_h[(size_t)r0 * NOUT + cc]) =
                    make_float2(c[mt][nt][0], c[mt][nt][1]);
            if (r0 + 8 < M)
                *reinterpret_cast<float2*>(&d_h[(size_t)(r0 + 8) * NOUT + cc]) =
                    make_float2(c[mt][nt][2], c[mt][nt][3]);
        }
    }
}

// ================= fused aggregation: WPN warps per dst node, degree-sorted =============
template <int H, int WPN, int HN, bool DOELU, bool SRCA, bool POOL>
__launch_bounds__(256)
__global__ void agg_k(const float* __restrict__ bias, const int* __restrict__ batch, int n) {
    constexpr int C = 64, F = H * C, CH = F / WPN, RF = CH / 32;
    constexpr int HL = (H == 4) ? 2 : 1;
    __shared__ float4 wsn4[HN == 4 ? F : 1], wdn4[HN == 4 ? F : 1];
    __shared__ float  wsn1[HN == 1 ? F : 1], wdn1[HN == 1 ? F : 1];
    __shared__ float  parts[8][8];
    if (HN == 4) {
        for (int i = threadIdx.x; i < F; i += 256) { wsn4[i] = d_wa2s[i]; wdn4[i] = d_wa2d[i]; }
        __syncthreads();
    } else if (HN == 1) {
        for (int i = threadIdx.x; i < F; i += 256) { wsn1[i] = d_wa3s[i]; wdn1[i] = d_wa3d[i]; }
        __syncthreads();
    }
    const float* asrc  = SRCA ? d_asrcA : d_asrcB;
    const float* adstp = SRCA ? d_adstA : d_adstB;
    float* nsrc = SRCA ? d_asrcB : d_asrcA;
    float* ndst = SRCA ? d_adstB : d_adstA;

    int gw   = (blockIdx.x * blockDim.x + threadIdx.x) >> 5;
    int wblk = threadIdx.x >> 5;
    int lane = threadIdx.x & 31;
    int slot = gw / WPN;
    int sub  = gw % WPN;
    bool valid = slot < n;
    int node = valid ? d_perm[slot] : 0;   // degree-sorted mapping

    float acc[RF];
#pragma unroll
    for (int k = 0; k < RF; k++) acc[k] = 0.f;

    if (valid) {
        int off = d_off[node], deg = d_deg[node];

        float ad[HL];
#pragma unroll
        for (int h = 0; h < HL; h++) ad[h] = adstp[node * H + sub * HL + h];

        // phase 1: online softmax (lane-strided)
        float mx[HL], sv[HL];
#pragma unroll
        for (int h = 0; h < HL; h++) { mx[h] = -FLTMAX; sv[h] = 0.f; }
        for (int j = lane; j < deg; j += 32) {
            int s = d_csr_src[off + j];
            float av[HL];
            if (H == 4) {
                float2 a2 = *reinterpret_cast<const float2*>(&asrc[s * 4 + sub * 2]);
                av[0] = a2.x; av[1] = a2.y;
            } else {
                av[0] = asrc[s];
            }
#pragma unroll
            for (int h = 0; h < HL; h++) {
                float v = av[h] + ad[h];
                v = v > 0.f ? v : NEG * v;
                float nm = fmaxf(mx[h], v);
                sv[h] = sv[h] * __expf(mx[h] - nm) + __expf(v - nm);
                mx[h] = nm;
            }
        }
#pragma unroll
        for (int h = 0; h < HL; h++) {
#pragma unroll
            for (int o = 16; o; o >>= 1) {
                float om = __shfl_xor_sync(0xffffffffu, mx[h], o);
                float os = __shfl_xor_sync(0xffffffffu, sv[h], o);
                float nm = fmaxf(mx[h], om);
                sv[h] = sv[h] * __expf(mx[h] - nm) + os * __expf(om - nm);
                mx[h] = nm;
            }
            sv[h] = 1.f / (sv[h] + EPSV);
        }

        // phase 2: weighted gather; lane covers RF contiguous channels of its sub-slice
        const int hl = (H == 4) ? (lane >> 4) : 0;
        const float adh = ad[hl], mxh = mx[hl], svh = sv[hl];
        const int asoff = (H == 4) ? (sub * 2 + hl) : 0;
        const size_t cbase = sub * CH + lane * RF;

#pragma unroll 2
        for (int j = 0; j < deg; j++) {
            int s = d_csr_src[off + j];
            float v = asrc[s * H + asoff] + adh;
            v = v > 0.f ? v : NEG * v;
            float w = __expf(v - mxh) * svh;
            const float* hs = &d_h[(size_t)s * F + cbase];
            if (RF == 4) {
                float4 v0 = *reinterpret_cast<const float4*>(hs);
                acc[0] = fmaf(w, v0.x, acc[0]); acc[1] = fmaf(w, v0.y, acc[1]);
                acc[2] = fmaf(w, v0.z, acc[2]); acc[3] = fmaf(w, v0.w, acc[3]);
            } else {
                float2 v0 = *reinterpret_cast<const float2*>(hs);
                acc[0] = fmaf(w, v0.x, acc[0]); acc[1] = fmaf(w, v0.y, acc[1]);
            }
        }

        // bias + optional ELU
#pragma unroll
        for (int k = 0; k < RF; k++) {
            float v = acc[k] + bias[sub * CH + lane * RF + k];
            if (DOELU) v = v > 0.f ? v : (__expf(v) - 1.f);
            acc[k] = v;
        }

        if (POOL) {
            int g = __ldg(&batch[node]);
            atomicAdd(&d_pool[g * HIDC + lane * RF + 0], acc[0]);
            atomicAdd(&d_pool[g * HIDC + lane * RF + 1], acc[1]);
            if (!lane) atomicAdd(&d_cnt[g], 1.0f);
        } else {
            float* outp = &d_feat[(size_t)node * F + sub * CH + lane * RF];
            if (RF == 4)
                *reinterpret_cast<float4*>(outp) = make_float4(acc[0], acc[1], acc[2], acc[3]);
            else
                *reinterpret_cast<float2*>(outp) = make_float2(acc[0], acc[1]);
        }

        // partial next-layer coefficients
        if (HN == 4) {
            float ps[4] = {}, pd[4] = {};
#pragma unroll
            for (int k = 0; k < RF; k++) {
                float4 a = wsn4[sub * CH + k * 32 + lane];
                float4 b = wdn4[sub * CH + k * 32 + lane];
                ps[0] = fmaf(acc[k], a.x, ps[0]); ps[1] = fmaf(acc[k], a.y, ps[1]);
                ps[2] = fmaf(acc[k], a.z, ps[2]); ps[3] = fmaf(acc[k], a.w, ps[3]);
                pd[0] = fmaf(acc[k], b.x, pd[0]); pd[1] = fmaf(acc[k], b.y, pd[1]);
                pd[2] = fmaf(acc[k], b.z, pd[2]); pd[3] = fmaf(acc[k], b.w, pd[3]);
            }
#pragma unroll
            for (int h = 0; h < 4; h++) {
#pragma unroll
                for (int o = 16; o; o >>= 1) {
                    ps[h] += __shfl_xor_sync(0xffffffffu, ps[h], o);
                    pd[h] += __shfl_xor_sync(0xffffffffu, pd[h], o);
                }
            }
            if (!lane) {
#pragma unroll
                for (int h = 0; h < 4; h++) {
                    parts[wblk][h] = ps[h];
                    parts[wblk][4 + h] = pd[h];
                }
            }
        } else if (HN == 1) {
            float ps = 0.f, pd = 0.f;
#pragma unroll
            for (int k = 0; k < RF; k++) {
                ps = fmaf(acc[k], wsn1[sub * CH + k * 32 + lane], ps);
                pd = fmaf(acc[k], wdn1[sub * CH + k * 32 + lane], pd);
            }
#pragma unroll
            for (int o = 16; o; o >>= 1) {
                ps += __shfl_xor_sync(0xffffffffu, ps, o);
                pd += __shfl_xor_sync(0xffffffffu, pd, o);
            }
            if (!lane) { parts[wblk][0] = ps; parts[wblk][1] = pd; }
        }
    }

    if (HN > 0) {
        __syncthreads();
        if (valid && sub == 0 && !lane) {
            if (HN == 4) {
#pragma unroll
                for (int h = 0; h < 4; h++) {
                    nsrc[node * 4 + h] = parts[wblk][h]     + parts[wblk + 1][h];
                    ndst[node * 4 + h] = parts[wblk][4 + h] + parts[wblk + 1][4 + h];
                }
            } else {
                nsrc[node] = parts[wblk][0] + parts[wblk + 1][0];
                ndst[node] = parts[wblk][1] + parts[wblk + 1][1];
            }
        }
    }
}

// ---------------- head ----------------
__global__ void head_k(const float* __restrict__ Wc, const float* __restrict__ bc,
                       float* __restrict__ out) {
    int t = blockIdx.x * blockDim.x + threadIdx.x;
    if (t >= GG * OUTC) return;
    int g = t / OUTC, o = t % OUTC;
    float inv = 1.f / fmaxf(d_cnt[g], 1.f);
    float s = 0.f;
#pragma unroll
    for (int c = 0; c < HIDC; c++) s += d_pool[g * HIDC + c] * Wc[c * OUTC + o];
    out[t] = s * inv + bc[o];
}

// ---------------- host orchestration ----------------
extern "C" void kernel_launch(void* const* d_in, const int* in_sizes, int n_in,
                              void* d_out, int out_size) {
    const float* x   = (const float*)d_in[0];
    const int*   ei  = (const int*)d_in[1];
    const int*   bat = (const int*)d_in[2];
    const float* W1 = (const float*)d_in[3],  *as1 = (const float*)d_in[4],
               * ad1 = (const float*)d_in[5], *b1  = (const float*)d_in[6];
    const float* W2 = (const float*)d_in[7],  *as2 = (const float*)d_in[8],
               * ad2 = (const float*)d_in[9], *b2  = (const float*)d_in[10];
    const float* W3 = (const float*)d_in[11], *as3 = (const float*)d_in[12],
               * ad3 = (const float*)d_in[13],*b3  = (const float*)d_in[14];
    const float* Wc = (const float*)d_in[15], *bc  = (const float*)d_in[16];
    float* out = (float*)d_out;

    int n    = in_sizes[0] / INC;
    int E    = in_sizes[1] / 2;
    int Etot = E + n;

    int gemm_rows = (n + 127) / 128;
    int eb    = (Etot + 255) / 256;
    int nb    = (n + 255) / 256;
    int sb    = (n + 1023) / 1024;
    int aggb2 = (int)(((long long)n * 2 * 32 + 255) / 256);
    int aggb1 = (int)(((long long)n * 32 + 255) / 256);

    wa_prep<<<32, 256>>>(W1, as1, ad1, W2, as2, ad2, W3, as3, ad3);         // 0
    zero_all<<<nb, 256>>>(n);                                               // 1
    hist_k<<<eb, 256>>>(ei, E, n);                                          // 2
    tgemm_k<INC, F1, false, 128, 2, 4><<<dim3(F1 / 128, gemm_rows), 256>>>(x, W1, n); // 3
    scan_blk<<<sb, 1024>>>(n);                                              // 4
    scan_top<<<1, 64>>>(sb);                                                // 5
    scan_add<<<sb, 1024>>>(n);                                              // 6
    scatter_k<<<eb, 256>>>(ei, E, n);                                       // 7
    dhist_k<<<nb, 256>>>(n);                                                // 8
    dscan_k<<<1, 1024>>>();                                                 // 9
    dscatter_k<<<nb, 256>>>(n);                                             // 10
    gemv_attn<<<(n + 7) / 8, 256>>>(x, n);                                  // 11

    // ---- Layer 1 agg (H=4, 2 warps/node, deg-sorted); writes layer-2 coeffs ----
    agg_k<NHEADS, 2, NHEADS, true, true, false><<<aggb2, 256>>>(b1, nullptr, n);

    // ---- Layer 2 (H=4, in=256, out=256) ----
    tgemm_k<F1, F1, true, 128, 2, 4><<<dim3(F1 / 128, gemm_rows), 256>>>(nullptr, W2, n);
    agg_k<NHEADS, 2, 1, true, false, false><<<aggb2, 256>>>(b2, nullptr, n);

    // ---- Layer 3 (H=1, in=256, out=64) ----
    tgemm_k<F1, HIDC, true, 64, 4, 2><<<dim3(1, gemm_rows), 256>>>(nullptr, W3, n);
    agg_k<1, 1, 0, false, true, true><<<aggb1, 256>>>(b3, bat, n);

    // ---- head ----
    head_k<<<(GG * OUTC + 255) / 256, 256>>>(Wc, bc, out);
}

// round 14
// speedup vs baseline: 1.7295x; 1.1280x over previous
#include <cuda_runtime.h>
#include <cstdint>

// ---------------- Problem constants ----------------
#define NMAX    50000
#define EMAX    800000
#define ETOTMAX (EMAX + NMAX)
#define GG      64
#define INC     128
#define HIDC    64
#define NHEADS  4
#define F1      (NHEADS * HIDC)   // 256
#define OUTC    10
#define NEG     0.2f
#define EPSV    1e-16f
#define FLTMAX  3.402823466e38f
#define DBINS   1024

// ---------------- Device scratch ----------------
__device__ float d_h[(size_t)NMAX * F1];
__device__ float d_feat[(size_t)NMAX * F1];
__device__ __align__(16) float d_asrcA[NMAX * NHEADS];
__device__ __align__(16) float d_adstA[NMAX * NHEADS];
__device__ __align__(16) float d_asrcB[NMAX * NHEADS];
__device__ __align__(16) float d_adstB[NMAX * NHEADS];
__device__ int   d_deg[NMAX];
__device__ int   d_off[NMAX];
__device__ int   d_cur[NMAX];
__device__ int   d_bsum[64];
__device__ int   d_csr_src[ETOTMAX];
__device__ int   d_dhist[DBINS];
__device__ int   d_dcur[DBINS];
__device__ int   d_perm[NMAX];
__device__ float d_pool[GG * HIDC];
__device__ float d_cnt[GG];
// precomputed W @ a vectors, PERMUTED: p(ch) = (ch>>7)*128 + (ch&3)*32 + ((ch>>2)&31)
__device__ float4 d_wa1s[INC], d_wa1d[INC];
__device__ float4 d_wa2s[F1],  d_wa2d[F1];
__device__ float  d_wa3s[F1],  d_wa3d[F1];

__device__ __forceinline__ int waperm(int ch) {
    return (ch >> 7) * 128 + (ch & 3) * 32 + ((ch >> 2) & 31);
}

// ================= wa precompute: warp per k, coalesced =================
__global__ void wa_prep(const float* __restrict__ W1, const float* __restrict__ as1, const float* __restrict__ ad1,
                        const float* __restrict__ W2, const float* __restrict__ as2, const float* __restrict__ ad2,
                        const float* __restrict__ W3, const float* __restrict__ as3, const float* __restrict__ ad3) {
    int gw = (blockIdx.x * blockDim.x + threadIdx.x) >> 5;
    int lane = threadIdx.x & 31;
    if (gw >= F1) return;
    int k = gw;

    if (k < INC) {
        float4 s, d;
        float* sp = (float*)&s; float* dp = (float*)&d;
#pragma unroll
        for (int h = 0; h < NHEADS; h++) {
            float w0 = W1[(size_t)k * F1 + h * HIDC + lane];
            float w1 = W1[(size_t)k * F1 + h * HIDC + lane + 32];
            float ss = w0 * as1[h * HIDC + lane] + w1 * as1[h * HIDC + lane + 32];
            float dd = w0 * ad1[h * HIDC + lane] + w1 * ad1[h * HIDC + lane + 32];
#pragma unroll
            for (int o = 16; o; o >>= 1) {
                ss += __shfl_xor_sync(0xffffffffu, ss, o);
                dd += __shfl_xor_sync(0xffffffffu, dd, o);
            }
            sp[h] = ss; dp[h] = dd;
        }
        if (!lane) {
            int p = (k & 3) * 32 + (k >> 2);
            d_wa1s[p] = s; d_wa1d[p] = d;
        }
    }
    {
        float4 s, d;
        float* sp = (float*)&s; float* dp = (float*)&d;
#pragma unroll
        for (int h = 0; h < NHEADS; h++) {
            float w0 = W2[(size_t)k * F1 + h * HIDC + lane];
            float w1 = W2[(size_t)k * F1 + h * HIDC + lane + 32];
            float ss = w0 * as2[h * HIDC + lane] + w1 * as2[h * HIDC + lane + 32];
            float dd = w0 * ad2[h * HIDC + lane] + w1 * ad2[h * HIDC + lane + 32];
#pragma unroll
            for (int o = 16; o; o >>= 1) {
                ss += __shfl_xor_sync(0xffffffffu, ss, o);
                dd += __shfl_xor_sync(0xffffffffu, dd, o);
            }
            sp[h] = ss; dp[h] = dd;
        }
        float w0 = W3[(size_t)k * HIDC + lane];
        float w1 = W3[(size_t)k * HIDC + lane + 32];
        float s3 = w0 * as3[lane] + w1 * as3[lane + 32];
        float d3 = w0 * ad3[lane] + w1 * ad3[lane + 32];
#pragma unroll
        for (int o = 16; o; o >>= 1) {
            s3 += __shfl_xor_sync(0xffffffffu, s3, o);
            d3 += __shfl_xor_sync(0xffffffffu, d3, o);
        }
        if (!lane) {
            int p = waperm(k);
            d_wa2s[p] = s; d_wa2d[p] = d;
            d_wa3s[p] = s3; d_wa3d[p] = d3;
        }
    }
}

// ================= zero =================
__global__ void zero_all(int n) {
    int i = blockIdx.x * blockDim.x + threadIdx.x;
    if (i < n) { d_deg[i] = 0; d_cur[i] = 0; }
    if (i < GG * HIDC) d_pool[i] = 0.f;
    if (i < GG) d_cnt[i] = 0.f;
    if (i < DBINS) { d_dhist[i] = 0; d_dcur[i] = 0; }
}

// ================= CSR construction =================
__global__ void hist_k(const int* __restrict__ ei, int E, int n) {
    int e = blockIdx.x * blockDim.x + threadIdx.x;
    int Etot = E + n;
    if (e >= Etot) return;
    int d = (e < E) ? __ldg(&ei[E + e]) : (e - E);
    atomicAdd(&d_deg[d], 1);
}

__global__ void scan_blk(int n) {
    int i = blockIdx.x * 1024 + threadIdx.x;
    int lane = threadIdx.x & 31, wid = threadIdx.x >> 5;
    int v = (i < n) ? d_deg[i] : 0;
    int x = v;
#pragma unroll
    for (int o = 1; o < 32; o <<= 1) {
        int t = __shfl_up_sync(0xffffffffu, x, o);
        if (lane >= o) x += t;
    }
    __shared__ int ws[32];
    if (lane == 31) ws[wid] = x;
    __syncthreads();
    if (wid == 0) {
        int y = ws[lane];
#pragma unroll
        for (int o = 1; o < 32; o <<= 1) {
            int t = __shfl_up_sync(0xffffffffu, y, o);
            if (lane >= o) y += t;
        }
        ws[lane] = y;
    }
    __syncthreads();
    int incl = x + (wid ? ws[wid - 1] : 0);
    if (i < n) d_off[i] = incl - v;
    if (threadIdx.x == 1023) d_bsum[blockIdx.x] = incl;
}

__global__ void scan_top(int nb) {
    int tid = threadIdx.x;
    int lane = tid & 31, wid = tid >> 5;
    int v = (tid < nb) ? d_bsum[tid] : 0;
    int x = v;
#pragma unroll
    for (int o = 1; o < 32; o <<= 1) {
        int t = __shfl_up_sync(0xffffffffu, x, o);
        if (lane >= o) x += t;
    }
    __shared__ int w0;
    if (wid == 0 && lane == 31) w0 = x;
    __syncthreads();
    int incl = x + (wid ? w0 : 0);
    if (tid < nb) d_bsum[tid] = incl - v;
}

__global__ void scan_add(int n) {
    int i = blockIdx.x * 1024 + threadIdx.x;
    if (i < n) d_off[i] += d_bsum[blockIdx.x];
}

__global__ void scatter_k(const int* __restrict__ ei, int E, int n) {
    int e = blockIdx.x * blockDim.x + threadIdx.x;
    int Etot = E + n;
    if (e >= Etot) return;
    int s, d;
    if (e < E) { s = __ldg(&ei[e]); d = __ldg(&ei[E + e]); } else { s = d = e - E; }
    int pos = d_off[d] + atomicAdd(&d_cur[d], 1);
    d_csr_src[pos] = s;
}

// ================= degree-sorted node permutation =================
__global__ void dhist_k(int n) {
    int i = blockIdx.x * blockDim.x + threadIdx.x;
    if (i >= n) return;
    int b = min(d_deg[i], DBINS - 1);
    atomicAdd(&d_dhist[b], 1);
}

__global__ void dscan_k() {
    int tid = threadIdx.x;     // 1024 threads
    int lane = tid & 31, wid = tid >> 5;
    int v = d_dhist[tid];
    int x = v;
#pragma unroll
    for (int o = 1; o < 32; o <<= 1) {
        int t = __shfl_up_sync(0xffffffffu, x, o);
        if (lane >= o) x += t;
    }
    __shared__ int ws[32];
    if (lane == 31) ws[wid] = x;
    __syncthreads();
    if (wid == 0) {
        int y = ws[lane];
#pragma unroll
        for (int o = 1; o < 32; o <<= 1) {
            int t = __shfl_up_sync(0xffffffffu, y, o);
            if (lane >= o) y += t;
        }
        ws[lane] = y;
    }
    __syncthreads();
    int incl = x + (wid ? ws[wid - 1] : 0);
    d_dhist[tid] = incl - v;
}

__global__ void dscatter_k(int n) {
    int i = blockIdx.x * blockDim.x + threadIdx.x;
    if (i >= n) return;
    int b = min(d_deg[i], DBINS - 1);
    int pos = d_dhist[b] + atomicAdd(&d_dcur[b], 1);
    d_perm[pos] = i;
}

// ================= layer-1 attention coefficients =================
__global__ void gemv_attn(const float* __restrict__ x, int n) {
    __shared__ float4 ws[INC], wd[INC];
    for (int i = threadIdx.x; i < INC; i += 256) { ws[i] = d_wa1s[i]; wd[i] = d_wa1d[i]; }
    __syncthreads();
    int warp = (blockIdx.x * blockDim.x + threadIdx.x) >> 5;
    int lane = threadIdx.x & 31;
    if (warp >= n) return;
    float4 xv = *reinterpret_cast<const float4*>(&x[(size_t)warp * INC + lane * 4]);
    float xr[4] = {xv.x, xv.y, xv.z, xv.w};
    float ps[NHEADS] = {}, pd[NHEADS] = {};
#pragma unroll
    for (int j = 0; j < 4; j++) {
        float4 a = ws[j * 32 + lane];
        float4 b = wd[j * 32 + lane];
        ps[0] = fmaf(xr[j], a.x, ps[0]); ps[1] = fmaf(xr[j], a.y, ps[1]);
        ps[2] = fmaf(xr[j], a.z, ps[2]); ps[3] = fmaf(xr[j], a.w, ps[3]);
        pd[0] = fmaf(xr[j], b.x, pd[0]); pd[1] = fmaf(xr[j], b.y, pd[1]);
        pd[2] = fmaf(xr[j], b.z, pd[2]); pd[3] = fmaf(xr[j], b.w, pd[3]);
    }
#pragma unroll
    for (int h = 0; h < NHEADS; h++) {
#pragma unroll
        for (int o = 16; o; o >>= 1) {
            ps[h] += __shfl_xor_sync(0xffffffffu, ps[h], o);
            pd[h] += __shfl_xor_sync(0xffffffffu, pd[h], o);
        }
    }
    if (!lane) {
#pragma unroll
        for (int h = 0; h < NHEADS; h++) {
            d_asrcA[warp * NHEADS + h] = ps[h];
            d_adstA[warp * NHEADS + h] = pd[h];
        }
    }
}

// ================= TF32 GEMM (cp.async double buffer, cvt at frag load) ======
__device__ __forceinline__ uint32_t cvt_tf32(float x) {
    uint32_t u;
    asm("cvt.rna.tf32.f32 %0, %1;" : "=r"(u) : "f"(x));
    return u;
}

__device__ __forceinline__ void mma_tf32(float c[4], uint32_t a0, uint32_t a1,
                                         uint32_t a2, uint32_t a3,
                                         uint32_t b0, uint32_t b1) {
    asm volatile(
        "mma.sync.aligned.m16n8k8.row.col.f32.tf32.tf32.f32 "
        "{%0,%1,%2,%3}, {%4,%5,%6,%7}, {%8,%9}, {%0,%1,%2,%3};"
        : "+f"(c[0]), "+f"(c[1]), "+f"(c[2]), "+f"(c[3])
        : "r"(a0), "r"(a1), "r"(a2), "r"(a3), "r"(b0), "r"(b1));
}

__device__ __forceinline__ void cp16p(float* smem_dst, const float* gsrc, bool pred) {
    unsigned sa = (unsigned)__cvta_generic_to_shared(smem_dst);
    int sz = pred ? 16 : 0;
    asm volatile("cp.async.ca.shared.global [%0], [%1], 16, %2;\n" :: "r"(sa), "l"(gsrc), "r"(sz));
}
__device__ __forceinline__ void cp_commit() { asm volatile("cp.async.commit_group;"); }
template <int N>
__device__ __forceinline__ void cp_wait() { asm volatile("cp.async.wait_group %0;" :: "n"(N)); }

template <int K, int NOUT, bool AG, int BN, int WM, int WN>
__launch_bounds__(256, 2)
__global__ void tgemm_k(const float* __restrict__ Ain, const float* __restrict__ B, int M) {
    constexpr int BM = 128, BK = 16;
    constexpr int MT = BM / (WM * 16);
    constexpr int NT = BN / (WN * 8);
    __shared__ float As[2][BM][BK + 4];
    __shared__ float Bs[2][BK][BN + 8];
    const float* A = AG ? (const float*)d_feat : Ain;

    int tid = threadIdx.x;
    int wid = tid >> 5, lane = tid & 31;
    int wm = wid % WM, wn = wid / WM;
    int row0 = blockIdx.y * BM;
    int col0 = blockIdx.x * BN;
    int lr = lane >> 2, lc = lane & 3;

    float c[MT][NT][4];
#pragma unroll
    for (int i = 0; i < MT; i++)
#pragma unroll
        for (int j = 0; j < NT; j++)
#pragma unroll
            for (int q = 0; q < 4; q++) c[i][j][q] = 0.f;

    constexpr int B4 = BN / 4;
    constexpr int BLD = (BK * B4) / 256;
    const int nk = K / BK;

    {
#pragma unroll
        for (int j = 0; j < 2; j++) {
            int idx = tid + j * 256;
            int r = idx >> 2, q = idx & 3;
            cp16p(&As[0][r][q * 4], &A[(size_t)(row0 + r) * K + q * 4], (row0 + r) < M);
        }
#pragma unroll
        for (int j = 0; j < BLD; j++) {
            int idx = tid + j * 256;
            int r = idx / B4, q = idx % B4;
            cp16p(&Bs[0][r][q * 4], &B[(size_t)r * NOUT + col0 + q * 4], true);
        }
        cp_commit();
    }

    for (int t = 0; t < nk; t++) {
        int cur = t & 1;
        if (t + 1 < nk) {
            int k0 = (t + 1) * BK;
#pragma unroll
            for (int j = 0; j < 2; j++) {
                int idx = tid + j * 256;
                int r = idx >> 2, q = idx & 3;
                cp16p(&As[1 - cur][r][q * 4], &A[(size_t)(row0 + r) * K + k0 + q * 4], (row0 + r) < M);
            }
#pragma unroll
            for (int j = 0; j < BLD; j++) {
                int idx = tid + j * 256;
                int r = idx / B4, q = idx % B4;
                cp16p(&Bs[1 - cur][r][q * 4], &B[(size_t)(k0 + r) * NOUT + col0 + q * 4], true);
            }
            cp_commit();
            cp_wait<1>();
        } else {
            cp_wait<0>();
        }
        __syncthreads();

#pragma unroll
        for (int kk = 0; kk < BK; kk += 8) {
            uint32_t af[MT][4], bf[NT][2];
#pragma unroll
            for (int mt = 0; mt < MT; mt++) {
                int bm = wm * MT * 16 + mt * 16;
                af[mt][0] = cvt_tf32(As[cur][bm + lr][kk + lc]);
                af[mt][1] = cvt_tf32(As[cur][bm + lr + 8][kk + lc]);
                af[mt][2] = cvt_tf32(As[cur][bm + lr][kk + lc + 4]);
                af[mt][3] = cvt_tf32(As[cur][bm + lr + 8][kk + lc + 4]);
            }
#pragma unroll
            for (int nt = 0; nt < NT; nt++) {
                int bn = wn * NT * 8 + nt * 8;
                bf[nt][0] = cvt_tf32(Bs[cur][kk + lc][bn + lr]);
                bf[nt][1] = cvt_tf32(Bs[cur][kk + lc + 4][bn + lr]);
            }
#pragma unroll
            for (int mt = 0; mt < MT; mt++)
#pragma unroll
                for (int nt = 0; nt < NT; nt++)
                    mma_tf32(c[mt][nt], af[mt][0], af[mt][1], af[mt][2], af[mt][3],
                             bf[nt][0], bf[nt][1]);
        }
        __syncthreads();
    }

#pragma unroll
    for (int mt = 0; mt < MT; mt++) {
        int r0 = row0 + wm * MT * 16 + mt * 16 + lr;
#pragma unroll
        for (int nt = 0; nt < NT; nt++) {
            int cc = col0 + wn * NT * 8 + nt * 8 + 2 * lc;
            if (r0 < M)
                *reinterpret_cast<float2*>(&d_h[(size_t)r0 * NOUT + cc]) =
                    make_float2(c[mt][nt][0], c[mt][nt][1]);
            if (r0 + 8 < M)
                *reinterpret_cast<float2*>(&d_h[(size_t)(r0 + 8) * NOUT + cc]) =
                    make_float2(c[mt][nt][2], c[mt][nt][3]);
        }
    }
}

// ======== fused aggregation: single-pass unnormalized softmax, WPN warps/node ========
// out = sum_j exp(v_j) h_j / (sum_j exp(v_j) + eps); logits are small -> no max needed.
template <int H, int WPN, int HN, bool DOELU, bool SRCA, bool POOL>
__launch_bounds__(256)
__global__ void agg_k(const float* __restrict__ bias, const int* __restrict__ batch, int n) {
    constexpr int C = 64, F = H * C, CH = F / WPN, RF = CH / 32;
    __shared__ float4 wsn4[HN == 4 ? F : 1], wdn4[HN == 4 ? F : 1];
    __shared__ float  wsn1[HN == 1 ? F : 1], wdn1[HN == 1 ? F : 1];
    __shared__ float  parts[8][8];
    if (HN == 4) {
        for (int i = threadIdx.x; i < F; i += 256) { wsn4[i] = d_wa2s[i]; wdn4[i] = d_wa2d[i]; }
        __syncthreads();
    } else if (HN == 1) {
        for (int i = threadIdx.x; i < F; i += 256) { wsn1[i] = d_wa3s[i]; wdn1[i] = d_wa3d[i]; }
        __syncthreads();
    }
    const float* asrc  = SRCA ? d_asrcA : d_asrcB;
    const float* adstp = SRCA ? d_adstA : d_adstB;
    float* nsrc = SRCA ? d_asrcB : d_asrcA;
    float* ndst = SRCA ? d_adstB : d_adstA;

    int gw   = (blockIdx.x * blockDim.x + threadIdx.x) >> 5;
    int wblk = threadIdx.x >> 5;
    int lane = threadIdx.x & 31;
    int slot = gw / WPN;
    int sub  = gw % WPN;
    bool valid = slot < n;
    int node = valid ? d_perm[slot] : 0;

    float acc[RF];
#pragma unroll
    for (int k = 0; k < RF; k++) acc[k] = 0.f;

    if (valid) {
        int off = d_off[node], deg = d_deg[node];

        // this lane's head within the node
        const int hl = (H == 4) ? (lane >> 4) : 0;
        const int asoff = (H == 4) ? (sub * 2 + hl) : 0;
        const float adh = adstp[node * H + asoff];
        const size_t cbase = sub * CH + lane * RF;

        float S = 0.f;
#pragma unroll 2
        for (int j = 0; j < deg; j++) {
            int s = d_csr_src[off + j];
            float v = asrc[s * H + asoff] + adh;
            v = v > 0.f ? v : NEG * v;
            float w = __expf(v);
            S += w;
            const float* hs = &d_h[(size_t)s * F + cbase];
            if (RF == 4) {
                float4 v0 = *reinterpret_cast<const float4*>(hs);
                acc[0] = fmaf(w, v0.x, acc[0]); acc[1] = fmaf(w, v0.y, acc[1]);
                acc[2] = fmaf(w, v0.z, acc[2]); acc[3] = fmaf(w, v0.w, acc[3]);
            } else {
                float2 v0 = *reinterpret_cast<const float2*>(hs);
                acc[0] = fmaf(w, v0.x, acc[0]); acc[1] = fmaf(w, v0.y, acc[1]);
            }
        }
        float inv = 1.f / (S + EPSV);

        // normalize + bias + optional ELU
#pragma unroll
        for (int k = 0; k < RF; k++) {
            float v = acc[k] * inv + bias[sub * CH + lane * RF + k];
            if (DOELU) v = v > 0.f ? v : (__expf(v) - 1.f);
            acc[k] = v;
        }

        if (POOL) {
            int g = __ldg(&batch[node]);
            atomicAdd(&d_pool[g * HIDC + lane * RF + 0], acc[0]);
            atomicAdd(&d_pool[g * HIDC + lane * RF + 1], acc[1]);
            if (!lane) atomicAdd(&d_cnt[g], 1.0f);
        } else {
            float* outp = &d_feat[(size_t)node * F + sub * CH + lane * RF];
            if (RF == 4)
                *reinterpret_cast<float4*>(outp) = make_float4(acc[0], acc[1], acc[2], acc[3]);
            else
                *reinterpret_cast<float2*>(outp) = make_float2(acc[0], acc[1]);
        }

        // partial next-layer coefficients
        if (HN == 4) {
            float ps[4] = {}, pd[4] = {};
#pragma unroll
            for (int k = 0; k < RF; k++) {
                float4 a = wsn4[sub * CH + k * 32 + lane];
                float4 b = wdn4[sub * CH + k * 32 + lane];
                ps[0] = fmaf(acc[k], a.x, ps[0]); ps[1] = fmaf(acc[k], a.y, ps[1]);
                ps[2] = fmaf(acc[k], a.z, ps[2]); ps[3] = fmaf(acc[k], a.w, ps[3]);
                pd[0] = fmaf(acc[k], b.x, pd[0]); pd[1] = fmaf(acc[k], b.y, pd[1]);
                pd[2] = fmaf(acc[k], b.z, pd[2]); pd[3] = fmaf(acc[k], b.w, pd[3]);
            }
#pragma unroll
            for (int h = 0; h < 4; h++) {
#pragma unroll
                for (int o = 16; o; o >>= 1) {
                    ps[h] += __shfl_xor_sync(0xffffffffu, ps[h], o);
                    pd[h] += __shfl_xor_sync(0xffffffffu, pd[h], o);
                }
            }
            if (!lane) {
#pragma unroll
                for (int h = 0; h < 4; h++) {
                    parts[wblk][h] = ps[h];
                    parts[wblk][4 + h] = pd[h];
                }
            }
        } else if (HN == 1) {
            float ps = 0.f, pd = 0.f;
#pragma unroll
            for (int k = 0; k < RF; k++) {
                ps = fmaf(acc[k], wsn1[sub * CH + k * 32 + lane], ps);
                pd = fmaf(acc[k], wdn1[sub * CH + k * 32 + lane], pd);
            }
#pragma unroll
            for (int o = 16; o; o >>= 1) {
                ps += __shfl_xor_sync(0xffffffffu, ps, o);
                pd += __shfl_xor_sync(0xffffffffu, pd, o);
            }
            if (!lane) { parts[wblk][0] = ps; parts[wblk][1] = pd; }
        }
    }

    if (HN > 0) {
        __syncthreads();
        if (valid && sub == 0 && !lane) {
            if (HN == 4) {
#pragma unroll
                for (int h = 0; h < 4; h++) {
                    nsrc[node * 4 + h] = parts[wblk][h]     + parts[wblk + 1][h];
                    ndst[node * 4 + h] = parts[wblk][4 + h] + parts[wblk + 1][4 + h];
                }
            } else {
                nsrc[node] = parts[wblk][0] + parts[wblk + 1][0];
                ndst[node] = parts[wblk][1] + parts[wblk + 1][1];
            }
        }
    }
}

// ---------------- head ----------------
__global__ void head_k(const float* __restrict__ Wc, const float* __restrict__ bc,
                       float* __restrict__ out) {
    int t = blockIdx.x * blockDim.x + threadIdx.x;
    if (t >= GG * OUTC) return;
    int g = t / OUTC, o = t % OUTC;
    float inv = 1.f / fmaxf(d_cnt[g], 1.f);
    float s = 0.f;
#pragma unroll
    for (int c = 0; c < HIDC; c++) s += d_pool[g * HIDC + c] * Wc[c * OUTC + o];
    out[t] = s * inv + bc[o];
}

// ---------------- host orchestration ----------------
extern "C" void kernel_launch(void* const* d_in, const int* in_sizes, int n_in,
                              void* d_out, int out_size) {
    const float* x   = (const float*)d_in[0];
    const int*   ei  = (const int*)d_in[1];
    const int*   bat = (const int*)d_in[2];
    const float* W1 = (const float*)d_in[3],  *as1 = (const float*)d_in[4],
               * ad1 = (const float*)d_in[5], *b1  = (const float*)d_in[6];
    const float* W2 = (const float*)d_in[7],  *as2 = (const float*)d_in[8],
               * ad2 = (const float*)d_in[9], *b2  = (const float*)d_in[10];
    const float* W3 = (const float*)d_in[11], *as3 = (const float*)d_in[12],
               * ad3 = (const float*)d_in[13],*b3  = (const float*)d_in[14];
    const float* Wc = (const float*)d_in[15], *bc  = (const float*)d_in[16];
    float* out = (float*)d_out;

    int n    = in_sizes[0] / INC;
    int E    = in_sizes[1] / 2;
    int Etot = E + n;

    int gemm_rows = (n + 127) / 128;
    int eb    = (Etot + 255) / 256;
    int nb    = (n + 255) / 256;
    int sb    = (n + 1023) / 1024;
    int aggb2 = (int)(((long long)n * 2 * 32 + 255) / 256);
    int aggb1 = (int)(((long long)n * 32 + 255) / 256);

    wa_prep<<<32, 256>>>(W1, as1, ad1, W2, as2, ad2, W3, as3, ad3);         // 0
    zero_all<<<nb, 256>>>(n);                                               // 1
    hist_k<<<eb, 256>>>(ei, E, n);                                          // 2
    tgemm_k<INC, F1, false, 128, 2, 4><<<dim3(F1 / 128, gemm_rows), 256>>>(x, W1, n); // 3
    scan_blk<<<sb, 1024>>>(n);                                              // 4
    scan_top<<<1, 64>>>(sb);                                                // 5
    scan_add<<<sb, 1024>>>(n);                                              // 6
    scatter_k<<<eb, 256>>>(ei, E, n);                                       // 7
    dhist_k<<<nb, 256>>>(n);                                                // 8
    dscan_k<<<1, 1024>>>();                                                 // 9
    dscatter_k<<<nb, 256>>>(n);                                             // 10
    gemv_attn<<<(n + 7) / 8, 256>>>(x, n);                                  // 11

    // ---- Layer 1 agg (H=4, 2 warps/node, deg-sorted, single-pass); layer-2 coeffs ----
    agg_k<NHEADS, 2, NHEADS, true, true, false><<<aggb2, 256>>>(b1, nullptr, n);

    // ---- Layer 2 (H=4, in=256, out=256) ----
    tgemm_k<F1, F1, true, 128, 2, 4><<<dim3(F1 / 128, gemm_rows), 256>>>(nullptr, W2, n);
    agg_k<NHEADS, 2, 1, true, false, false><<<aggb2, 256>>>(b2, nullptr, n);

    // ---- Layer 3 (H=1, in=256, out=64) ----
    tgemm_k<F1, HIDC, true, 64, 4, 2><<<dim3(1, gemm_rows), 256>>>(nullptr, W3, n);
    agg_k<1, 1, 0, false, true, true><<<aggb1, 256>>>(b3, bat, n);

    // ---- head ----
    head_k<<<(GG * OUTC + 255) / 256, 256>>>(Wc, bc, out);
}

// round 15
// speedup vs baseline: 1.7492x; 1.0114x over previous
#include <cuda_runtime.h>
#include <cstdint>

// ---------------- Problem constants ----------------
#define NMAX    50000
#define EMAX    800000
#define ETOTMAX (EMAX + NMAX)
#define GG      64
#define INC     128
#define HIDC    64
#define NHEADS  4
#define F1      (NHEADS * HIDC)   // 256
#define OUTC    10
#define NEG     0.2f
#define EPSV    1e-16f
#define FLTMAX  3.402823466e38f
#define DBINS   1024

// ---------------- Device scratch ----------------
__device__ float d_h[(size_t)NMAX * F1];
__device__ float d_feat[(size_t)NMAX * F1];
__device__ __align__(16) float d_asrcA[NMAX * NHEADS];
__device__ __align__(16) float d_adstA[NMAX * NHEADS];
__device__ __align__(16) float d_asrcB[NMAX * NHEADS];
__device__ __align__(16) float d_adstB[NMAX * NHEADS];
__device__ int   d_deg[NMAX];
__device__ int   d_off[NMAX];
__device__ int   d_cur[NMAX];
__device__ int   d_bsum[64];
__device__ int   d_csr_src[ETOTMAX];
__device__ int   d_dhist[DBINS];
__device__ int   d_dcur[DBINS];
__device__ int   d_perm[NMAX];
__device__ float d_pool[GG * HIDC];
__device__ float d_cnt[GG];
// precomputed W @ a vectors, PERMUTED: p(ch) = (ch>>7)*128 + (ch&3)*32 + ((ch>>2)&31)
__device__ float4 d_wa1s[INC], d_wa1d[INC];
__device__ float4 d_wa2s[F1],  d_wa2d[F1];
__device__ float  d_wa3s[F1],  d_wa3d[F1];

__device__ __forceinline__ int waperm(int ch) {
    return (ch >> 7) * 128 + (ch & 3) * 32 + ((ch >> 2) & 31);
}

__device__ __forceinline__ uint32_t cvt_tf32(float x) {
    uint32_t u;
    asm("cvt.rna.tf32.f32 %0, %1;" : "=r"(u) : "f"(x));
    return u;
}

// ================= wa precompute: warp per k, coalesced =================
__global__ void wa_prep(const float* __restrict__ W1, const float* __restrict__ as1, const float* __restrict__ ad1,
                        const float* __restrict__ W2, const float* __restrict__ as2, const float* __restrict__ ad2,
                        const float* __restrict__ W3, const float* __restrict__ as3, const float* __restrict__ ad3) {
    int gw = (blockIdx.x * blockDim.x + threadIdx.x) >> 5;
    int lane = threadIdx.x & 31;
    if (gw >= F1) return;
    int k = gw;

    if (k < INC) {
        float4 s, d;
        float* sp = (float*)&s; float* dp = (float*)&d;
#pragma unroll
        for (int h = 0; h < NHEADS; h++) {
            float w0 = W1[(size_t)k * F1 + h * HIDC + lane];
            float w1 = W1[(size_t)k * F1 + h * HIDC + lane + 32];
            float ss = w0 * as1[h * HIDC + lane] + w1 * as1[h * HIDC + lane + 32];
            float dd = w0 * ad1[h * HIDC + lane] + w1 * ad1[h * HIDC + lane + 32];
#pragma unroll
            for (int o = 16; o; o >>= 1) {
                ss += __shfl_xor_sync(0xffffffffu, ss, o);
                dd += __shfl_xor_sync(0xffffffffu, dd, o);
            }
            sp[h] = ss; dp[h] = dd;
        }
        if (!lane) {
            int p = (k & 3) * 32 + (k >> 2);
            d_wa1s[p] = s; d_wa1d[p] = d;
        }
    }
    {
        float4 s, d;
        float* sp = (float*)&s; float* dp = (float*)&d;
#pragma unroll
        for (int h = 0; h < NHEADS; h++) {
            float w0 = W2[(size_t)k * F1 + h * HIDC + lane];
            float w1 = W2[(size_t)k * F1 + h * HIDC + lane + 32];
            float ss = w0 * as2[h * HIDC + lane] + w1 * as2[h * HIDC + lane + 32];
            float dd = w0 * ad2[h * HIDC + lane] + w1 * ad2[h * HIDC + lane + 32];
#pragma unroll
            for (int o = 16; o; o >>= 1) {
                ss += __shfl_xor_sync(0xffffffffu, ss, o);
                dd += __shfl_xor_sync(0xffffffffu, dd, o);
            }
            sp[h] = ss; dp[h] = dd;
        }
        float w0 = W3[(size_t)k * HIDC + lane];
        float w1 = W3[(size_t)k * HIDC + lane + 32];
        float s3 = w0 * as3[lane] + w1 * as3[lane + 32];
        float d3 = w0 * ad3[lane] + w1 * ad3[lane + 32];
#pragma unroll
        for (int o = 16; o; o >>= 1) {
            s3 += __shfl_xor_sync(0xffffffffu, s3, o);
            d3 += __shfl_xor_sync(0xffffffffu, d3, o);
        }
        if (!lane) {
            int p = waperm(k);
            d_wa2s[p] = s; d_wa2d[p] = d;
            d_wa3s[p] = s3; d_wa3d[p] = d3;
        }
    }
}

// ================= zero =================
__global__ void zero_all(int n) {
    int i = blockIdx.x * blockDim.x + threadIdx.x;
    if (i < n) { d_deg[i] = 0; d_cur[i] = 0; }
    if (i < GG * HIDC) d_pool[i] = 0.f;
    if (i < GG) d_cnt[i] = 0.f;
    if (i < DBINS) { d_dhist[i] = 0; d_dcur[i] = 0; }
}

// ================= CSR construction =================
__global__ void hist_k(const int* __restrict__ ei, int E, int n) {
    int e = blockIdx.x * blockDim.x + threadIdx.x;
    int Etot = E + n;
    if (e >= Etot) return;
    int d = (e < E) ? __ldg(&ei[E + e]) : (e - E);
    atomicAdd(&d_deg[d], 1);
}

// block scan of deg -> off; also accumulates the degree histogram
__global__ void scan_blk(int n) {
    int i = blockIdx.x * 1024 + threadIdx.x;
    int lane = threadIdx.x & 31, wid = threadIdx.x >> 5;
    int v = (i < n) ? d_deg[i] : 0;
    if (i < n) atomicAdd(&d_dhist[min(v, DBINS - 1)], 1);
    int x = v;
#pragma unroll
    for (int o = 1; o < 32; o <<= 1) {
        int t = __shfl_up_sync(0xffffffffu, x, o);
        if (lane >= o) x += t;
    }
    __shared__ int ws[32];
    if (lane == 31) ws[wid] = x;
    __syncthreads();
    if (wid == 0) {
        int y = ws[lane];
#pragma unroll
        for (int o = 1; o < 32; o <<= 1) {
            int t = __shfl_up_sync(0xffffffffu, y, o);
            if (lane >= o) y += t;
        }
        ws[lane] = y;
    }
    __syncthreads();
    int incl = x + (wid ? ws[wid - 1] : 0);
    if (i < n) d_off[i] = incl - v;
    if (threadIdx.x == 1023) d_bsum[blockIdx.x] = incl;
}

// top scan of block sums (first 64 threads) + exclusive scan of the 1024-bin dhist
__global__ void scan_top(int nb) {
    int tid = threadIdx.x;     // 1024 threads
    int lane = tid & 31, wid = tid >> 5;

    // part A: scan of d_bsum (threads 0..63)
    if (tid < 64) {
        int v = (tid < nb) ? d_bsum[tid] : 0;
        int x = v;
#pragma unroll
        for (int o = 1; o < 32; o <<= 1) {
            int t = __shfl_up_sync(0xffffffffu, x, o);
            if (lane >= o) x += t;
        }
        __shared__ int w0;
        if (wid == 0 && lane == 31) w0 = x;
        __syncwarp();
        // threads 32..63 need w0 from warp 0; use a block-level path:
        // store warp sums in shared and recombine below.
        __shared__ int wsum[2];
        if (lane == 31) wsum[wid] = x;
        __syncthreads();
        int incl = x + (wid ? wsum[0] : 0);
        if (tid < nb) d_bsum[tid] = incl - v;
        (void)w0;
    } else {
        __syncthreads();   // match part-A barrier
    }
    __syncthreads();

    // part B: exclusive scan of d_dhist (all 1024 threads)
    int v = d_dhist[tid];
    int x = v;
#pragma unroll
    for (int o = 1; o < 32; o <<= 1) {
        int t = __shfl_up_sync(0xffffffffu, x, o);
        if (lane >= o) x += t;
    }
    __shared__ int ws[32];
    if (lane == 31) ws[wid] = x;
    __syncthreads();
    if (wid == 0) {
        int y = ws[lane];
#pragma unroll
        for (int o = 1; o < 32; o <<= 1) {
            int t = __shfl_up_sync(0xffffffffu, y, o);
            if (lane >= o) y += t;
        }
        ws[lane] = y;
    }
    __syncthreads();
    int incl = x + (wid ? ws[wid - 1] : 0);
    d_dhist[tid] = incl - v;
}

// add block offsets + degree-sorted scatter of node ids
__global__ void scan_add(int n) {
    int i = blockIdx.x * 1024 + threadIdx.x;
    if (i >= n) return;
    d_off[i] += d_bsum[blockIdx.x];
    int b = min(d_deg[i], DBINS - 1);
    int pos = d_dhist[b] + atomicAdd(&d_dcur[b], 1);
    d_perm[pos] = i;
}

__global__ void scatter_k(const int* __restrict__ ei, int E, int n) {
    int e = blockIdx.x * blockDim.x + threadIdx.x;
    int Etot = E + n;
    if (e >= Etot) return;
    int s, d;
    if (e < E) { s = __ldg(&ei[e]); d = __ldg(&ei[E + e]); } else { s = d = e - E; }
    int pos = d_off[d] + atomicAdd(&d_cur[d], 1);
    d_csr_src[pos] = s;
}

// ================= layer-1 attention coefficients =================
__global__ void gemv_attn(const float* __restrict__ x, int n) {
    __shared__ float4 ws[INC], wd[INC];
    for (int i = threadIdx.x; i < INC; i += 256) { ws[i] = d_wa1s[i]; wd[i] = d_wa1d[i]; }
    __syncthreads();
    int warp = (blockIdx.x * blockDim.x + threadIdx.x) >> 5;
    int lane = threadIdx.x & 31;
    if (warp >= n) return;
    float4 xv = *reinterpret_cast<const float4*>(&x[(size_t)warp * INC + lane * 4]);
    float xr[4] = {xv.x, xv.y, xv.z, xv.w};
    float ps[NHEADS] = {}, pd[NHEADS] = {};
#pragma unroll
    for (int j = 0; j < 4; j++) {
        float4 a = ws[j * 32 + lane];
        float4 b = wd[j * 32 + lane];
        ps[0] = fmaf(xr[j], a.x, ps[0]); ps[1] = fmaf(xr[j], a.y, ps[1]);
        ps[2] = fmaf(xr[j], a.z, ps[2]); ps[3] = fmaf(xr[j], a.w, ps[3]);
        pd[0] = fmaf(xr[j], b.x, pd[0]); pd[1] = fmaf(xr[j], b.y, pd[1]);
        pd[2] = fmaf(xr[j], b.z, pd[2]); pd[3] = fmaf(xr[j], b.w, pd[3]);
    }
#pragma unroll
    for (int h = 0; h < NHEADS; h++) {
#pragma unroll
        for (int o = 16; o; o >>= 1) {
            ps[h] += __shfl_xor_sync(0xffffffffu, ps[h], o);
            pd[h] += __shfl_xor_sync(0xffffffffu, pd[h], o);
        }
    }
    if (!lane) {
#pragma unroll
        for (int h = 0; h < NHEADS; h++) {
            d_asrcA[warp * NHEADS + h] = ps[h];
            d_adstA[warp * NHEADS + h] = pd[h];
        }
    }
}

// ================= TF32 GEMM (cp.async double buffer) ======================
// AG=true: A = d_feat, values pre-rounded to tf32 by agg epilogue -> no cvt needed.
__device__ __forceinline__ void mma_tf32(float c[4], uint32_t a0, uint32_t a1,
                                         uint32_t a2, uint32_t a3,
                                         uint32_t b0, uint32_t b1) {
    asm volatile(
        "mma.sync.aligned.m16n8k8.row.col.f32.tf32.tf32.f32 "
        "{%0,%1,%2,%3}, {%4,%5,%6,%7}, {%8,%9}, {%0,%1,%2,%3};"
        : "+f"(c[0]), "+f"(c[1]), "+f"(c[2]), "+f"(c[3])
        : "r"(a0), "r"(a1), "r"(a2), "r"(a3), "r"(b0), "r"(b1));
}

__device__ __forceinline__ void cp16p(float* smem_dst, const float* gsrc, bool pred) {
    unsigned sa = (unsigned)__cvta_generic_to_shared(smem_dst);
    int sz = pred ? 16 : 0;
    asm volatile("cp.async.ca.shared.global [%0], [%1], 16, %2;\n" :: "r"(sa), "l"(gsrc), "r"(sz));
}
__device__ __forceinline__ void cp_commit() { asm volatile("cp.async.commit_group;"); }
template <int N>
__device__ __forceinline__ void cp_wait() { asm volatile("cp.async.wait_group %0;" :: "n"(N)); }

template <int K, int NOUT, bool AG, int BN, int WM, int WN>
__launch_bounds__(256, 2)
__global__ void tgemm_k(const float* __restrict__ Ain, const float* __restrict__ B, int M) {
    constexpr int BM = 128, BK = 16;
    constexpr int MT = BM / (WM * 16);
    constexpr int NT = BN / (WN * 8);
    __shared__ float As[2][BM][BK + 4];
    __shared__ float Bs[2][BK][BN + 8];
    const float* A = AG ? (const float*)d_feat : Ain;

    int tid = threadIdx.x;
    int wid = tid >> 5, lane = tid & 31;
    int wm = wid % WM, wn = wid / WM;
    int row0 = blockIdx.y * BM;
    int col0 = blockIdx.x * BN;
    int lr = lane >> 2, lc = lane & 3;

    float c[MT][NT][4];
#pragma unroll
    for (int i = 0; i < MT; i++)
#pragma unroll
        for (int j = 0; j < NT; j++)
#pragma unroll
            for (int q = 0; q < 4; q++) c[i][j][q] = 0.f;

    constexpr int B4 = BN / 4;
    constexpr int BLD = (BK * B4) / 256;
    const int nk = K / BK;

    {
#pragma unroll
        for (int j = 0; j < 2; j++) {
            int idx = tid + j * 256;
            int r = idx >> 2, q = idx & 3;
            cp16p(&As[0][r][q * 4], &A[(size_t)(row0 + r) * K + q * 4], (row0 + r) < M);
        }
#pragma unroll
        for (int j = 0; j < BLD; j++) {
            int idx = tid + j * 256;
            int r = idx / B4, q = idx % B4;
            cp16p(&Bs[0][r][q * 4], &B[(size_t)r * NOUT + col0 + q * 4], true);
        }
        cp_commit();
    }

    for (int t = 0; t < nk; t++) {
        int cur = t & 1;
        if (t + 1 < nk) {
            int k0 = (t + 1) * BK;
#pragma unroll
            for (int j = 0; j < 2; j++) {
                int idx = tid + j * 256;
                int r = idx >> 2, q = idx & 3;
                cp16p(&As[1 - cur][r][q * 4], &A[(size_t)(row0 + r) * K + k0 + q * 4], (row0 + r) < M);
            }
#pragma unroll
            for (int j = 0; j < BLD; j++) {
                int idx = tid + j * 256;
                int r = idx / B4, q = idx % B4;
                cp16p(&Bs[1 - cur][r][q * 4], &B[(size_t)(k0 + r) * NOUT + col0 + q * 4], true);
            }
            cp_commit();
            cp_wait<1>();
        } else {
            cp_wait<0>();
        }
        __syncthreads();

#pragma unroll
        for (int kk = 0; kk < BK; kk += 8) {
            uint32_t af[MT][4], bf[NT][2];
#pragma unroll
            for (int mt = 0; mt < MT; mt++) {
                int bm = wm * MT * 16 + mt * 16;
                if (AG) {   // pre-rounded: raw bits
                    af[mt][0] = __float_as_uint(As[cur][bm + lr][kk + lc]);
                    af[mt][1] = __float_as_uint(As[cur][bm + lr + 8][kk + lc]);
                    af[mt][2] = __float_as_uint(As[cur][bm + lr][kk + lc + 4]);
                    af[mt][3] = __float_as_uint(As[cur][bm + lr + 8][kk + lc + 4]);
                } else {
                    af[mt][0] = cvt_tf32(As[cur][bm + lr][kk + lc]);
                    af[mt][1] = cvt_tf32(As[cur][bm + lr + 8][kk + lc]);
                    af[mt][2] = cvt_tf32(As[cur][bm + lr][kk + lc + 4]);
                    af[mt][3] = cvt_tf32(As[cur][bm + lr + 8][kk + lc + 4]);
                }
            }
#pragma unroll
            for (int nt = 0; nt < NT; nt++) {
                int bn = wn * NT * 8 + nt * 8;
                bf[nt][0] = cvt_tf32(Bs[cur][kk + lc][bn + lr]);
                bf[nt][1] = cvt_tf32(Bs[cur][kk + lc + 4][bn + lr]);
            }
#pragma unroll
            for (int mt = 0; mt < MT; mt++)
#pragma unroll
                for (int nt = 0; nt < NT; nt++)
                    mma_tf32(c[mt][nt], af[mt][0], af[mt][1], af[mt][2], af[mt][3],
                             bf[nt][0], bf[nt][1]);
        }
        __syncthreads();
    }

#pragma unroll
    for (int mt = 0; mt < MT; mt++) {
        int r0 = row0 + wm * MT * 16 + mt * 16 + lr;
#pragma unroll
        for (int nt = 0; nt < NT; nt++) {
            int cc = col0 + wn * NT * 8 + nt * 8 + 2 * lc;
            if (r0 < M)
                *reinterpret_cast<float2*>(&d_h[(size_t)r0 * NOUT + cc]) =
                    make_float2(c[mt][nt][0], c[mt][nt][1]);
            if (r0 + 8 < M)
                *reinterpret_cast<float2*>(&d_h[(size_t)(r0 + 8) * NOUT + cc]) =
                    make_float2(c[mt][nt][2], c[mt][nt][3]);
        }
    }
}

// ======== fused aggregation: single-pass unnormalized softmax, WPN warps/node ========
template <int H, int WPN, int HN, bool DOELU, bool SRCA, bool POOL>
__launch_bounds__(256)
__global__ void agg_k(const float* __restrict__ bias, const int* __restrict__ batch, int n) {
    constexpr int C = 64, F = H * C, CH = F / WPN, RF = CH / 32;
    __shared__ float4 wsn4[HN == 4 ? F : 1], wdn4[HN == 4 ? F : 1];
    __shared__ float  wsn1[HN == 1 ? F : 1], wdn1[HN == 1 ? F : 1];
    __shared__ float  parts[8][8];
    if (HN == 4) {
        for (int i = threadIdx.x; i < F; i += 256) { wsn4[i] = d_wa2s[i]; wdn4[i] = d_wa2d[i]; }
        __syncthreads();
    } else if (HN == 1) {
        for (int i = threadIdx.x; i < F; i += 256) { wsn1[i] = d_wa3s[i]; wdn1[i] = d_wa3d[i]; }
        __syncthreads();
    }
    const float* asrc  = SRCA ? d_asrcA : d_asrcB;
    const float* adstp = SRCA ? d_adstA : d_adstB;
    float* nsrc = SRCA ? d_asrcB : d_asrcA;
    float* ndst = SRCA ? d_adstB : d_adstA;

    int gw   = (blockIdx.x * blockDim.x + threadIdx.x) >> 5;
    int wblk = threadIdx.x >> 5;
    int lane = threadIdx.x & 31;
    int slot = gw / WPN;
    int sub  = gw % WPN;
    bool valid = slot < n;
    int node = valid ? d_perm[slot] : 0;

    float acc[RF];
#pragma unroll
    for (int k = 0; k < RF; k++) acc[k] = 0.f;

    if (valid) {
        int off = d_off[node], deg = d_deg[node];

        const int hl = (H == 4) ? (lane >> 4) : 0;
        const int asoff = (H == 4) ? (sub * 2 + hl) : 0;
        const float adh = adstp[node * H + asoff];
        const size_t cbase = sub * CH + lane * RF;

        float S = 0.f;
#pragma unroll 2
        for (int j = 0; j < deg; j++) {
            int s = d_csr_src[off + j];
            float v = asrc[s * H + asoff] + adh;
            v = v > 0.f ? v : NEG * v;
            float w = __expf(v);
            S += w;
            const float* hs = &d_h[(size_t)s * F + cbase];
            if (RF == 4) {
                float4 v0 = *reinterpret_cast<const float4*>(hs);
                acc[0] = fmaf(w, v0.x, acc[0]); acc[1] = fmaf(w, v0.y, acc[1]);
                acc[2] = fmaf(w, v0.z, acc[2]); acc[3] = fmaf(w, v0.w, acc[3]);
            } else {
                float2 v0 = *reinterpret_cast<const float2*>(hs);
                acc[0] = fmaf(w, v0.x, acc[0]); acc[1] = fmaf(w, v0.y, acc[1]);
            }
        }
        float inv = 1.f / (S + EPSV);

#pragma unroll
        for (int k = 0; k < RF; k++) {
            float v = acc[k] * inv + bias[sub * CH + lane * RF + k];
            if (DOELU) v = v > 0.f ? v : (__expf(v) - 1.f);
            acc[k] = v;
        }

        if (POOL) {
            int g = __ldg(&batch[node]);
            atomicAdd(&d_pool[g * HIDC + lane * RF + 0], acc[0]);
            atomicAdd(&d_pool[g * HIDC + lane * RF + 1], acc[1]);
            if (!lane) atomicAdd(&d_cnt[g], 1.0f);
        } else {
            // store tf32-pre-rounded values (identical to GEMM's own rounding)
            float* outp = &d_feat[(size_t)node * F + sub * CH + lane * RF];
            if (RF == 4) {
                *reinterpret_cast<float4*>(outp) = make_float4(
                    __uint_as_float(cvt_tf32(acc[0])), __uint_as_float(cvt_tf32(acc[1])),
                    __uint_as_float(cvt_tf32(acc[2])), __uint_as_float(cvt_tf32(acc[3])));
            } else {
                *reinterpret_cast<float2*>(outp) = make_float2(
                    __uint_as_float(cvt_tf32(acc[0])), __uint_as_float(cvt_tf32(acc[1])));
            }
        }

        // partial next-layer coefficients (from UNROUNDED acc)
        if (HN == 4) {
            float ps[4] = {}, pd[4] = {};
#pragma unroll
            for (int k = 0; k < RF; k++) {
                float4 a = wsn4[sub * CH + k * 32 + lane];
                float4 b = wdn4[sub * CH + k * 32 + lane];
                ps[0] = fmaf(acc[k], a.x, ps[0]); ps[1] = fmaf(acc[k], a.y, ps[1]);
                ps[2] = fmaf(acc[k], a.z, ps[2]); ps[3] = fmaf(acc[k], a.w, ps[3]);
                pd[0] = fmaf(acc[k], b.x, pd[0]); pd[1] = fmaf(acc[k], b.y, pd[1]);
                pd[2] = fmaf(acc[k], b.z, pd[2]); pd[3] = fmaf(acc[k], b.w, pd[3]);
            }
#pragma unroll
            for (int h = 0; h < 4; h++) {
#pragma unroll
                for (int o = 16; o; o >>= 1) {
                    ps[h] += __shfl_xor_sync(0xffffffffu, ps[h], o);
                    pd[h] += __shfl_xor_sync(0xffffffffu, pd[h], o);
                }
            }
            if (!lane) {
#pragma unroll
                for (int h = 0; h < 4; h++) {
                    parts[wblk][h] = ps[h];
                    parts[wblk][4 + h] = pd[h];
                }
            }
        } else if (HN == 1) {
            float ps = 0.f, pd = 0.f;
#pragma unroll
            for (int k = 0; k < RF; k++) {
                ps = fmaf(acc[k], wsn1[sub * CH + k * 32 + lane], ps);
                pd = fmaf(acc[k], wdn1[sub * CH + k * 32 + lane], pd);
            }
#pragma unroll
            for (int o = 16; o; o >>= 1) {
                ps += __shfl_xor_sync(0xffffffffu, ps, o);
                pd += __shfl_xor_sync(0xffffffffu, pd, o);
            }
            if (!lane) { parts[wblk][0] = ps; parts[wblk][1] = pd; }
        }
    }

    if (HN > 0) {
        __syncthreads();
        if (valid && sub == 0 && !lane) {
            if (HN == 4) {
#pragma unroll
                for (int h = 0; h < 4; h++) {
                    nsrc[node * 4 + h] = parts[wblk][h]     + parts[wblk + 1][h];
                    ndst[node * 4 + h] = parts[wblk][4 + h] + parts[wblk + 1][4 + h];
                }
            } else {
                nsrc[node] = parts[wblk][0] + parts[wblk + 1][0];
                ndst[node] = parts[wblk][1] + parts[wblk + 1][1];
            }
        }
    }
}

// ---------------- head ----------------
__global__ void head_k(const float* __restrict__ Wc, const float* __restrict__ bc,
                       float* __restrict__ out) {
    int t = blockIdx.x * blockDim.x + threadIdx.x;
    if (t >= GG * OUTC) return;
    int g = t / OUTC, o = t % OUTC;
    float inv = 1.f / fmaxf(d_cnt[g], 1.f);
    float s = 0.f;
#pragma unroll
    for (int c = 0; c < HIDC; c++) s += d_pool[g * HIDC + c] * Wc[c * OUTC + o];
    out[t] = s * inv + bc[o];
}

// ---------------- host orchestration ----------------
extern "C" void kernel_launch(void* const* d_in, const int* in_sizes, int n_in,
                              void* d_out, int out_size) {
    const float* x   = (const float*)d_in[0];
    const int*   ei  = (const int*)d_in[1];
    const int*   bat = (const int*)d_in[2];
    const float* W1 = (const float*)d_in[3],  *as1 = (const float*)d_in[4],
               * ad1 = (const float*)d_in[5], *b1  = (const float*)d_in[6];
    const float* W2 = (const float*)d_in[7],  *as2 = (const float*)d_in[8],
               * ad2 = (const float*)d_in[9], *b2  = (const float*)d_in[10];
    const float* W3 = (const float*)d_in[11], *as3 = (const float*)d_in[12],
               * ad3 = (const float*)d_in[13],*b3  = (const float*)d_in[14];
    const float* Wc = (const float*)d_in[15], *bc  = (const float*)d_in[16];
    float* out = (float*)d_out;

    int n    = in_sizes[0] / INC;
    int E    = in_sizes[1] / 2;
    int Etot = E + n;

    int gemm_rows = (n + 127) / 128;
    int eb    = (Etot + 255) / 256;
    int nb    = (n + 255) / 256;
    int sb    = (n + 1023) / 1024;
    int aggb2 = (int)(((long long)n * 2 * 32 + 255) / 256);
    int aggb1 = (int)(((long long)n * 32 + 255) / 256);

    wa_prep<<<32, 256>>>(W1, as1, ad1, W2, as2, ad2, W3, as3, ad3);         // 0
    zero_all<<<nb, 256>>>(n);                                               // 1
    hist_k<<<eb, 256>>>(ei, E, n);                                          // 2
    tgemm_k<INC, F1, false, 128, 2, 4><<<dim3(F1 / 128, gemm_rows), 256>>>(x, W1, n); // 3
    scan_blk<<<sb, 1024>>>(n);                                              // 4 (+dhist)
    scan_top<<<1, 1024>>>(sb);                                              // 5 (+dscan)
    scan_add<<<sb, 1024>>>(n);                                              // 6 (+dscatter)
    scatter_k<<<eb, 256>>>(ei, E, n);                                       // 7
    gemv_attn<<<(n + 7) / 8, 256>>>(x, n);                                  // 8

    // ---- Layer 1 agg (H=4, 2 warps/node, deg-sorted, single-pass); layer-2 coeffs ----
    agg_k<NHEADS, 2, NHEADS, true, true, false><<<aggb2, 256>>>(b1, nullptr, n);

    // ---- Layer 2 (H=4, in=256, out=256); A pre-rounded -> no cvt ----
    tgemm_k<F1, F1, true, 128, 2, 4><<<dim3(F1 / 128, gemm_rows), 256>>>(nullptr, W2, n);
    agg_k<NHEADS, 2, 1, true, false, false><<<aggb2, 256>>>(b2, nullptr, n);

    // ---- Layer 3 (H=1, in=256, out=64); A pre-rounded -> no cvt ----
    tgemm_k<F1, HIDC, true, 64, 4, 2><<<dim3(1, gemm_rows), 256>>>(nullptr, W3, n);
    agg_k<1, 1, 0, false, true, true><<<aggb1, 256>>>(b3, bat, n);

    // ---- head ----
    head_k<<<(GG * OUTC + 255) / 256, 256>>>(Wc, bc, out);
}

// round 16
// speedup vs baseline: 1.7896x; 1.0231x over previous
#include <cuda_runtime.h>
#include <cstdint>

// ---------------- Problem constants ----------------
#define NMAX    50000
#define EMAX    800000
#define ETOTMAX (EMAX + NMAX)
#define GG      64
#define INC     128
#define HIDC    64
#define NHEADS  4
#define F1      (NHEADS * HIDC)   // 256
#define OUTC    10
#define NEG     0.2f
#define EPSV    1e-16f
#define FLTMAX  3.402823466e38f
#define DBINS   1024

// ---------------- Device scratch ----------------
__device__ float d_h[(size_t)NMAX * F1];
__device__ float d_feat[(size_t)NMAX * F1];
__device__ __align__(16) float d_asrcA[NMAX * NHEADS];
__device__ __align__(16) float d_adstA[NMAX * NHEADS];
__device__ __align__(16) float d_asrcB[NMAX * NHEADS];
__device__ __align__(16) float d_adstB[NMAX * NHEADS];
__device__ int   d_deg[NMAX];
__device__ int   d_off[NMAX];
__device__ int   d_cur[NMAX];
__device__ int   d_bsum[64];
__device__ int   d_csr_src[ETOTMAX];
__device__ int   d_dhist[DBINS];
__device__ int   d_dcur[DBINS];
__device__ int   d_perm[NMAX];
__device__ float d_pool[GG * HIDC];
__device__ float d_cnt[GG];
// precomputed W @ a vectors, PERMUTED: p(ch) = (ch>>7)*128 + (ch&3)*32 + ((ch>>2)&31)
__device__ float4 d_wa1s[INC], d_wa1d[INC];
__device__ float4 d_wa2s[F1],  d_wa2d[F1];
__device__ float  d_wa3s[F1],  d_wa3d[F1];

__device__ __forceinline__ int waperm(int ch) {
    return (ch >> 7) * 128 + (ch & 3) * 32 + ((ch >> 2) & 31);
}

__device__ __forceinline__ uint32_t cvt_tf32(float x) {
    uint32_t u;
    asm("cvt.rna.tf32.f32 %0, %1;" : "=r"(u) : "f"(x));
    return u;
}

// ================= wa precompute: warp per k, coalesced =================
__global__ void wa_prep(const float* __restrict__ W1, const float* __restrict__ as1, const float* __restrict__ ad1,
                        const float* __restrict__ W2, const float* __restrict__ as2, const float* __restrict__ ad2,
                        const float* __restrict__ W3, const float* __restrict__ as3, const float* __restrict__ ad3) {
    int gw = (blockIdx.x * blockDim.x + threadIdx.x) >> 5;
    int lane = threadIdx.x & 31;
    if (gw >= F1) return;
    int k = gw;

    if (k < INC) {
        float4 s, d;
        float* sp = (float*)&s; float* dp = (float*)&d;
#pragma unroll
        for (int h = 0; h < NHEADS; h++) {
            float w0 = W1[(size_t)k * F1 + h * HIDC + lane];
            float w1 = W1[(size_t)k * F1 + h * HIDC + lane + 32];
            float ss = w0 * as1[h * HIDC + lane] + w1 * as1[h * HIDC + lane + 32];
            float dd = w0 * ad1[h * HIDC + lane] + w1 * ad1[h * HIDC + lane + 32];
#pragma unroll
            for (int o = 16; o; o >>= 1) {
                ss += __shfl_xor_sync(0xffffffffu, ss, o);
                dd += __shfl_xor_sync(0xffffffffu, dd, o);
            }
            sp[h] = ss; dp[h] = dd;
        }
        if (!lane) {
            int p = (k & 3) * 32 + (k >> 2);
            d_wa1s[p] = s; d_wa1d[p] = d;
        }
    }
    {
        float4 s, d;
        float* sp = (float*)&s; float* dp = (float*)&d;
#pragma unroll
        for (int h = 0; h < NHEADS; h++) {
            float w0 = W2[(size_t)k * F1 + h * HIDC + lane];
            float w1 = W2[(size_t)k * F1 + h * HIDC + lane + 32];
            float ss = w0 * as2[h * HIDC + lane] + w1 * as2[h * HIDC + lane + 32];
            float dd = w0 * ad2[h * HIDC + lane] + w1 * ad2[h * HIDC + lane + 32];
#pragma unroll
            for (int o = 16; o; o >>= 1) {
                ss += __shfl_xor_sync(0xffffffffu, ss, o);
                dd += __shfl_xor_sync(0xffffffffu, dd, o);
            }
            sp[h] = ss; dp[h] = dd;
        }
        float w0 = W3[(size_t)k * HIDC + lane];
        float w1 = W3[(size_t)k * HIDC + lane + 32];
        float s3 = w0 * as3[lane] + w1 * as3[lane + 32];
        float d3 = w0 * ad3[lane] + w1 * ad3[lane + 32];
#pragma unroll
        for (int o = 16; o; o >>= 1) {
            s3 += __shfl_xor_sync(0xffffffffu, s3, o);
            d3 += __shfl_xor_sync(0xffffffffu, d3, o);
        }
        if (!lane) {
            int p = waperm(k);
            d_wa2s[p] = s; d_wa2d[p] = d;
            d_wa3s[p] = s3; d_wa3d[p] = d3;
        }
    }
}

// ================= zero =================
__global__ void zero_all(int n) {
    int i = blockIdx.x * blockDim.x + threadIdx.x;
    if (i < n) { d_deg[i] = 0; d_cur[i] = 0; }
    if (i < GG * HIDC) d_pool[i] = 0.f;
    if (i < GG) d_cnt[i] = 0.f;
    if (i < DBINS) { d_dhist[i] = 0; d_dcur[i] = 0; }
}

// ================= CSR construction =================
__global__ void hist_k(const int* __restrict__ ei, int E, int n) {
    int e = blockIdx.x * blockDim.x + threadIdx.x;
    int Etot = E + n;
    if (e >= Etot) return;
    int d = (e < E) ? __ldg(&ei[E + e]) : (e - E);
    atomicAdd(&d_deg[d], 1);
}

// block scan of deg -> off; also accumulates the degree histogram
__global__ void scan_blk(int n) {
    int i = blockIdx.x * 1024 + threadIdx.x;
    int lane = threadIdx.x & 31, wid = threadIdx.x >> 5;
    int v = (i < n) ? d_deg[i] : 0;
    if (i < n) atomicAdd(&d_dhist[min(v, DBINS - 1)], 1);
    int x = v;
#pragma unroll
    for (int o = 1; o < 32; o <<= 1) {
        int t = __shfl_up_sync(0xffffffffu, x, o);
        if (lane >= o) x += t;
    }
    __shared__ int ws[32];
    if (lane == 31) ws[wid] = x;
    __syncthreads();
    if (wid == 0) {
        int y = ws[lane];
#pragma unroll
        for (int o = 1; o < 32; o <<= 1) {
            int t = __shfl_up_sync(0xffffffffu, y, o);
            if (lane >= o) y += t;
        }
        ws[lane] = y;
    }
    __syncthreads();
    int incl = x + (wid ? ws[wid - 1] : 0);
    if (i < n) d_off[i] = incl - v;
    if (threadIdx.x == 1023) d_bsum[blockIdx.x] = incl;
}

// top scan of block sums (first 64 threads) + exclusive scan of the 1024-bin dhist
__global__ void scan_top(int nb) {
    int tid = threadIdx.x;     // 1024 threads
    int lane = tid & 31, wid = tid >> 5;

    // part A: scan of d_bsum (threads 0..63)
    if (tid < 64) {
        int v = (tid < nb) ? d_bsum[tid] : 0;
        int x = v;
#pragma unroll
        for (int o = 1; o < 32; o <<= 1) {
            int t = __shfl_up_sync(0xffffffffu, x, o);
            if (lane >= o) x += t;
        }
        __shared__ int wsum[2];
        if (lane == 31) wsum[wid] = x;
        __syncthreads();
        int incl = x + (wid ? wsum[0] : 0);
        if (tid < nb) d_bsum[tid] = incl - v;
    } else {
        __syncthreads();   // match part-A barrier
    }
    __syncthreads();

    // part B: exclusive scan of d_dhist (all 1024 threads)
    int v = d_dhist[tid];
    int x = v;
#pragma unroll
    for (int o = 1; o < 32; o <<= 1) {
        int t = __shfl_up_sync(0xffffffffu, x, o);
        if (lane >= o) x += t;
    }
    __shared__ int ws[32];
    if (lane == 31) ws[wid] = x;
    __syncthreads();
    if (wid == 0) {
        int y = ws[lane];
#pragma unroll
        for (int o = 1; o < 32; o <<= 1) {
            int t = __shfl_up_sync(0xffffffffu, y, o);
            if (lane >= o) y += t;
        }
        ws[lane] = y;
    }
    __syncthreads();
    int incl = x + (wid ? ws[wid - 1] : 0);
    d_dhist[tid] = incl - v;
}

// add block offsets + degree-sorted scatter of node ids
__global__ void scan_add(int n) {
    int i = blockIdx.x * 1024 + threadIdx.x;
    if (i >= n) return;
    d_off[i] += d_bsum[blockIdx.x];
    int b = min(d_deg[i], DBINS - 1);
    int pos = d_dhist[b] + atomicAdd(&d_dcur[b], 1);
    d_perm[pos] = i;
}

__global__ void scatter_k(const int* __restrict__ ei, int E, int n) {
    int e = blockIdx.x * blockDim.x + threadIdx.x;
    int Etot = E + n;
    if (e >= Etot) return;
    int s, d;
    if (e < E) { s = __ldg(&ei[e]); d = __ldg(&ei[E + e]); } else { s = d = e - E; }
    int pos = d_off[d] + atomicAdd(&d_cur[d], 1);
    d_csr_src[pos] = s;
}

// ================= layer-1 attention coefficients =================
__global__ void gemv_attn(const float* __restrict__ x, int n) {
    __shared__ float4 ws[INC], wd[INC];
    for (int i = threadIdx.x; i < INC; i += 256) { ws[i] = d_wa1s[i]; wd[i] = d_wa1d[i]; }
    __syncthreads();
    int warp = (blockIdx.x * blockDim.x + threadIdx.x) >> 5;
    int lane = threadIdx.x & 31;
    if (warp >= n) return;
    float4 xv = *reinterpret_cast<const float4*>(&x[(size_t)warp * INC + lane * 4]);
    float xr[4] = {xv.x, xv.y, xv.z, xv.w};
    float ps[NHEADS] = {}, pd[NHEADS] = {};
#pragma unroll
    for (int j = 0; j < 4; j++) {
        float4 a = ws[j * 32 + lane];
        float4 b = wd[j * 32 + lane];
        ps[0] = fmaf(xr[j], a.x, ps[0]); ps[1] = fmaf(xr[j], a.y, ps[1]);
        ps[2] = fmaf(xr[j], a.z, ps[2]); ps[3] = fmaf(xr[j], a.w, ps[3]);
        pd[0] = fmaf(xr[j], b.x, pd[0]); pd[1] = fmaf(xr[j], b.y, pd[1]);
        pd[2] = fmaf(xr[j], b.z, pd[2]); pd[3] = fmaf(xr[j], b.w, pd[3]);
    }
#pragma unroll
    for (int h = 0; h < NHEADS; h++) {
#pragma unroll
        for (int o = 16; o; o >>= 1) {
            ps[h] += __shfl_xor_sync(0xffffffffu, ps[h], o);
            pd[h] += __shfl_xor_sync(0xffffffffu, pd[h], o);
        }
    }
    if (!lane) {
#pragma unroll
        for (int h = 0; h < NHEADS; h++) {
            d_asrcA[warp * NHEADS + h] = ps[h];
            d_adstA[warp * NHEADS + h] = pd[h];
        }
    }
}

// ================= TF32 GEMM (cp.async double buffer) ======================
__device__ __forceinline__ void mma_tf32(float c[4], uint32_t a0, uint32_t a1,
                                         uint32_t a2, uint32_t a3,
                                         uint32_t b0, uint32_t b1) {
    asm volatile(
        "mma.sync.aligned.m16n8k8.row.col.f32.tf32.tf32.f32 "
        "{%0,%1,%2,%3}, {%4,%5,%6,%7}, {%8,%9}, {%0,%1,%2,%3};"
        : "+f"(c[0]), "+f"(c[1]), "+f"(c[2]), "+f"(c[3])
        : "r"(a0), "r"(a1), "r"(a2), "r"(a3), "r"(b0), "r"(b1));
}

__device__ __forceinline__ void cp16p(float* smem_dst, const float* gsrc, bool pred) {
    unsigned sa = (unsigned)__cvta_generic_to_shared(smem_dst);
    int sz = pred ? 16 : 0;
    asm volatile("cp.async.ca.shared.global [%0], [%1], 16, %2;\n" :: "r"(sa), "l"(gsrc), "r"(sz));
}
__device__ __forceinline__ void cp_commit() { asm volatile("cp.async.commit_group;"); }
template <int N>
__device__ __forceinline__ void cp_wait() { asm volatile("cp.async.wait_group %0;" :: "n"(N)); }

template <int K, int NOUT, bool AG, int BN, int WM, int WN>
__launch_bounds__(256, 2)
__global__ void tgemm_k(const float* __restrict__ Ain, const float* __restrict__ B, int M) {
    constexpr int BM = 128, BK = 16;
    constexpr int MT = BM / (WM * 16);
    constexpr int NT = BN / (WN * 8);
    __shared__ float As[2][BM][BK + 4];
    __shared__ float Bs[2][BK][BN + 8];
    const float* A = AG ? (const float*)d_feat : Ain;

    int tid = threadIdx.x;
    int wid = tid >> 5, lane = tid & 31;
    int wm = wid % WM, wn = wid / WM;
    int row0 = blockIdx.y * BM;
    int col0 = blockIdx.x * BN;
    int lr = lane >> 2, lc = lane & 3;

    float c[MT][NT][4];
#pragma unroll
    for (int i = 0; i < MT; i++)
#pragma unroll
        for (int j = 0; j < NT; j++)
#pragma unroll
            for (int q = 0; q < 4; q++) c[i][j][q] = 0.f;

    constexpr int B4 = BN / 4;
    constexpr int BLD = (BK * B4) / 256;
    const int nk = K / BK;

    {
#pragma unroll
        for (int j = 0; j < 2; j++) {
            int idx = tid + j * 256;
            int r = idx >> 2, q = idx & 3;
            cp16p(&As[0][r][q * 4], &A[(size_t)(row0 + r) * K + q * 4], (row0 + r) < M);
        }
#pragma unroll
        for (int j = 0; j < BLD; j++) {
            int idx = tid + j * 256;
            int r = idx / B4, q = idx % B4;
            cp16p(&Bs[0][r][q * 4], &B[(size_t)r * NOUT + col0 + q * 4], true);
        }
        cp_commit();
    }

    for (int t = 0; t < nk; t++) {
        int cur = t & 1;
        if (t + 1 < nk) {
            int k0 = (t + 1) * BK;
#pragma unroll
            for (int j = 0; j < 2; j++) {
                int idx = tid + j * 256;
                int r = idx >> 2, q = idx & 3;
                cp16p(&As[1 - cur][r][q * 4], &A[(size_t)(row0 + r) * K + k0 + q * 4], (row0 + r) < M);
            }
#pragma unroll
            for (int j = 0; j < BLD; j++) {
                int idx = tid + j * 256;
                int r = idx / B4, q = idx % B4;
                cp16p(&Bs[1 - cur][r][q * 4], &B[(size_t)(k0 + r) * NOUT + col0 + q * 4], true);
            }
            cp_commit();
            cp_wait<1>();
        } else {
            cp_wait<0>();
        }
        __syncthreads();

#pragma unroll
        for (int kk = 0; kk < BK; kk += 8) {
            uint32_t af[MT][4], bf[NT][2];
#pragma unroll
            for (int mt = 0; mt < MT; mt++) {
                int bm = wm * MT * 16 + mt * 16;
                if (AG) {
                    af[mt][0] = __float_as_uint(As[cur][bm + lr][kk + lc]);
                    af[mt][1] = __float_as_uint(As[cur][bm + lr + 8][kk + lc]);
                    af[mt][2] = __float_as_uint(As[cur][bm + lr][kk + lc + 4]);
                    af[mt][3] = __float_as_uint(As[cur][bm + lr + 8][kk + lc + 4]);
                } else {
                    af[mt][0] = cvt_tf32(As[cur][bm + lr][kk + lc]);
                    af[mt][1] = cvt_tf32(As[cur][bm + lr + 8][kk + lc]);
                    af[mt][2] = cvt_tf32(As[cur][bm + lr][kk + lc + 4]);
                    af[mt][3] = cvt_tf32(As[cur][bm + lr + 8][kk + lc + 4]);
                }
            }
#pragma unroll
            for (int nt = 0; nt < NT; nt++) {
                int bn = wn * NT * 8 + nt * 8;
                bf[nt][0] = cvt_tf32(Bs[cur][kk + lc][bn + lr]);
                bf[nt][1] = cvt_tf32(Bs[cur][kk + lc + 4][bn + lr]);
            }
#pragma unroll
            for (int mt = 0; mt < MT; mt++)
#pragma unroll
                for (int nt = 0; nt < NT; nt++)
                    mma_tf32(c[mt][nt], af[mt][0], af[mt][1], af[mt][2], af[mt][3],
                             bf[nt][0], bf[nt][1]);
        }
        __syncthreads();
    }

#pragma unroll
    for (int mt = 0; mt < MT; mt++) {
        int r0 = row0 + wm * MT * 16 + mt * 16 + lr;
#pragma unroll
        for (int nt = 0; nt < NT; nt++) {
            int cc = col0 + wn * NT * 8 + nt * 8 + 2 * lc;
            if (r0 < M)
                *reinterpret_cast<float2*>(&d_h[(size_t)r0 * NOUT + cc]) =
                    make_float2(c[mt][nt][0], c[mt][nt][1]);
            if (r0 + 8 < M)
                *reinterpret_cast<float2*>(&d_h[(size_t)(r0 + 8) * NOUT + cc]) =
                    make_float2(c[mt][nt][2], c[mt][nt][3]);
        }
    }
}

// ======== fused aggregation: single-pass unnormalized softmax, WPN warps/node ========
template <int H, int WPN, int HN, bool DOELU, bool SRCA, bool POOL>
__launch_bounds__(256)
__global__ void agg_k(const float* __restrict__ bias, const int* __restrict__ batch, int n) {
    constexpr int C = 64, F = H * C, CH = F / WPN, RF = CH / 32;
    __shared__ float4 wsn4[HN == 4 ? F : 1], wdn4[HN == 4 ? F : 1];
    __shared__ float  wsn1[HN == 1 ? F : 1], wdn1[HN == 1 ? F : 1];
    __shared__ float  parts[8][8];
    if (HN == 4) {
        for (int i = threadIdx.x; i < F; i += 256) { wsn4[i] = d_wa2s[i]; wdn4[i] = d_wa2d[i]; }
        __syncthreads();
    } else if (HN == 1) {
        for (int i = threadIdx.x; i < F; i += 256) { wsn1[i] = d_wa3s[i]; wdn1[i] = d_wa3d[i]; }
        __syncthreads();
    }
    const float* asrc  = SRCA ? d_asrcA : d_asrcB;
    const float* adstp = SRCA ? d_adstA : d_adstB;
    float* nsrc = SRCA ? d_asrcB : d_asrcA;
    float* ndst = SRCA ? d_adstB : d_adstA;

    int gw   = (blockIdx.x * blockDim.x + threadIdx.x) >> 5;
    int wblk = threadIdx.x >> 5;
    int lane = threadIdx.x & 31;
    int slot = gw / WPN;
    int sub  = gw % WPN;
    bool valid = slot < n;
    int node = valid ? d_perm[slot] : 0;

    float acc[RF];
#pragma unroll
    for (int k = 0; k < RF; k++) acc[k] = 0.f;

    if (valid) {
        int off = d_off[node], deg = d_deg[node];

        const int hl = (H == 4) ? (lane >> 4) : 0;
        const int asoff = (H == 4) ? (sub * 2 + hl) : 0;
        const float adh = adstp[node * H + asoff];
        const size_t cbase = sub * CH + lane * RF;

        float S = 0.f;
#pragma unroll 2
        for (int j = 0; j < deg; j++) {
            int s = d_csr_src[off + j];
            float v = asrc[s * H + asoff] + adh;
            v = v > 0.f ? v : NEG * v;
            float w = __expf(v);
            S += w;
            const float* hs = &d_h[(size_t)s * F + cbase];
            if (RF == 4) {
                float4 v0 = *reinterpret_cast<const float4*>(hs);
                acc[0] = fmaf(w, v0.x, acc[0]); acc[1] = fmaf(w, v0.y, acc[1]);
                acc[2] = fmaf(w, v0.z, acc[2]); acc[3] = fmaf(w, v0.w, acc[3]);
            } else {
                float2 v0 = *reinterpret_cast<const float2*>(hs);
                acc[0] = fmaf(w, v0.x, acc[0]); acc[1] = fmaf(w, v0.y, acc[1]);
            }
        }
        float inv = 1.f / (S + EPSV);

#pragma unroll
        for (int k = 0; k < RF; k++) {
            float v = acc[k] * inv + bias[sub * CH + lane * RF + k];
            if (DOELU) v = v > 0.f ? v : (__expf(v) - 1.f);
            acc[k] = v;
        }

        if (POOL) {
            int g = __ldg(&batch[node]);
            atomicAdd(&d_pool[g * HIDC + lane * RF + 0], acc[0]);
            atomicAdd(&d_pool[g * HIDC + lane * RF + 1], acc[1]);
            if (!lane) atomicAdd(&d_cnt[g], 1.0f);
        } else {
            float* outp = &d_feat[(size_t)node * F + sub * CH + lane * RF];
            if (RF == 4) {
                *reinterpret_cast<float4*>(outp) = make_float4(
                    __uint_as_float(cvt_tf32(acc[0])), __uint_as_float(cvt_tf32(acc[1])),
                    __uint_as_float(cvt_tf32(acc[2])), __uint_as_float(cvt_tf32(acc[3])));
            } else {
                *reinterpret_cast<float2*>(outp) = make_float2(
                    __uint_as_float(cvt_tf32(acc[0])), __uint_as_float(cvt_tf32(acc[1])));
            }
        }

        if (HN == 4) {
            float ps[4] = {}, pd[4] = {};
#pragma unroll
            for (int k = 0; k < RF; k++) {
                float4 a = wsn4[sub * CH + k * 32 + lane];
                float4 b = wdn4[sub * CH + k * 32 + lane];
                ps[0] = fmaf(acc[k], a.x, ps[0]); ps[1] = fmaf(acc[k], a.y, ps[1]);
                ps[2] = fmaf(acc[k], a.z, ps[2]); ps[3] = fmaf(acc[k], a.w, ps[3]);
                pd[0] = fmaf(acc[k], b.x, pd[0]); pd[1] = fmaf(acc[k], b.y, pd[1]);
                pd[2] = fmaf(acc[k], b.z, pd[2]); pd[3] = fmaf(acc[k], b.w, pd[3]);
            }
#pragma unroll
            for (int h = 0; h < 4; h++) {
#pragma unroll
                for (int o = 16; o; o >>= 1) {
                    ps[h] += __shfl_xor_sync(0xffffffffu, ps[h], o);
                    pd[h] += __shfl_xor_sync(0xffffffffu, pd[h], o);
                }
            }
            if (!lane) {
#pragma unroll
                for (int h = 0; h < 4; h++) {
                    parts[wblk][h] = ps[h];
                    parts[wblk][4 + h] = pd[h];
                }
            }
        } else if (HN == 1) {
            float ps = 0.f, pd = 0.f;
#pragma unroll
            for (int k = 0; k < RF; k++) {
                ps = fmaf(acc[k], wsn1[sub * CH + k * 32 + lane], ps);
                pd = fmaf(acc[k], wdn1[sub * CH + k * 32 + lane], pd);
            }
#pragma unroll
            for (int o = 16; o; o >>= 1) {
                ps += __shfl_xor_sync(0xffffffffu, ps, o);
                pd += __shfl_xor_sync(0xffffffffu, pd, o);
            }
            if (!lane) { parts[wblk][0] = ps; parts[wblk][1] = pd; }
        }
    }

    if (HN > 0) {
        __syncthreads();
        if (valid && sub == 0 && !lane) {
            if (HN == 4) {
#pragma unroll
                for (int h = 0; h < 4; h++) {
                    nsrc[node * 4 + h] = parts[wblk][h]     + parts[wblk + 1][h];
                    ndst[node * 4 + h] = parts[wblk][4 + h] + parts[wblk + 1][4 + h];
                }
            } else {
                nsrc[node] = parts[wblk][0] + parts[wblk + 1][0];
                ndst[node] = parts[wblk][1] + parts[wblk + 1][1];
            }
        }
    }
}

// ---------------- head ----------------
__global__ void head_k(const float* __restrict__ Wc, const float* __restrict__ bc,
                       float* __restrict__ out) {
    int t = blockIdx.x * blockDim.x + threadIdx.x;
    if (t >= GG * OUTC) return;
    int g = t / OUTC, o = t % OUTC;
    float inv = 1.f / fmaxf(d_cnt[g], 1.f);
    float s = 0.f;
#pragma unroll
    for (int c = 0; c < HIDC; c++) s += d_pool[g * HIDC + c] * Wc[c * OUTC + o];
    out[t] = s * inv + bc[o];
}

// ---------------- host orchestration ----------------
extern "C" void kernel_launch(void* const* d_in, const int* in_sizes, int n_in,
                              void* d_out, int out_size) {
    const float* x   = (const float*)d_in[0];
    const int*   ei  = (const int*)d_in[1];
    const int*   bat = (const int*)d_in[2];
    const float* W1 = (const float*)d_in[3],  *as1 = (const float*)d_in[4],
               * ad1 = (const float*)d_in[5], *b1  = (const float*)d_in[6];
    const float* W2 = (const float*)d_in[7],  *as2 = (const float*)d_in[8],
               * ad2 = (const float*)d_in[9], *b2  = (const float*)d_in[10];
    const float* W3 = (const float*)d_in[11], *as3 = (const float*)d_in[12],
               * ad3 = (const float*)d_in[13],*b3  = (const float*)d_in[14];
    const float* Wc = (const float*)d_in[15], *bc  = (const float*)d_in[16];
    float* out = (float*)d_out;

    int n    = in_sizes[0] / INC;
    int E    = in_sizes[1] / 2;
    int Etot = E + n;

    int gemm_rows = (n + 127) / 128;
    int eb    = (Etot + 255) / 256;
    int nb    = (n + 255) / 256;
    int sb    = (n + 1023) / 1024;
    int aggb2 = (int)(((long long)n * 2 * 32 + 255) / 256);
    int aggb1 = (int)(((long long)n * 32 + 255) / 256);

    // one-time stream/event creation (host objects; same launched work every call)
    static cudaStream_t s2 = nullptr;
    static cudaEvent_t evF = nullptr, evJ = nullptr;
    if (s2 == nullptr) {
        cudaStreamCreateWithFlags(&s2, cudaStreamNonBlocking);
        cudaEventCreateWithFlags(&evF, cudaEventDisableTiming);
        cudaEventCreateWithFlags(&evJ, cudaEventDisableTiming);
    }

    // ---- fork: CSR chain on s2, concurrent with wa/GEMM1/gemv on main ----
    cudaEventRecord(evF, 0);
    cudaStreamWaitEvent(s2, evF, 0);

    // stream s2: CSR build + degree sort (independent of weights/features)
    zero_all<<<nb, 256, 0, s2>>>(n);
    hist_k<<<eb, 256, 0, s2>>>(ei, E, n);
    scan_blk<<<sb, 1024, 0, s2>>>(n);
    scan_top<<<1, 1024, 0, s2>>>(sb);
    scan_add<<<sb, 1024, 0, s2>>>(n);
    scatter_k<<<eb, 256, 0, s2>>>(ei, E, n);
    cudaEventRecord(evJ, s2);

    // main stream: weights prep + layer-1 GEMM + layer-1 coefficients
    wa_prep<<<32, 256>>>(W1, as1, ad1, W2, as2, ad2, W3, as3, ad3);
    tgemm_k<INC, F1, false, 128, 2, 4><<<dim3(F1 / 128, gemm_rows), 256>>>(x, W1, n);
    gemv_attn<<<(n + 7) / 8, 256>>>(x, n);

    // ---- join ----
    cudaStreamWaitEvent(0, evJ, 0);

    // ---- Layer 1 agg (H=4, 2 warps/node, deg-sorted, single-pass); layer-2 coeffs ----
    agg_k<NHEADS, 2, NHEADS, true, true, false><<<aggb2, 256>>>(b1, nullptr, n);

    // ---- Layer 2 (H=4, in=256, out=256); A pre-rounded -> no cvt ----
    tgemm_k<F1, F1, true, 128, 2, 4><<<dim3(F1 / 128, gemm_rows), 256>>>(nullptr, W2, n);
    agg_k<NHEADS, 2, 1, true, false, false><<<aggb2, 256>>>(b2, nullptr, n);

    // ---- Layer 3 (H=1, in=256, out=64); A pre-rounded -> no cvt ----
    tgemm_k<F1, HIDC, true, 64, 4, 2><<<dim3(1, gemm_rows), 256>>>(nullptr, W3, n);
    agg_k<1, 1, 0, false, true, true><<<aggb1, 256>>>(b3, bat, n);

    // ---- head ----
    head_k<<<(GG * OUTC + 255) / 256, 256>>>(Wc, bc, out);
}

// round 17
// speedup vs baseline: 1.8706x; 1.0452x over previous
#include <cuda_runtime.h>
#include <cuda_fp16.h>
#include <cstdint>

// ---------------- Problem constants ----------------
#define NMAX    50000
#define EMAX    800000
#define ETOTMAX (EMAX + NMAX)
#define GG      64
#define INC     128
#define HIDC    64
#define NHEADS  4
#define F1      (NHEADS * HIDC)   // 256
#define OUTC    10
#define NEG     0.2f
#define EPSV    1e-16f
#define FLTMAX  3.402823466e38f
#define DBINS   1024

// ---------------- Device scratch ----------------
__device__ __align__(16) __half d_h[(size_t)NMAX * F1];   // fp16 features
__device__ float d_feat[(size_t)NMAX * F1];
__device__ __align__(16) float d_asrcA[NMAX * NHEADS];
__device__ __align__(16) float d_adstA[NMAX * NHEADS];
__device__ __align__(16) float d_asrcB[NMAX * NHEADS];
__device__ __align__(16) float d_adstB[NMAX * NHEADS];
__device__ int   d_deg[NMAX];
__device__ int   d_off[NMAX];
__device__ int   d_cur[NMAX];
__device__ int   d_bsum[64];
__device__ int   d_csr_src[ETOTMAX];
__device__ int   d_dhist[DBINS];
__device__ int   d_dcur[DBINS];
__device__ int   d_perm[NMAX];
__device__ float d_pool[GG * HIDC];
__device__ float d_cnt[GG];
// precomputed W @ a vectors, PERMUTED: p(ch) = (ch>>7)*128 + (ch&3)*32 + ((ch>>2)&31)
__device__ float4 d_wa1s[INC], d_wa1d[INC];
__device__ float4 d_wa2s[F1],  d_wa2d[F1];
__device__ float  d_wa3s[F1],  d_wa3d[F1];

__device__ __forceinline__ int waperm(int ch) {
    return (ch >> 7) * 128 + (ch & 3) * 32 + ((ch >> 2) & 31);
}

__device__ __forceinline__ uint32_t cvt_tf32(float x) {
    uint32_t u;
    asm("cvt.rna.tf32.f32 %0, %1;" : "=r"(u) : "f"(x));
    return u;
}

// ================= wa precompute: warp per k, coalesced =================
__global__ void wa_prep(const float* __restrict__ W1, const float* __restrict__ as1, const float* __restrict__ ad1,
                        const float* __restrict__ W2, const float* __restrict__ as2, const float* __restrict__ ad2,
                        const float* __restrict__ W3, const float* __restrict__ as3, const float* __restrict__ ad3) {
    int gw = (blockIdx.x * blockDim.x + threadIdx.x) >> 5;
    int lane = threadIdx.x & 31;
    if (gw >= F1) return;
    int k = gw;

    if (k < INC) {
        float4 s, d;
        float* sp = (float*)&s; float* dp = (float*)&d;
#pragma unroll
        for (int h = 0; h < NHEADS; h++) {
            float w0 = W1[(size_t)k * F1 + h * HIDC + lane];
            float w1 = W1[(size_t)k * F1 + h * HIDC + lane + 32];
            float ss = w0 * as1[h * HIDC + lane] + w1 * as1[h * HIDC + lane + 32];
            float dd = w0 * ad1[h * HIDC + lane] + w1 * ad1[h * HIDC + lane + 32];
#pragma unroll
            for (int o = 16; o; o >>= 1) {
                ss += __shfl_xor_sync(0xffffffffu, ss, o);
                dd += __shfl_xor_sync(0xffffffffu, dd, o);
            }
            sp[h] = ss; dp[h] = dd;
        }
        if (!lane) {
            int p = (k & 3) * 32 + (k >> 2);
            d_wa1s[p] = s; d_wa1d[p] = d;
        }
    }
    {
        float4 s, d;
        float* sp = (float*)&s; float* dp = (float*)&d;
#pragma unroll
        for (int h = 0; h < NHEADS; h++) {
            float w0 = W2[(size_t)k * F1 + h * HIDC + lane];
            float w1 = W2[(size_t)k * F1 + h * HIDC + lane + 32];
            float ss = w0 * as2[h * HIDC + lane] + w1 * as2[h * HIDC + lane + 32];
            float dd = w0 * ad2[h * HIDC + lane] + w1 * ad2[h * HIDC + lane + 32];
#pragma unroll
            for (int o = 16; o; o >>= 1) {
                ss += __shfl_xor_sync(0xffffffffu, ss, o);
                dd += __shfl_xor_sync(0xffffffffu, dd, o);
            }
            sp[h] = ss; dp[h] = dd;
        }
        float w0 = W3[(size_t)k * HIDC + lane];
        float w1 = W3[(size_t)k * HIDC + lane + 32];
        float s3 = w0 * as3[lane] + w1 * as3[lane + 32];
        float d3 = w0 * ad3[lane] + w1 * ad3[lane + 32];
#pragma unroll
        for (int o = 16; o; o >>= 1) {
            s3 += __shfl_xor_sync(0xffffffffu, s3, o);
            d3 += __shfl_xor_sync(0xffffffffu, d3, o);
        }
        if (!lane) {
            int p = waperm(k);
            d_wa2s[p] = s; d_wa2d[p] = d;
            d_wa3s[p] = s3; d_wa3d[p] = d3;
        }
    }
}

// ================= zero =================
__global__ void zero_all(int n) {
    int i = blockIdx.x * blockDim.x + threadIdx.x;
    if (i < n) { d_deg[i] = 0; d_cur[i] = 0; }
    if (i < GG * HIDC) d_pool[i] = 0.f;
    if (i < GG) d_cnt[i] = 0.f;
    if (i < DBINS) { d_dhist[i] = 0; d_dcur[i] = 0; }
}

// ================= CSR construction =================
__global__ void hist_k(const int* __restrict__ ei, int E, int n) {
    int e = blockIdx.x * blockDim.x + threadIdx.x;
    int Etot = E + n;
    if (e >= Etot) return;
    int d = (e < E) ? __ldg(&ei[E + e]) : (e - E);
    atomicAdd(&d_deg[d], 1);
}

__global__ void scan_blk(int n) {
    int i = blockIdx.x * 1024 + threadIdx.x;
    int lane = threadIdx.x & 31, wid = threadIdx.x >> 5;
    int v = (i < n) ? d_deg[i] : 0;
    if (i < n) atomicAdd(&d_dhist[min(v, DBINS - 1)], 1);
    int x = v;
#pragma unroll
    for (int o = 1; o < 32; o <<= 1) {
        int t = __shfl_up_sync(0xffffffffu, x, o);
        if (lane >= o) x += t;
    }
    __shared__ int ws[32];
    if (lane == 31) ws[wid] = x;
    __syncthreads();
    if (wid == 0) {
        int y = ws[lane];
#pragma unroll
        for (int o = 1; o < 32; o <<= 1) {
            int t = __shfl_up_sync(0xffffffffu, y, o);
            if (lane >= o) y += t;
        }
        ws[lane] = y;
    }
    __syncthreads();
    int incl = x + (wid ? ws[wid - 1] : 0);
    if (i < n) d_off[i] = incl - v;
    if (threadIdx.x == 1023) d_bsum[blockIdx.x] = incl;
}

__global__ void scan_top(int nb) {
    int tid = threadIdx.x;     // 1024 threads
    int lane = tid & 31, wid = tid >> 5;

    if (tid < 64) {
        int v = (tid < nb) ? d_bsum[tid] : 0;
        int x = v;
#pragma unroll
        for (int o = 1; o < 32; o <<= 1) {
            int t = __shfl_up_sync(0xffffffffu, x, o);
            if (lane >= o) x += t;
        }
        __shared__ int wsum[2];
        if (lane == 31) wsum[wid] = x;
        __syncthreads();
        int incl = x + (wid ? wsum[0] : 0);
        if (tid < nb) d_bsum[tid] = incl - v;
    } else {
        __syncthreads();
    }
    __syncthreads();

    int v = d_dhist[tid];
    int x = v;
#pragma unroll
    for (int o = 1; o < 32; o <<= 1) {
        int t = __shfl_up_sync(0xffffffffu, x, o);
        if (lane >= o) x += t;
    }
    __shared__ int ws[32];
    if (lane == 31) ws[wid] = x;
    __syncthreads();
    if (wid == 0) {
        int y = ws[lane];
#pragma unroll
        for (int o = 1; o < 32; o <<= 1) {
            int t = __shfl_up_sync(0xffffffffu, y, o);
            if (lane >= o) y += t;
        }
        ws[lane] = y;
    }
    __syncthreads();
    int incl = x + (wid ? ws[wid - 1] : 0);
    d_dhist[tid] = incl - v;
}

__global__ void scan_add(int n) {
    int i = blockIdx.x * 1024 + threadIdx.x;
    if (i >= n) return;
    d_off[i] += d_bsum[blockIdx.x];
    int b = min(d_deg[i], DBINS - 1);
    int pos = d_dhist[b] + atomicAdd(&d_dcur[b], 1);
    d_perm[pos] = i;
}

__global__ void scatter_k(const int* __restrict__ ei, int E, int n) {
    int e = blockIdx.x * blockDim.x + threadIdx.x;
    int Etot = E + n;
    if (e >= Etot) return;
    int s, d;
    if (e < E) { s = __ldg(&ei[e]); d = __ldg(&ei[E + e]); } else { s = d = e - E; }
    int pos = d_off[d] + atomicAdd(&d_cur[d], 1);
    d_csr_src[pos] = s;
}

// ================= layer-1 attention coefficients =================
__global__ void gemv_attn(const float* __restrict__ x, int n) {
    __shared__ float4 ws[INC], wd[INC];
    for (int i = threadIdx.x; i < INC; i += 256) { ws[i] = d_wa1s[i]; wd[i] = d_wa1d[i]; }
    __syncthreads();
    int warp = (blockIdx.x * blockDim.x + threadIdx.x) >> 5;
    int lane = threadIdx.x & 31;
    if (warp >= n) return;
    float4 xv = *reinterpret_cast<const float4*>(&x[(size_t)warp * INC + lane * 4]);
    float xr[4] = {xv.x, xv.y, xv.z, xv.w};
    float ps[NHEADS] = {}, pd[NHEADS] = {};
#pragma unroll
    for (int j = 0; j < 4; j++) {
        float4 a = ws[j * 32 + lane];
        float4 b = wd[j * 32 + lane];
        ps[0] = fmaf(xr[j], a.x, ps[0]); ps[1] = fmaf(xr[j], a.y, ps[1]);
        ps[2] = fmaf(xr[j], a.z, ps[2]); ps[3] = fmaf(xr[j], a.w, ps[3]);
        pd[0] = fmaf(xr[j], b.x, pd[0]); pd[1] = fmaf(xr[j], b.y, pd[1]);
        pd[2] = fmaf(xr[j], b.z, pd[2]); pd[3] = fmaf(xr[j], b.w, pd[3]);
    }
#pragma unroll
    for (int h = 0; h < NHEADS; h++) {
#pragma unroll
        for (int o = 16; o; o >>= 1) {
            ps[h] += __shfl_xor_sync(0xffffffffu, ps[h], o);
            pd[h] += __shfl_xor_sync(0xffffffffu, pd[h], o);
        }
    }
    if (!lane) {
#pragma unroll
        for (int h = 0; h < NHEADS; h++) {
            d_asrcA[warp * NHEADS + h] = ps[h];
            d_adstA[warp * NHEADS + h] = pd[h];
        }
    }
}

// ================= TF32 GEMM -> fp16 output with coalesced staged epilogue ============
__device__ __forceinline__ void mma_tf32(float c[4], uint32_t a0, uint32_t a1,
                                         uint32_t a2, uint32_t a3,
                                         uint32_t b0, uint32_t b1) {
    asm volatile(
        "mma.sync.aligned.m16n8k8.row.col.f32.tf32.tf32.f32 "
        "{%0,%1,%2,%3}, {%4,%5,%6,%7}, {%8,%9}, {%0,%1,%2,%3};"
        : "+f"(c[0]), "+f"(c[1]), "+f"(c[2]), "+f"(c[3])
        : "r"(a0), "r"(a1), "r"(a2), "r"(a3), "r"(b0), "r"(b1));
}

__device__ __forceinline__ void cp16p(float* smem_dst, const float* gsrc, bool pred) {
    unsigned sa = (unsigned)__cvta_generic_to_shared(smem_dst);
    int sz = pred ? 16 : 0;
    asm volatile("cp.async.ca.shared.global [%0], [%1], 16, %2;\n" :: "r"(sa), "l"(gsrc), "r"(sz));
}
__device__ __forceinline__ void cp_commit() { asm volatile("cp.async.commit_group;"); }
template <int N>
__device__ __forceinline__ void cp_wait() { asm volatile("cp.async.wait_group %0;" :: "n"(N)); }

template <int K, int NOUT, bool AG, int BN, int WM, int WN>
__launch_bounds__(256, 2)
__global__ void tgemm_k(const float* __restrict__ Ain, const float* __restrict__ B, int M) {
    constexpr int BM = 128, BK = 16;
    constexpr int MT = BM / (WM * 16);
    constexpr int NT = BN / (WN * 8);
    constexpr int ASZ = 2 * BM * (BK + 4);            // floats
    constexpr int BSZ = 2 * BK * (BN + 8);            // floats
    __shared__ __align__(16) char smem_raw[(ASZ + BSZ) * 4];
    float (*As)[BM][BK + 4] = reinterpret_cast<float (*)[BM][BK + 4]>(smem_raw);
    float (*Bs)[BK][BN + 8] = reinterpret_cast<float (*)[BK][BN + 8]>(smem_raw + ASZ * 4);
    const float* A = AG ? (const float*)d_feat : Ain;

    int tid = threadIdx.x;
    int wid = tid >> 5, lane = tid & 31;
    int wm = wid % WM, wn = wid / WM;
    int row0 = blockIdx.y * BM;
    int col0 = blockIdx.x * BN;
    int lr = lane >> 2, lc = lane & 3;

    float c[MT][NT][4];
#pragma unroll
    for (int i = 0; i < MT; i++)
#pragma unroll
        for (int j = 0; j < NT; j++)
#pragma unroll
            for (int q = 0; q < 4; q++) c[i][j][q] = 0.f;

    constexpr int B4 = BN / 4;
    constexpr int BLD = (BK * B4) / 256;
    const int nk = K / BK;

    {
#pragma unroll
        for (int j = 0; j < 2; j++) {
            int idx = tid + j * 256;
            int r = idx >> 2, q = idx & 3;
            cp16p(&As[0][r][q * 4], &A[(size_t)(row0 + r) * K + q * 4], (row0 + r) < M);
        }
#pragma unroll
        for (int j = 0; j < BLD; j++) {
            int idx = tid + j * 256;
            int r = idx / B4, q = idx % B4;
            cp16p(&Bs[0][r][q * 4], &B[(size_t)r * NOUT + col0 + q * 4], true);
        }
        cp_commit();
    }

    for (int t = 0; t < nk; t++) {
        int cur = t & 1;
        if (t + 1 < nk) {
            int k0 = (t + 1) * BK;
#pragma unroll
            for (int j = 0; j < 2; j++) {
                int idx = tid + j * 256;
                int r = idx >> 2, q = idx & 3;
                cp16p(&As[1 - cur][r][q * 4], &A[(size_t)(row0 + r) * K + k0 + q * 4], (row0 + r) < M);
            }
#pragma unroll
            for (int j = 0; j < BLD; j++) {
                int idx = tid + j * 256;
                int r = idx / B4, q = idx % B4;
                cp16p(&Bs[1 - cur][r][q * 4], &B[(size_t)(k0 + r) * NOUT + col0 + q * 4], true);
            }
            cp_commit();
            cp_wait<1>();
        } else {
            cp_wait<0>();
        }
        __syncthreads();

#pragma unroll
        for (int kk = 0; kk < BK; kk += 8) {
            uint32_t af[MT][4], bf[NT][2];
#pragma unroll
            for (int mt = 0; mt < MT; mt++) {
                int bm = wm * MT * 16 + mt * 16;
                if (AG) {
                    af[mt][0] = __float_as_uint(As[cur][bm + lr][kk + lc]);
                    af[mt][1] = __float_as_uint(As[cur][bm + lr + 8][kk + lc]);
                    af[mt][2] = __float_as_uint(As[cur][bm + lr][kk + lc + 4]);
                    af[mt][3] = __float_as_uint(As[cur][bm + lr + 8][kk + lc + 4]);
                } else {
                    af[mt][0] = cvt_tf32(As[cur][bm + lr][kk + lc]);
                    af[mt][1] = cvt_tf32(As[cur][bm + lr + 8][kk + lc]);
                    af[mt][2] = cvt_tf32(As[cur][bm + lr][kk + lc + 4]);
                    af[mt][3] = cvt_tf32(As[cur][bm + lr + 8][kk + lc + 4]);
                }
            }
#pragma unroll
            for (int nt = 0; nt < NT; nt++) {
                int bn = wn * NT * 8 + nt * 8;
                bf[nt][0] = cvt_tf32(Bs[cur][kk + lc][bn + lr]);
                bf[nt][1] = cvt_tf32(Bs[cur][kk + lc + 4][bn + lr]);
            }
#pragma unroll
            for (int mt = 0; mt < MT; mt++)
#pragma unroll
                for (int nt = 0; nt < NT; nt++)
                    mma_tf32(c[mt][nt], af[mt][0], af[mt][1], af[mt][2], af[mt][3],
                             bf[nt][0], bf[nt][1]);
        }
        __syncthreads();
    }

    // ---- epilogue: stage fp16 tile in smem (pad rows), then coalesced global stores ----
    constexpr int TP = BN + 8;                    // padded row stride in halves
    static_assert(BM * TP * 2 <= (ASZ + BSZ) * 4, "staging tile must fit");
    __half* tile = reinterpret_cast<__half*>(smem_raw);
#pragma unroll
    for (int mt = 0; mt < MT; mt++) {
        int rl = wm * MT * 16 + mt * 16 + lr;
#pragma unroll
        for (int nt = 0; nt < NT; nt++) {
            int cw = wn * NT * 8 + nt * 8 + 2 * lc;
            *reinterpret_cast<__half2*>(&tile[rl * TP + cw]) =
                __floats2half2_rn(c[mt][nt][0], c[mt][nt][1]);
            *reinterpret_cast<__half2*>(&tile[(rl + 8) * TP + cw]) =
                __floats2half2_rn(c[mt][nt][2], c[mt][nt][3]);
        }
    }
    __syncthreads();
    constexpr int U4R = BN / 8;                   // uint4 per row
    constexpr int NIT = (BM * U4R) / 256;
#pragma unroll
    for (int j = 0; j < NIT; j++) {
        int idx = tid + j * 256;
        int r = idx / U4R, q = idx % U4R;
        if (row0 + r < M) {
            uint4 v = *reinterpret_cast<const uint4*>(&tile[r * TP + q * 8]);
            *reinterpret_cast<uint4*>(&d_h[(size_t)(row0 + r) * NOUT + col0 + q * 8]) = v;
        }
    }
}

// ======== fused aggregation: single-pass unnormalized softmax, fp16 gather ========
template <int H, int WPN, int HN, bool DOELU, bool SRCA, bool POOL>
__launch_bounds__(256)
__global__ void agg_k(const float* __restrict__ bias, const int* __restrict__ batch, int n) {
    constexpr int C = 64, F = H * C, CH = F / WPN, RF = CH / 32;
    __shared__ float4 wsn4[HN == 4 ? F : 1], wdn4[HN == 4 ? F : 1];
    __shared__ float  wsn1[HN == 1 ? F : 1], wdn1[HN == 1 ? F : 1];
    __shared__ float  parts[8][8];
    if (HN == 4) {
        for (int i = threadIdx.x; i < F; i += 256) { wsn4[i] = d_wa2s[i]; wdn4[i] = d_wa2d[i]; }
        __syncthreads();
    } else if (HN == 1) {
        for (int i = threadIdx.x; i < F; i += 256) { wsn1[i] = d_wa3s[i]; wdn1[i] = d_wa3d[i]; }
        __syncthreads();
    }
    const float* asrc  = SRCA ? d_asrcA : d_asrcB;
    const float* adstp = SRCA ? d_adstA : d_adstB;
    float* nsrc = SRCA ? d_asrcB : d_asrcA;
    float* ndst = SRCA ? d_adstB : d_adstA;

    int gw   = (blockIdx.x * blockDim.x + threadIdx.x) >> 5;
    int wblk = threadIdx.x >> 5;
    int lane = threadIdx.x & 31;
    int slot = gw / WPN;
    int sub  = gw % WPN;
    bool valid = slot < n;
    int node = valid ? d_perm[slot] : 0;

    float acc[RF];
#pragma unroll
    for (int k = 0; k < RF; k++) acc[k] = 0.f;

    if (valid) {
        int off = d_off[node], deg = d_deg[node];

        const int hl = (H == 4) ? (lane >> 4) : 0;
        const int asoff = (H == 4) ? (sub * 2 + hl) : 0;
        const float adh = adstp[node * H + asoff];
        const size_t cbase = sub * CH + lane * RF;

        float S = 0.f;
#pragma unroll 2
        for (int j = 0; j < deg; j++) {
            int s = d_csr_src[off + j];
            float v = asrc[s * H + asoff] + adh;
            v = v > 0.f ? v : NEG * v;
            float w = __expf(v);
            S += w;
            const __half* hs = &d_h[(size_t)s * F + cbase];
            if (RF == 4) {
                uint2 u = *reinterpret_cast<const uint2*>(hs);
                float2 a0 = __half22float2(*reinterpret_cast<__half2*>(&u.x));
                float2 a1 = __half22float2(*reinterpret_cast<__half2*>(&u.y));
                acc[0] = fmaf(w, a0.x, acc[0]); acc[1] = fmaf(w, a0.y, acc[1]);
                acc[2] = fmaf(w, a1.x, acc[2]); acc[3] = fmaf(w, a1.y, acc[3]);
            } else {
                unsigned u = *reinterpret_cast<const unsigned*>(hs);
                float2 a0 = __half22float2(*reinterpret_cast<__half2*>(&u));
                acc[0] = fmaf(w, a0.x, acc[0]); acc[1] = fmaf(w, a0.y, acc[1]);
            }
        }
        float inv = 1.f / (S + EPSV);

#pragma unroll
        for (int k = 0; k < RF; k++) {
            float v = acc[k] * inv + bias[sub * CH + lane * RF + k];
            if (DOELU) v = v > 0.f ? v : (__expf(v) - 1.f);
            acc[k] = v;
        }

        if (POOL) {
            int g = __ldg(&batch[node]);
            atomicAdd(&d_pool[g * HIDC + lane * RF + 0], acc[0]);
            atomicAdd(&d_pool[g * HIDC + lane * RF + 1], acc[1]);
            if (!lane) atomicAdd(&d_cnt[g], 1.0f);
        } else {
            float* outp = &d_feat[(size_t)node * F + sub * CH + lane * RF];
            if (RF == 4) {
                *reinterpret_cast<float4*>(outp) = make_float4(
                    __uint_as_float(cvt_tf32(acc[0])), __uint_as_float(cvt_tf32(acc[1])),
                    __uint_as_float(cvt_tf32(acc[2])), __uint_as_float(cvt_tf32(acc[3])));
            } else {
                *reinterpret_cast<float2*>(outp) = make_float2(
                    __uint_as_float(cvt_tf32(acc[0])), __uint_as_float(cvt_tf32(acc[1])));
            }
        }

        if (HN == 4) {
            float ps[4] = {}, pd[4] = {};
#pragma unroll
            for (int k = 0; k < RF; k++) {
                float4 a = wsn4[sub * CH + k * 32 + lane];
                float4 b = wdn4[sub * CH + k * 32 + lane];
                ps[0] = fmaf(acc[k], a.x, ps[0]); ps[1] = fmaf(acc[k], a.y, ps[1]);
                ps[2] = fmaf(acc[k], a.z, ps[2]); ps[3] = fmaf(acc[k], a.w, ps[3]);
                pd[0] = fmaf(acc[k], b.x, pd[0]); pd[1] = fmaf(acc[k], b.y, pd[1]);
                pd[2] = fmaf(acc[k], b.z, pd[2]); pd[3] = fmaf(acc[k], b.w, pd[3]);
            }
#pragma unroll
            for (int h = 0; h < 4; h++) {
#pragma unroll
                for (int o = 16; o; o >>= 1) {
                    ps[h] += __shfl_xor_sync(0xffffffffu, ps[h], o);
                    pd[h] += __shfl_xor_sync(0xffffffffu, pd[h], o);
                }
            }
            if (!lane) {
#pragma unroll
                for (int h = 0; h < 4; h++) {
                    parts[wblk][h] = ps[h];
                    parts[wblk][4 + h] = pd[h];
                }
            }
        } else if (HN == 1) {
            float ps = 0.f, pd = 0.f;
#pragma unroll
            for (int k = 0; k < RF; k++) {
                ps = fmaf(acc[k], wsn1[sub * CH + k * 32 + lane], ps);
                pd = fmaf(acc[k], wdn1[sub * CH + k * 32 + lane], pd);
            }
#pragma unroll
            for (int o = 16; o; o >>= 1) {
                ps += __shfl_xor_sync(0xffffffffu, ps, o);
                pd += __shfl_xor_sync(0xffffffffu, pd, o);
            }
            if (!lane) { parts[wblk][0] = ps; parts[wblk][1] = pd; }
        }
    }

    if (HN > 0) {
        __syncthreads();
        if (valid && sub == 0 && !lane) {
            if (HN == 4) {
#pragma unroll
                for (int h = 0; h < 4; h++) {
                    nsrc[node * 4 + h] = parts[wblk][h]     + parts[wblk + 1][h];
                    ndst[node * 4 + h] = parts[wblk][4 + h] + parts[wblk + 1][4 + h];
                }
            } else {
                nsrc[node] = parts[wblk][0] + parts[wblk + 1][0];
                ndst[node] = parts[wblk][1] + parts[wblk + 1][1];
            }
        }
    }
}

// ---------------- head ----------------
__global__ void head_k(const float* __restrict__ Wc, const float* __restrict__ bc,
                       float* __restrict__ out) {
    int t = blockIdx.x * blockDim.x + threadIdx.x;
    if (t >= GG * OUTC) return;
    int g = t / OUTC, o = t % OUTC;
    float inv = 1.f / fmaxf(d_cnt[g], 1.f);
    float s = 0.f;
#pragma unroll
    for (int c = 0; c < HIDC; c++) s += d_pool[g * HIDC + c] * Wc[c * OUTC + o];
    out[t] = s * inv + bc[o];
}

// ---------------- host orchestration ----------------
extern "C" void kernel_launch(void* const* d_in, const int* in_sizes, int n_in,
                              void* d_out, int out_size) {
    const float* x   = (const float*)d_in[0];
    const int*   ei  = (const int*)d_in[1];
    const int*   bat = (const int*)d_in[2];
    const float* W1 = (const float*)d_in[3],  *as1 = (const float*)d_in[4],
               * ad1 = (const float*)d_in[5], *b1  = (const float*)d_in[6];
    const float* W2 = (const float*)d_in[7],  *as2 = (const float*)d_in[8],
               * ad2 = (const float*)d_in[9], *b2  = (const float*)d_in[10];
    const float* W3 = (const float*)d_in[11], *as3 = (const float*)d_in[12],
               * ad3 = (const float*)d_in[13],*b3  = (const float*)d_in[14];
    const float* Wc = (const float*)d_in[15], *bc  = (const float*)d_in[16];
    float* out = (float*)d_out;

    int n    = in_sizes[0] / INC;
    int E    = in_sizes[1] / 2;
    int Etot = E + n;

    int gemm_rows = (n + 127) / 128;
    int eb    = (Etot + 255) / 256;
    int nb    = (n + 255) / 256;
    int sb    = (n + 1023) / 1024;
    int aggb2 = (int)(((long long)n * 2 * 32 + 255) / 256);
    int aggb1 = (int)(((long long)n * 32 + 255) / 256);

    static cudaStream_t s2 = nullptr;
    static cudaEvent_t evF = nullptr, evJ = nullptr;
    if (s2 == nullptr) {
        cudaStreamCreateWithFlags(&s2, cudaStreamNonBlocking);
        cudaEventCreateWithFlags(&evF, cudaEventDisableTiming);
        cudaEventCreateWithFlags(&evJ, cudaEventDisableTiming);
    }

    // ---- fork: CSR chain on s2, concurrent with wa/GEMM1/gemv on main ----
    cudaEventRecord(evF, 0);
    cudaStreamWaitEvent(s2, evF, 0);

    zero_all<<<nb, 256, 0, s2>>>(n);
    hist_k<<<eb, 256, 0, s2>>>(ei, E, n);
    scan_blk<<<sb, 1024, 0, s2>>>(n);
    scan_top<<<1, 1024, 0, s2>>>(sb);
    scan_add<<<sb, 1024, 0, s2>>>(n);
    scatter_k<<<eb, 256, 0, s2>>>(ei, E, n);
    cudaEventRecord(evJ, s2);

    wa_prep<<<32, 256>>>(W1, as1, ad1, W2, as2, ad2, W3, as3, ad3);
    tgemm_k<INC, F1, false, 128, 2, 4><<<dim3(F1 / 128, gemm_rows), 256>>>(x, W1, n);
    gemv_attn<<<(n + 7) / 8, 256>>>(x, n);

    cudaStreamWaitEvent(0, evJ, 0);

    // ---- Layer 1 agg (H=4, 2 warps/node, deg-sorted, single-pass); layer-2 coeffs ----
    agg_k<NHEADS, 2, NHEADS, true, true, false><<<aggb2, 256>>>(b1, nullptr, n);

    // ---- Layer 2 (H=4, in=256, out=256) ----
    tgemm_k<F1, F1, true, 128, 2, 4><<<dim3(F1 / 128, gemm_rows), 256>>>(nullptr, W2, n);
    agg_k<NHEADS, 2, 1, true, false, false><<<aggb2, 256>>>(b2, nullptr, n);

    // ---- Layer 3 (H=1, in=256, out=64) ----
    tgemm_k<F1, HIDC, true, 64, 4, 2><<<dim3(1, gemm_rows), 256>>>(nullptr, W3, n);
    agg_k<1, 1, 0, false, true, true><<<aggb1, 256>>>(b3, bat, n);

    // ---- head ----
    head_k<<<(GG * OUTC + 255) / 256, 256>>>(Wc, bc, out);
}